// round 10
// baseline (speedup 1.0000x reference)
#include <cuda_runtime.h>
#include <cuda_fp16.h>
#include <math.h>
#include <stdint.h>

#define BB    32
#define NN    4096
#define NPQ   512
#define NSAMP 16
#define CC    256
#define HIDC  128
#define NPIX  (BB*NPQ*NSAMP)
#define NPTS  (BB*NN)

#define OUT_FEAT (BB*NPQ*3)
#define OUT_INDS (OUT_FEAT + BB*HIDC*NPQ)

__device__ float    g_PF[(size_t)NPTS*HIDC];
__device__ float    g_Y1[(size_t)NPIX*HIDC];
__device__ float    g_Y2[(size_t)NPIX*HIDC];
__device__ float    g_MX[(size_t)BB*NPQ*HIDC];
__device__ int      g_idx[NPIX];
__device__ float    g_gxyz[(size_t)NPIX*3];
__device__ double   g_stats[3*2*HIDC];
__device__ float    g_bn[3*3*HIDC];
__device__ __half   g_W1h[HIDC*CC];
__device__ __half   g_W2h[HIDC*HIDC];
__device__ __half   g_W3h[HIDC*HIDC];

#define MMAH(c, a, b) asm volatile( \
  "mma.sync.aligned.m16n8k16.row.col.f32.f16.f16.f32 " \
  "{%0,%1,%2,%3}, {%4,%5,%6,%7}, {%8,%9}, {%0,%1,%2,%3};" \
  : "+f"((c)[0]), "+f"((c)[1]), "+f"((c)[2]), "+f"((c)[3]) \
  : "r"((a)[0]), "r"((a)[1]), "r"((a)[2]), "r"((a)[3]), "r"((b)[0]), "r"((b)[1]))

#define LDSM4(r0, r1, r2, r3, a) asm volatile( \
  "ldmatrix.sync.aligned.m8n8.x4.shared.b16 {%0,%1,%2,%3}, [%4];" \
  : "=r"(r0), "=r"(r1), "=r"(r2), "=r"(r3) : "r"(a))

#define SSTRIDE 20   /* gemm1: 80B rows, 16B-aligned, conflict-free ldmatrix */
#define NTW 2304     /* gemm_nt: words per k-chunk = 128*18 */
#define NT_DSMEM (8*NTW*4)   /* 73728 B: As[4 chunks] + Bs[4 chunks] */

__device__ __forceinline__ uint32_t packh2(float x, float y) {
    __half2 h = __floats2half2_rn(x, y);
    return *(uint32_t*)&h;
}

__global__ void zero_stats_kernel() {
    int i = blockIdx.x*256 + threadIdx.x;
    if (i < 3*2*HIDC) g_stats[i] = 0.0;
}
__global__ void prep_w_kernel(const float* __restrict__ w1,
                              const float* __restrict__ w2,
                              const float* __restrict__ w3) {
    int o = blockIdx.x, k = threadIdx.x;
    g_W1h[o*CC + k] = __float2half_rn(w1[o*(CC+3) + 3 + k]);
    if (k < HIDC) {
        g_W2h[o*HIDC + k] = __float2half_rn(w2[o*HIDC + k]);
        g_W3h[o*HIDC + k] = __float2half_rn(w3[o*HIDC + k]);
    }
}

// ---------------- FPS (unchanged, passing) ----------------
__global__ __launch_bounds__(1024) void fps_kernel(
    const float* __restrict__ seed, const float* __restrict__ xyz,
    float* __restrict__ out)
{
    int b = blockIdx.x, t = threadIdx.x;
    int lane = t & 31, wid = t >> 5;
    __shared__ float s_cv[2][32], s_cx[2][32], s_cy[2][32], s_cz[2][32];
    __shared__ int   s_ci[2][32];
    __shared__ int   s_inds[NPQ];

    const float* sb = seed + (size_t)b*NN*3;
    float px[4], py[4], pz[4], dist[4];
#pragma unroll
    for (int j = 0; j < 4; j++) {
        int i = t + j*1024;
        px[j] = sb[i*3+0]; py[j] = sb[i*3+1]; pz[j] = sb[i*3+2];
        dist[j] = 1e10f;
    }
    if (t == 0) s_inds[0] = 0;
    float lx = sb[0], ly = sb[1], lz = sb[2];

    for (int it = 1; it < NPQ; ++it) {
        float bv = -1.0f; int bi = 0;
        float bx = 0.f, by = 0.f, bz = 0.f;
#pragma unroll
        for (int j = 0; j < 4; j++) {
            float dx = __fadd_rn(px[j], -lx);
            float dy = __fadd_rn(py[j], -ly);
            float dz = __fadd_rn(pz[j], -lz);
            float d  = __fadd_rn(__fadd_rn(__fmul_rn(dx,dx), __fmul_rn(dy,dy)),
                                 __fmul_rn(dz,dz));
            dist[j] = fminf(dist[j], d);
            if (dist[j] > bv) { bv = dist[j]; bi = t + j*1024;
                                bx = px[j]; by = py[j]; bz = pz[j]; }
        }
#pragma unroll
        for (int off = 16; off > 0; off >>= 1) {
            float ov = __shfl_xor_sync(0xffffffffu, bv, off);
            int   oi = __shfl_xor_sync(0xffffffffu, bi, off);
            float ox = __shfl_xor_sync(0xffffffffu, bx, off);
            float oy = __shfl_xor_sync(0xffffffffu, by, off);
            float oz = __shfl_xor_sync(0xffffffffu, bz, off);
            if (ov > bv || (ov == bv && oi < bi)) {
                bv = ov; bi = oi; bx = ox; by = oy; bz = oz;
            }
        }
        int buf = it & 1;
        if (lane == 0) {
            s_cv[buf][wid] = bv; s_ci[buf][wid] = bi;
            s_cx[buf][wid] = bx; s_cy[buf][wid] = by; s_cz[buf][wid] = bz;
        }
        __syncthreads();
        float v  = s_cv[buf][lane];
        int   ci = s_ci[buf][lane];
        int   sl = lane;
#pragma unroll
        for (int off = 16; off > 0; off >>= 1) {
            float ov = __shfl_xor_sync(0xffffffffu, v,  off);
            int   oi = __shfl_xor_sync(0xffffffffu, ci, off);
            int   os = __shfl_xor_sync(0xffffffffu, sl, off);
            if (ov > v || (ov == v && oi < ci)) { v = ov; ci = oi; sl = os; }
        }
        lx = s_cx[buf][sl]; ly = s_cy[buf][sl]; lz = s_cz[buf][sl];
        if (t == 0) s_inds[it] = ci;
    }
    __syncthreads();
    for (int i = t; i < NPQ; i += 1024) {
        int id = s_inds[i];
        out[OUT_INDS + b*NPQ + i] = (float)id;
        const float* xb = xyz + ((size_t)b*NN + id)*3;
        out[((size_t)b*NPQ + i)*3 + 0] = xb[0];
        out[((size_t)b*NPQ + i)*3 + 1] = xb[1];
        out[((size_t)b*NPQ + i)*3 + 2] = xb[2];
    }
}

// ---------------- Ball query (unchanged, passing) ----------------
__global__ __launch_bounds__(256) void bq2_kernel(
    const float* __restrict__ xyz, const float* __restrict__ out)
{
    __shared__ float sx[NN], sy[NN], sz[NN];
    int tid = threadIdx.x, lane = tid & 31, w = tid >> 5;
    int qbase = blockIdx.x * 32;
    int b = qbase >> 9;
    const float* xb = xyz + (size_t)b*NN*3;
    for (int i = tid; i < NN; i += 256) {
        sx[i] = xb[i*3+0]; sy[i] = xb[i*3+1]; sz[i] = xb[i*3+2];
    }
    __syncthreads();

    const float R2c = (float)(0.3*0.3);
    const float RAD = 0.3f;
    int q0 = qbase + w*4;
    float qx[4], qy[4], qz[4];
    int found[4], first[4];
#pragma unroll
    for (int j = 0; j < 4; j++) {
        qx[j] = out[(size_t)(q0+j)*3+0];
        qy[j] = out[(size_t)(q0+j)*3+1];
        qz[j] = out[(size_t)(q0+j)*3+2];
        found[j] = 0; first[j] = -1;
    }
    for (int s = 0; s < NN/32; s++) {
        int i = s*32 + lane;
        float x = sx[i], y = sy[i], z = sz[i];
        bool pr[4];
#pragma unroll
        for (int j = 0; j < 4; j++) {
            float dx = __fadd_rn(qx[j], -x);
            float dy = __fadd_rn(qy[j], -y);
            float dz = __fadd_rn(qz[j], -z);
            float d  = __fadd_rn(__fadd_rn(__fmul_rn(dx,dx), __fmul_rn(dy,dy)),
                                 __fmul_rn(dz,dz));
            pr[j] = (d < R2c) && (found[j] < NSAMP);
        }
        unsigned anym = __ballot_sync(0xffffffffu, pr[0]|pr[1]|pr[2]|pr[3]);
        if (anym) {
#pragma unroll
            for (int j = 0; j < 4; j++) {
                if (found[j] >= NSAMP) continue;
                unsigned mask = __ballot_sync(0xffffffffu, pr[j]);
                if (!mask) continue;
                if (first[j] < 0) first[j] = s*32 + __ffs(mask) - 1;
                if (pr[j]) {
                    int pos = found[j] + __popc(mask & ((1u << lane) - 1u));
                    if (pos < NSAMP) {
                        int qg = q0 + j;
                        g_idx[qg*NSAMP + pos] = i;
                        g_gxyz[((size_t)qg*NSAMP + pos)*3 + 0] = __fdiv_rn(__fadd_rn(x, -qx[j]), RAD);
                        g_gxyz[((size_t)qg*NSAMP + pos)*3 + 1] = __fdiv_rn(__fadd_rn(y, -qy[j]), RAD);
                        g_gxyz[((size_t)qg*NSAMP + pos)*3 + 2] = __fdiv_rn(__fadd_rn(z, -qz[j]), RAD);
                    }
                }
                found[j] += __popc(mask);
            }
            if (found[0] >= NSAMP && found[1] >= NSAMP &&
                found[2] >= NSAMP && found[3] >= NSAMP) break;
        }
    }
#pragma unroll
    for (int j = 0; j < 4; j++) {
        if (found[j] < NSAMP) {
            int fi = first[j];
            float x = sx[fi], y = sy[fi], z = sz[fi];
            float p0 = __fdiv_rn(__fadd_rn(x, -qx[j]), RAD);
            float p1 = __fdiv_rn(__fadd_rn(y, -qy[j]), RAD);
            float p2 = __fdiv_rn(__fadd_rn(z, -qz[j]), RAD);
            if (lane >= found[j] && lane < NSAMP) {
                int qg = q0 + j;
                g_idx[qg*NSAMP + lane] = fi;
                g_gxyz[((size_t)qg*NSAMP + lane)*3 + 0] = p0;
                g_gxyz[((size_t)qg*NSAMP + lane)*3 + 1] = p1;
                g_gxyz[((size_t)qg*NSAMP + lane)*3 + 2] = p2;
            }
        }
    }
}

// ---------------- GEMM1 fp16 + ldmatrix (unchanged, measured 84us) --------
__global__ __launch_bounds__(256) void gemm1_h(const float* __restrict__ feat)
{
    __shared__ uint32_t As[128*SSTRIDE];
    __shared__ uint32_t Bs[128*SSTRIDE];
    int b = blockIdx.z;
    int mBase = blockIdx.x*128;
    const float* A = feat + (size_t)b*CC*NN;
    const uint32_t* W32 = (const uint32_t*)g_W1h;
    float* C = g_PF + ((size_t)b*NN + mBase)*HIDC;
    int tid = threadIdx.x;
    int lane = tid & 31, wid = tid >> 5;
    int wm = wid >> 2, wn = wid & 3;
    int lq = lane >> 2, lr = lane & 3;

    uint32_t asb = (uint32_t)__cvta_generic_to_shared(As);
    uint32_t bsb = (uint32_t)__cvta_generic_to_shared(Bs);
    int arow = (lane & 7) + ((lane >> 3) & 1)*8;
    int akp  = (lane >> 4)*4;
    int brow = (lane & 7) + (lane >> 4)*8;
    int bkp  = ((lane >> 3) & 1)*4;

    float c[4][4][4];
#pragma unroll
    for (int i = 0; i < 4; i++)
#pragma unroll
        for (int j = 0; j < 4; j++)
#pragma unroll
            for (int r = 0; r < 4; r++) c[i][j][r] = 0.f;

    for (int kb = 0; kb < CC/32; kb++) {
#pragma unroll
        for (int r = 0; r < 2; r++) {
            int p = tid + 256*r;
            int cp = p >> 5, m4 = p & 31;
            const float* a0 = A + (size_t)(kb*32 + 2*cp)*NN + mBase + m4*4;
            float4 va = *(const float4*)a0;
            float4 vb = *(const float4*)(a0 + NN);
            As[(m4*4+0)*SSTRIDE + cp] = packh2(va.x, vb.x);
            As[(m4*4+1)*SSTRIDE + cp] = packh2(va.y, vb.y);
            As[(m4*4+2)*SSTRIDE + cp] = packh2(va.z, vb.z);
            As[(m4*4+3)*SSTRIDE + cp] = packh2(va.w, vb.w);
        }
#pragma unroll
        for (int r = 0; r < 8; r++) {
            int p = tid + 256*r;
            int n = p >> 4, wd = p & 15;
            Bs[n*SSTRIDE + wd] = W32[n*(CC/2) + kb*16 + wd];
        }
        __syncthreads();
#pragma unroll
        for (int ks = 0; ks < 2; ks++) {
            int k0 = ks*8;
            uint32_t af[4][4], bf[4][2];
#pragma unroll
            for (int mi = 0; mi < 4; mi++) {
                uint32_t a = asb + (uint32_t)(((wm*64 + mi*16 + arow)*SSTRIDE + k0 + akp)*4);
                LDSM4(af[mi][0], af[mi][1], af[mi][2], af[mi][3], a);
            }
#pragma unroll
            for (int np = 0; np < 2; np++) {
                uint32_t a = bsb + (uint32_t)(((wn*32 + np*16 + brow)*SSTRIDE + k0 + bkp)*4);
                LDSM4(bf[np*2][0], bf[np*2][1], bf[np*2+1][0], bf[np*2+1][1], a);
            }
#pragma unroll
            for (int mi = 0; mi < 4; mi++)
#pragma unroll
                for (int nj = 0; nj < 4; nj++)
                    MMAH(c[mi][nj], af[mi], bf[nj]);
        }
        __syncthreads();
    }
#pragma unroll
    for (int mi = 0; mi < 4; mi++) {
#pragma unroll
        for (int nj = 0; nj < 4; nj++) {
            int gr  = wm*64 + mi*16 + lq;
            int col = wn*32 + nj*8 + 2*lr;
            *(float2*)(C + (size_t)gr*HIDC + col)     = make_float2(c[mi][nj][0], c[mi][nj][1]);
            *(float2*)(C + (size_t)(gr+8)*HIDC + col) = make_float2(c[mi][nj][2], c[mi][nj][3]);
        }
    }
}

// ---------------- assemble (unchanged, passing) ----------------
__global__ __launch_bounds__(256) void assemble_kernel(const float* __restrict__ w1)
{
    __shared__ float s_wx[HIDC], s_wy[HIDC], s_wz[HIDC];
    __shared__ float s_sum[HIDC], s_sq[HIDC];
    int tid = threadIdx.x, lane = tid & 31, w = tid >> 5;
    if (tid < HIDC) {
        s_wx[tid] = w1[tid*(CC+3) + 0];
        s_wy[tid] = w1[tid*(CC+3) + 1];
        s_wz[tid] = w1[tid*(CC+3) + 2];
        s_sum[tid] = 0.f; s_sq[tid] = 0.f;
    }
    __syncthreads();

    float ls[4] = {0,0,0,0}, lqa[4] = {0,0,0,0};
    float wx[4], wy[4], wz[4];
#pragma unroll
    for (int j = 0; j < 4; j++) {
        int o = lane*4 + j;
        wx[j] = s_wx[o]; wy[j] = s_wy[o]; wz[j] = s_wz[o];
    }
    for (int i = 0; i < 16; i++) {
        int p = blockIdx.x*128 + w*16 + i;
        int b = p >> 13;
        int n = g_idx[p];
        float gx = g_gxyz[(size_t)p*3+0];
        float gy = g_gxyz[(size_t)p*3+1];
        float gz = g_gxyz[(size_t)p*3+2];
        float4 v = *(const float4*)(g_PF + ((size_t)b*NN + n)*HIDC + lane*4);
        float y[4] = {v.x, v.y, v.z, v.w};
#pragma unroll
        for (int j = 0; j < 4; j++) {
            float r = y[j] + wx[j]*gx + wy[j]*gy + wz[j]*gz;
            y[j] = r;
            ls[j] += r; lqa[j] += r*r;
        }
        *(float4*)(g_Y1 + (size_t)p*HIDC + lane*4) = make_float4(y[0],y[1],y[2],y[3]);
    }
#pragma unroll
    for (int j = 0; j < 4; j++) {
        atomicAdd(&s_sum[lane*4 + j], ls[j]);
        atomicAdd(&s_sq [lane*4 + j], lqa[j]);
    }
    __syncthreads();
    if (tid < HIDC)      atomicAdd(&g_stats[0*256 + tid], (double)s_sum[tid]);
    else if (tid < 256)  atomicAdd(&g_stats[0*256 + 128 + (tid-128)], (double)s_sq[tid-128]);
}

__global__ void finalize_bn_kernel(int L, const float* __restrict__ g,
                                   const float* __restrict__ be)
{
    int cc = threadIdx.x;
    if (cc >= HIDC) return;
    const double cnt = (double)NPIX;
    double s = g_stats[L*256 + cc];
    double q = g_stats[L*256 + 128 + cc];
    double m = s / cnt;
    double v = q / cnt - m*m;
    if (v < 0.0) v = 0.0;
    float scale = g[cc] / sqrtf((float)v + 1e-5f);
    g_bn[L*384 + cc]       = (float)m;
    g_bn[L*384 + 128 + cc] = scale;
    g_bn[L*384 + 256 + cc] = be[cc];
}

// ---------------- NT GEMM fp16: single-shot full-K tile, 1 barrier ---------
// Same inner addressing ([128][18] chunks) as the passing scalar version;
// only the loop structure changed: load all 4 k-chunks, sync once, 128 MMAs.
__global__ __launch_bounds__(256) void gemm_nt_h(int layer)
{
    extern __shared__ uint32_t dyn[];
    uint32_t* As = dyn;            // 4 chunks x [128][18]
    uint32_t* Bs = dyn + 4*NTW;
    __shared__ float s_bnp[384];
    __shared__ float s_sum[HIDC], s_sq[HIDC];
    const float* A  = (layer == 1) ? g_Y1 : g_Y2;
    const uint32_t* W32 = (const uint32_t*)((layer == 1) ? g_W2h : g_W3h);
    const float* bnp = g_bn + (layer-1)*384;

    int tid = threadIdx.x;
    int lane = tid & 31, wid = tid >> 5;
    int wm = wid >> 2, wn = wid & 3;
    int lq = lane >> 2, lr = lane & 3;
    if (tid < HIDC) { s_sum[tid] = 0.f; s_sq[tid] = 0.f; }
    for (int i = tid; i < 384; i += 256) s_bnp[i] = bnp[i];
    __syncthreads();

    size_t mBase = (size_t)blockIdx.x * 128;
    float c[4][4][4];
#pragma unroll
    for (int i = 0; i < 4; i++)
#pragma unroll
        for (int j = 0; j < 4; j++)
#pragma unroll
            for (int r = 0; r < 4; r++) c[i][j][r] = 0.f;

    // ---- single load phase: all of K, high MLP ----
#pragma unroll
    for (int kb = 0; kb < 4; kb++) {
#pragma unroll
        for (int r = 0; r < 4; r++) {
            int p = tid + 256*r;
            int row = p >> 3, kq = p & 7;
            int ch = kb*32 + kq*4;
            float4 v = *(const float4*)(A + (mBase + row)*HIDC + ch);
            float a0 = fmaxf(0.f, (v.x - s_bnp[ch+0])*s_bnp[128+ch+0] + s_bnp[256+ch+0]);
            float a1 = fmaxf(0.f, (v.y - s_bnp[ch+1])*s_bnp[128+ch+1] + s_bnp[256+ch+1]);
            float a2 = fmaxf(0.f, (v.z - s_bnp[ch+2])*s_bnp[128+ch+2] + s_bnp[256+ch+2]);
            float a3 = fmaxf(0.f, (v.w - s_bnp[ch+3])*s_bnp[128+ch+3] + s_bnp[256+ch+3]);
            As[kb*NTW + row*18 + kq*2]     = packh2(a0, a1);
            As[kb*NTW + row*18 + kq*2 + 1] = packh2(a2, a3);
        }
#pragma unroll
        for (int r = 0; r < 8; r++) {
            int p = tid + 256*r;
            int n = p >> 4, wd = p & 15;
            Bs[kb*NTW + n*18 + wd] = W32[n*(HIDC/2) + kb*16 + wd];
        }
    }
    __syncthreads();

    // ---- uninterrupted MMA mainloop: 128 HMMAs/warp ----
#pragma unroll
    for (int kb = 0; kb < 4; kb++) {
        const uint32_t* Ac = As + kb*NTW;
        const uint32_t* Bc = Bs + kb*NTW;
#pragma unroll
        for (int ks = 0; ks < 2; ks++) {
            int k0 = ks*8;
            uint32_t af[4][4], bf[4][2];
#pragma unroll
            for (int mi = 0; mi < 4; mi++) {
                int m0 = wm*64 + mi*16;
                af[mi][0] = Ac[(m0 + lq    )*18 + k0 + lr    ];
                af[mi][1] = Ac[(m0 + 8 + lq)*18 + k0 + lr    ];
                af[mi][2] = Ac[(m0 + lq    )*18 + k0 + lr + 4];
                af[mi][3] = Ac[(m0 + 8 + lq)*18 + k0 + lr + 4];
            }
#pragma unroll
            for (int nj = 0; nj < 4; nj++) {
                int n0 = wn*32 + nj*8;
                bf[nj][0] = Bc[(n0+lq)*18 + k0 + lr    ];
                bf[nj][1] = Bc[(n0+lq)*18 + k0 + lr + 4];
            }
#pragma unroll
            for (int mi = 0; mi < 4; mi++)
#pragma unroll
                for (int nj = 0; nj < 4; nj++)
                    MMAH(c[mi][nj], af[mi], bf[nj]);
        }
    }

    if (layer == 1) {
#pragma unroll
        for (int mi = 0; mi < 4; mi++)
#pragma unroll
            for (int nj = 0; nj < 4; nj++) {
                size_t gr = mBase + wm*64 + mi*16 + lq;
                int col = wn*32 + nj*8 + 2*lr;
                *(float2*)(g_Y2 + gr*HIDC + col)     = make_float2(c[mi][nj][0], c[mi][nj][1]);
                *(float2*)(g_Y2 + (gr+8)*HIDC + col) = make_float2(c[mi][nj][2], c[mi][nj][3]);
            }
    } else {
#pragma unroll
        for (int mi = 0; mi < 4; mi++) {
            int qg = blockIdx.x*8 + wm*4 + mi;
#pragma unroll
            for (int nj = 0; nj < 4; nj++) {
                float m0v = fmaxf(c[mi][nj][0], c[mi][nj][2]);
                float m1v = fmaxf(c[mi][nj][1], c[mi][nj][3]);
#pragma unroll
                for (int o = 4; o <= 16; o <<= 1) {
                    m0v = fmaxf(m0v, __shfl_xor_sync(0xffffffffu, m0v, o));
                    m1v = fmaxf(m1v, __shfl_xor_sync(0xffffffffu, m1v, o));
                }
                if (lq == 0) {
                    int col = wn*32 + nj*8 + 2*lr;
                    *(float2*)(g_MX + (size_t)qg*HIDC + col) = make_float2(m0v, m1v);
                }
            }
        }
    }
#pragma unroll
    for (int nj = 0; nj < 4; nj++) {
        int ch = wn*32 + nj*8 + 2*lr;
        float s0 = 0.f, q0 = 0.f, s1 = 0.f, q1 = 0.f;
#pragma unroll
        for (int mi = 0; mi < 4; mi++) {
            float x;
            x = c[mi][nj][0]; s0 += x; q0 += x*x;
            x = c[mi][nj][2]; s0 += x; q0 += x*x;
            x = c[mi][nj][1]; s1 += x; q1 += x*x;
            x = c[mi][nj][3]; s1 += x; q1 += x*x;
        }
        atomicAdd(&s_sum[ch],   s0); atomicAdd(&s_sq[ch],   q0);
        atomicAdd(&s_sum[ch+1], s1); atomicAdd(&s_sq[ch+1], q1);
    }
    __syncthreads();
    if (tid < HIDC)      atomicAdd(&g_stats[layer*256 + tid], (double)s_sum[tid]);
    else if (tid < 256)  atomicAdd(&g_stats[layer*256 + 128 + (tid-128)], (double)s_sq[tid-128]);
}

// ---------------- BN3+ReLU on g_MX + transpose (unchanged) ----------------
__global__ __launch_bounds__(256) void maxfinal_kernel(float* __restrict__ out)
{
    __shared__ float T[HIDC][33];
    int b = blockIdx.x >> 4, pb = blockIdx.x & 15;
    int tid = threadIdx.x;
    const float* bnp = g_bn + 2*384;
#pragma unroll
    for (int r = 0; r < 16; r++) {
        int idx = tid + 256*r;
        int ql = idx >> 7, c = idx & 127;
        float v = g_MX[((size_t)(b*NPQ + pb*32 + ql))*HIDC + c];
        T[c][ql] = fmaxf(0.f, (v - bnp[c])*bnp[128+c] + bnp[256+c]);
    }
    __syncthreads();
#pragma unroll
    for (int r = 0; r < 16; r++) {
        int flat = tid + 256*r;
        int o = flat >> 5, pl = flat & 31;
        out[OUT_FEAT + (size_t)b*(HIDC*NPQ) + (size_t)o*NPQ + pb*32 + pl] = T[o][pl];
    }
}

// ---------------------------------------------------------------------------
extern "C" void kernel_launch(void* const* d_in, const int* in_sizes, int n_in,
                              void* d_out, int out_size)
{
    const float* xyz  = (const float*)d_in[0];
    const float* feat = (const float*)d_in[1];
    const float* seed = (const float*)d_in[2];
    const float* w1   = (const float*)d_in[3];
    const float* g1   = (const float*)d_in[4];
    const float* be1  = (const float*)d_in[5];
    const float* w2   = (const float*)d_in[6];
    const float* g2   = (const float*)d_in[7];
    const float* be2  = (const float*)d_in[8];
    const float* w3   = (const float*)d_in[9];
    const float* g3   = (const float*)d_in[10];
    const float* be3  = (const float*)d_in[11];
    float* out = (float*)d_out;

    // no static guard: unconditional, deterministic, not a stream op
    cudaFuncSetAttribute(gemm_nt_h, cudaFuncAttributeMaxDynamicSharedMemorySize, NT_DSMEM);

    zero_stats_kernel<<<3, 256>>>();
    prep_w_kernel<<<HIDC, CC>>>(w1, w2, w3);
    fps_kernel<<<BB, 1024>>>(seed, xyz, out);
    gemm1_h<<<dim3(NN/128, 1, BB), 256>>>(feat);
    bq2_kernel<<<(BB*NPQ)/32, 256>>>(xyz, out);
    assemble_kernel<<<NPIX/128, 256>>>(w1);
    finalize_bn_kernel<<<1, 128>>>(0, g1, be1);
    gemm_nt_h<<<NPIX/128, 256, NT_DSMEM>>>(1);
    finalize_bn_kernel<<<1, 128>>>(1, g2, be2);
    gemm_nt_h<<<NPIX/128, 256, NT_DSMEM>>>(2);
    finalize_bn_kernel<<<1, 128>>>(2, g3, be3);
    maxfinal_kernel<<<BB*16, 256>>>(out);
}

// round 11
// speedup vs baseline: 1.2880x; 1.2880x over previous
#include <cuda_runtime.h>
#include <cuda_fp16.h>
#include <math.h>
#include <stdint.h>

#define BB    32
#define NN    4096
#define NPQ   512
#define NSAMP 16
#define CC    256
#define HIDC  128
#define NPIX  (BB*NPQ*NSAMP)
#define NPTS  (BB*NN)

#define OUT_FEAT (BB*NPQ*3)
#define OUT_INDS (OUT_FEAT + BB*HIDC*NPQ)

__device__ float    g_PF[(size_t)NPTS*HIDC];
__device__ uint32_t g_Y1h[(size_t)NPIX*64];   // fp16x2 packed [pix][128ch]
__device__ uint32_t g_Y2h[(size_t)NPIX*64];
__device__ float    g_MX[(size_t)BB*NPQ*HIDC];
__device__ int      g_idx[NPIX];
__device__ float    g_gxyz[(size_t)NPIX*3];
__device__ double   g_stats[3*2*HIDC];
__device__ float    g_bn[3*3*HIDC];
__device__ __half   g_W1h[HIDC*CC];
__device__ __half   g_W2h[HIDC*HIDC];
__device__ __half   g_W3h[HIDC*HIDC];

#define MMAH(c, a, b) asm volatile( \
  "mma.sync.aligned.m16n8k16.row.col.f32.f16.f16.f32 " \
  "{%0,%1,%2,%3}, {%4,%5,%6,%7}, {%8,%9}, {%0,%1,%2,%3};" \
  : "+f"((c)[0]), "+f"((c)[1]), "+f"((c)[2]), "+f"((c)[3]) \
  : "r"((a)[0]), "r"((a)[1]), "r"((a)[2]), "r"((a)[3]), "r"((b)[0]), "r"((b)[1]))

#define LDSM4(r0, r1, r2, r3, a) asm volatile( \
  "ldmatrix.sync.aligned.m8n8.x4.shared.b16 {%0,%1,%2,%3}, [%4];" \
  : "=r"(r0), "=r"(r1), "=r"(r2), "=r"(r3) : "r"(a))

#define SSTRIDE 20   /* gemm1: 80B rows, conflict-free ldmatrix */
#define NSTR 36      /* gemm_nt: 64-ch chunk rows, conflict-free scalar frags */

__device__ __forceinline__ uint32_t packh2(float x, float y) {
    __half2 h = __floats2half2_rn(x, y);
    return *(uint32_t*)&h;
}

__global__ void zero_stats_kernel() {
    int i = blockIdx.x*256 + threadIdx.x;
    if (i < 3*2*HIDC) g_stats[i] = 0.0;
}
__global__ void prep_w_kernel(const float* __restrict__ w1,
                              const float* __restrict__ w2,
                              const float* __restrict__ w3) {
    int o = blockIdx.x, k = threadIdx.x;
    g_W1h[o*CC + k] = __float2half_rn(w1[o*(CC+3) + 3 + k]);
    if (k < HIDC) {
        g_W2h[o*HIDC + k] = __float2half_rn(w2[o*HIDC + k]);
        g_W3h[o*HIDC + k] = __float2half_rn(w3[o*HIDC + k]);
    }
}

// ---------------- FPS: redux.sync reductions, same fp + tie-break semantics
__global__ __launch_bounds__(1024) void fps_kernel(
    const float* __restrict__ seed, const float* __restrict__ xyz,
    float* __restrict__ out)
{
    int b = blockIdx.x, t = threadIdx.x;
    int lane = t & 31, wid = t >> 5;
    __shared__ float s_cv[2][32], s_cx[2][32], s_cy[2][32], s_cz[2][32];
    __shared__ int   s_ci[2][32];
    __shared__ int   s_inds[NPQ];

    const float* sb = seed + (size_t)b*NN*3;
    float px[4], py[4], pz[4], dist[4];
#pragma unroll
    for (int j = 0; j < 4; j++) {
        int i = t + j*1024;
        px[j] = sb[i*3+0]; py[j] = sb[i*3+1]; pz[j] = sb[i*3+2];
        dist[j] = 1e10f;
    }
    if (t == 0) s_inds[0] = 0;
    float lx = sb[0], ly = sb[1], lz = sb[2];

    for (int it = 1; it < NPQ; ++it) {
        float bv = -1.0f; int bi = 0;
        float bx = 0.f, by = 0.f, bz = 0.f;
#pragma unroll
        for (int j = 0; j < 4; j++) {
            float dx = __fadd_rn(px[j], -lx);
            float dy = __fadd_rn(py[j], -ly);
            float dz = __fadd_rn(pz[j], -lz);
            float d  = __fadd_rn(__fadd_rn(__fmul_rn(dx,dx), __fmul_rn(dy,dy)),
                                 __fmul_rn(dz,dz));
            dist[j] = fminf(dist[j], d);
            if (dist[j] > bv) { bv = dist[j]; bi = t + j*1024;
                                bx = px[j]; by = py[j]; bz = pz[j]; }
        }
        // warp reduce: max dist-bits (nonneg float = bit-monotone), min index tie
        unsigned fb = __float_as_uint(bv);
        unsigned m  = __reduce_max_sync(0xffffffffu, fb);
        unsigned cand = (fb == m) ? (unsigned)bi : 0xffffffffu;
        unsigned cmin = __reduce_min_sync(0xffffffffu, cand);
        int buf = it & 1;
        if (fb == m && (unsigned)bi == cmin) {
            s_cv[buf][wid] = bv; s_ci[buf][wid] = bi;
            s_cx[buf][wid] = bx; s_cy[buf][wid] = by; s_cz[buf][wid] = bz;
        }
        __syncthreads();
        // all warps redundantly reduce the 32 candidates
        float v  = s_cv[buf][lane];
        int   ci = s_ci[buf][lane];
        unsigned fb2 = __float_as_uint(v);
        unsigned m2  = __reduce_max_sync(0xffffffffu, fb2);
        unsigned cand2 = (fb2 == m2) ? (unsigned)ci : 0xffffffffu;
        unsigned cmin2 = __reduce_min_sync(0xffffffffu, cand2);
        unsigned wmask = __ballot_sync(0xffffffffu, fb2 == m2 && (unsigned)ci == cmin2);
        int sl = __ffs(wmask) - 1;
        lx = s_cx[buf][sl]; ly = s_cy[buf][sl]; lz = s_cz[buf][sl];
        if (t == 0) s_inds[it] = (int)cmin2;
    }
    __syncthreads();
    for (int i = t; i < NPQ; i += 1024) {
        int id = s_inds[i];
        out[OUT_INDS + b*NPQ + i] = (float)id;
        const float* xb = xyz + ((size_t)b*NN + id)*3;
        out[((size_t)b*NPQ + i)*3 + 0] = xb[0];
        out[((size_t)b*NPQ + i)*3 + 1] = xb[1];
        out[((size_t)b*NPQ + i)*3 + 2] = xb[2];
    }
}

// ---------------- Ball query (unchanged, passing) ----------------
__global__ __launch_bounds__(256) void bq2_kernel(
    const float* __restrict__ xyz, const float* __restrict__ out)
{
    __shared__ float sx[NN], sy[NN], sz[NN];
    int tid = threadIdx.x, lane = tid & 31, w = tid >> 5;
    int qbase = blockIdx.x * 32;
    int b = qbase >> 9;
    const float* xb = xyz + (size_t)b*NN*3;
    for (int i = tid; i < NN; i += 256) {
        sx[i] = xb[i*3+0]; sy[i] = xb[i*3+1]; sz[i] = xb[i*3+2];
    }
    __syncthreads();

    const float R2c = (float)(0.3*0.3);
    const float RAD = 0.3f;
    int q0 = qbase + w*4;
    float qx[4], qy[4], qz[4];
    int found[4], first[4];
#pragma unroll
    for (int j = 0; j < 4; j++) {
        qx[j] = out[(size_t)(q0+j)*3+0];
        qy[j] = out[(size_t)(q0+j)*3+1];
        qz[j] = out[(size_t)(q0+j)*3+2];
        found[j] = 0; first[j] = -1;
    }
    for (int s = 0; s < NN/32; s++) {
        int i = s*32 + lane;
        float x = sx[i], y = sy[i], z = sz[i];
        bool pr[4];
#pragma unroll
        for (int j = 0; j < 4; j++) {
            float dx = __fadd_rn(qx[j], -x);
            float dy = __fadd_rn(qy[j], -y);
            float dz = __fadd_rn(qz[j], -z);
            float d  = __fadd_rn(__fadd_rn(__fmul_rn(dx,dx), __fmul_rn(dy,dy)),
                                 __fmul_rn(dz,dz));
            pr[j] = (d < R2c) && (found[j] < NSAMP);
        }
        unsigned anym = __ballot_sync(0xffffffffu, pr[0]|pr[1]|pr[2]|pr[3]);
        if (anym) {
#pragma unroll
            for (int j = 0; j < 4; j++) {
                if (found[j] >= NSAMP) continue;
                unsigned mask = __ballot_sync(0xffffffffu, pr[j]);
                if (!mask) continue;
                if (first[j] < 0) first[j] = s*32 + __ffs(mask) - 1;
                if (pr[j]) {
                    int pos = found[j] + __popc(mask & ((1u << lane) - 1u));
                    if (pos < NSAMP) {
                        int qg = q0 + j;
                        g_idx[qg*NSAMP + pos] = i;
                        g_gxyz[((size_t)qg*NSAMP + pos)*3 + 0] = __fdiv_rn(__fadd_rn(x, -qx[j]), RAD);
                        g_gxyz[((size_t)qg*NSAMP + pos)*3 + 1] = __fdiv_rn(__fadd_rn(y, -qy[j]), RAD);
                        g_gxyz[((size_t)qg*NSAMP + pos)*3 + 2] = __fdiv_rn(__fadd_rn(z, -qz[j]), RAD);
                    }
                }
                found[j] += __popc(mask);
            }
            if (found[0] >= NSAMP && found[1] >= NSAMP &&
                found[2] >= NSAMP && found[3] >= NSAMP) break;
        }
    }
#pragma unroll
    for (int j = 0; j < 4; j++) {
        if (found[j] < NSAMP) {
            int fi = first[j];
            float x = sx[fi], y = sy[fi], z = sz[fi];
            float p0 = __fdiv_rn(__fadd_rn(x, -qx[j]), RAD);
            float p1 = __fdiv_rn(__fadd_rn(y, -qy[j]), RAD);
            float p2 = __fdiv_rn(__fadd_rn(z, -qz[j]), RAD);
            if (lane >= found[j] && lane < NSAMP) {
                int qg = q0 + j;
                g_idx[qg*NSAMP + lane] = fi;
                g_gxyz[((size_t)qg*NSAMP + lane)*3 + 0] = p0;
                g_gxyz[((size_t)qg*NSAMP + lane)*3 + 1] = p1;
                g_gxyz[((size_t)qg*NSAMP + lane)*3 + 2] = p2;
            }
        }
    }
}

// ---------------- GEMM1 fp16 + ldmatrix (unchanged, measured 84us) --------
__global__ __launch_bounds__(256) void gemm1_h(const float* __restrict__ feat)
{
    __shared__ uint32_t As[128*SSTRIDE];
    __shared__ uint32_t Bs[128*SSTRIDE];
    int b = blockIdx.z;
    int mBase = blockIdx.x*128;
    const float* A = feat + (size_t)b*CC*NN;
    const uint32_t* W32 = (const uint32_t*)g_W1h;
    float* C = g_PF + ((size_t)b*NN + mBase)*HIDC;
    int tid = threadIdx.x;
    int lane = tid & 31, wid = tid >> 5;
    int wm = wid >> 2, wn = wid & 3;
    int lq = lane >> 2, lr = lane & 3;

    uint32_t asb = (uint32_t)__cvta_generic_to_shared(As);
    uint32_t bsb = (uint32_t)__cvta_generic_to_shared(Bs);
    int arow = (lane & 7) + ((lane >> 3) & 1)*8;
    int akp  = (lane >> 4)*4;
    int brow = (lane & 7) + (lane >> 4)*8;
    int bkp  = ((lane >> 3) & 1)*4;

    float c[4][4][4];
#pragma unroll
    for (int i = 0; i < 4; i++)
#pragma unroll
        for (int j = 0; j < 4; j++)
#pragma unroll
            for (int r = 0; r < 4; r++) c[i][j][r] = 0.f;

    for (int kb = 0; kb < CC/32; kb++) {
#pragma unroll
        for (int r = 0; r < 2; r++) {
            int p = tid + 256*r;
            int cp = p >> 5, m4 = p & 31;
            const float* a0 = A + (size_t)(kb*32 + 2*cp)*NN + mBase + m4*4;
            float4 va = *(const float4*)a0;
            float4 vb = *(const float4*)(a0 + NN);
            As[(m4*4+0)*SSTRIDE + cp] = packh2(va.x, vb.x);
            As[(m4*4+1)*SSTRIDE + cp] = packh2(va.y, vb.y);
            As[(m4*4+2)*SSTRIDE + cp] = packh2(va.z, vb.z);
            As[(m4*4+3)*SSTRIDE + cp] = packh2(va.w, vb.w);
        }
#pragma unroll
        for (int r = 0; r < 8; r++) {
            int p = tid + 256*r;
            int n = p >> 4, wd = p & 15;
            Bs[n*SSTRIDE + wd] = W32[n*(CC/2) + kb*16 + wd];
        }
        __syncthreads();
#pragma unroll
        for (int ks = 0; ks < 2; ks++) {
            int k0 = ks*8;
            uint32_t af[4][4], bf[4][2];
#pragma unroll
            for (int mi = 0; mi < 4; mi++) {
                uint32_t a = asb + (uint32_t)(((wm*64 + mi*16 + arow)*SSTRIDE + k0 + akp)*4);
                LDSM4(af[mi][0], af[mi][1], af[mi][2], af[mi][3], a);
            }
#pragma unroll
            for (int np = 0; np < 2; np++) {
                uint32_t a = bsb + (uint32_t)(((wn*32 + np*16 + brow)*SSTRIDE + k0 + bkp)*4);
                LDSM4(bf[np*2][0], bf[np*2][1], bf[np*2+1][0], bf[np*2+1][1], a);
            }
#pragma unroll
            for (int mi = 0; mi < 4; mi++)
#pragma unroll
                for (int nj = 0; nj < 4; nj++)
                    MMAH(c[mi][nj], af[mi], bf[nj]);
        }
        __syncthreads();
    }
#pragma unroll
    for (int mi = 0; mi < 4; mi++) {
#pragma unroll
        for (int nj = 0; nj < 4; nj++) {
            int gr  = wm*64 + mi*16 + lq;
            int col = wn*32 + nj*8 + 2*lr;
            *(float2*)(C + (size_t)gr*HIDC + col)     = make_float2(c[mi][nj][0], c[mi][nj][1]);
            *(float2*)(C + (size_t)(gr+8)*HIDC + col) = make_float2(c[mi][nj][2], c[mi][nj][3]);
        }
    }
}

// ---------------- assemble: writes fp16-packed Y1 ----------------
__global__ __launch_bounds__(256) void assemble_kernel(const float* __restrict__ w1)
{
    __shared__ float s_wx[HIDC], s_wy[HIDC], s_wz[HIDC];
    __shared__ float s_sum[HIDC], s_sq[HIDC];
    int tid = threadIdx.x, lane = tid & 31, w = tid >> 5;
    if (tid < HIDC) {
        s_wx[tid] = w1[tid*(CC+3) + 0];
        s_wy[tid] = w1[tid*(CC+3) + 1];
        s_wz[tid] = w1[tid*(CC+3) + 2];
        s_sum[tid] = 0.f; s_sq[tid] = 0.f;
    }
    __syncthreads();

    float ls[4] = {0,0,0,0}, lqa[4] = {0,0,0,0};
    float wx[4], wy[4], wz[4];
#pragma unroll
    for (int j = 0; j < 4; j++) {
        int o = lane*4 + j;
        wx[j] = s_wx[o]; wy[j] = s_wy[o]; wz[j] = s_wz[o];
    }
    for (int i = 0; i < 16; i++) {
        int p = blockIdx.x*128 + w*16 + i;
        int b = p >> 13;
        int n = g_idx[p];
        float gx = g_gxyz[(size_t)p*3+0];
        float gy = g_gxyz[(size_t)p*3+1];
        float gz = g_gxyz[(size_t)p*3+2];
        float4 v = *(const float4*)(g_PF + ((size_t)b*NN + n)*HIDC + lane*4);
        float y[4] = {v.x, v.y, v.z, v.w};
#pragma unroll
        for (int j = 0; j < 4; j++) {
            float r = y[j] + wx[j]*gx + wy[j]*gy + wz[j]*gz;
            y[j] = r;
            ls[j] += r; lqa[j] += r*r;
        }
        uint2 pk = make_uint2(packh2(y[0], y[1]), packh2(y[2], y[3]));
        *(uint2*)(g_Y1h + (size_t)p*64 + lane*2) = pk;
    }
#pragma unroll
    for (int j = 0; j < 4; j++) {
        atomicAdd(&s_sum[lane*4 + j], ls[j]);
        atomicAdd(&s_sq [lane*4 + j], lqa[j]);
    }
    __syncthreads();
    if (tid < HIDC)      atomicAdd(&g_stats[0*256 + tid], (double)s_sum[tid]);
    else if (tid < 256)  atomicAdd(&g_stats[0*256 + 128 + (tid-128)], (double)s_sq[tid-128]);
}

__global__ void finalize_bn_kernel(int L, const float* __restrict__ g,
                                   const float* __restrict__ be)
{
    int cc = threadIdx.x;
    if (cc >= HIDC) return;
    const double cnt = (double)NPIX;
    double s = g_stats[L*256 + cc];
    double q = g_stats[L*256 + 128 + cc];
    double m = s / cnt;
    double v = q / cnt - m*m;
    if (v < 0.0) v = 0.0;
    float scale = g[cc] / sqrtf((float)v + 1e-5f);
    g_bn[L*384 + cc]       = (float)m;
    g_bn[L*384 + 128 + cc] = scale;
    g_bn[L*384 + 256 + cc] = be[cc];
}

// ---------------- NT GEMM fp16, fp16 Y storage, 64-ch chunks ----------------
// layer 1: A=g_Y1h -> writes g_Y2h; layer 2: A=g_Y2h -> fused max into g_MX.
__global__ __launch_bounds__(256) void gemm_nt_h(int layer)
{
    __shared__ uint32_t As[128*NSTR];
    __shared__ uint32_t Bs[128*NSTR];
    __shared__ float s_bnp[384];
    __shared__ float s_sum[HIDC], s_sq[HIDC];
    const uint32_t* Ah = (layer == 1) ? g_Y1h : g_Y2h;
    const uint32_t* W32 = (const uint32_t*)((layer == 1) ? g_W2h : g_W3h);
    const float* bnp = g_bn + (layer-1)*384;

    int tid = threadIdx.x;
    int lane = tid & 31, wid = tid >> 5;
    int wm = wid >> 2, wn = wid & 3;
    int lq = lane >> 2, lr = lane & 3;
    if (tid < HIDC) { s_sum[tid] = 0.f; s_sq[tid] = 0.f; }
    for (int i = tid; i < 384; i += 256) s_bnp[i] = bnp[i];
    __syncthreads();

    size_t mBase = (size_t)blockIdx.x * 128;
    float c[4][4][4];
#pragma unroll
    for (int i = 0; i < 4; i++)
#pragma unroll
        for (int j = 0; j < 4; j++)
#pragma unroll
            for (int r = 0; r < 4; r++) c[i][j][r] = 0.f;

    for (int kb = 0; kb < 2; kb++) {          // 64 channels per chunk
        // A: 128 rows x 8 uint4 = 1024 -> 4 per thread (MLP 4)
#pragma unroll
        for (int r = 0; r < 4; r++) {
            int p = tid + 256*r;
            int row = p >> 3, q = p & 7;      // q: uint4 within row (8 halves)
            int ch = kb*64 + q*8;
            uint4 v = *(const uint4*)(Ah + (mBase + row)*64 + kb*32 + q*4);
            uint32_t wds[4] = {v.x, v.y, v.z, v.w};
#pragma unroll
            for (int k = 0; k < 4; k++) {
                float2 f = __half22float2(*(__half2*)&wds[k]);
                int cch = ch + 2*k;
                float a0 = fmaxf(0.f, (f.x - s_bnp[cch])  *s_bnp[128+cch]   + s_bnp[256+cch]);
                float a1 = fmaxf(0.f, (f.y - s_bnp[cch+1])*s_bnp[128+cch+1] + s_bnp[256+cch+1]);
                As[row*NSTR + q*4 + k] = packh2(a0, a1);
            }
        }
        // B: 128 rows x 8 uint4 = 1024 -> 4 per thread
#pragma unroll
        for (int r = 0; r < 4; r++) {
            int p = tid + 256*r;
            int n = p >> 3, q = p & 7;
            *(uint4*)(Bs + n*NSTR + q*4) = *(const uint4*)(W32 + n*64 + kb*32 + q*4);
        }
        __syncthreads();
#pragma unroll
        for (int ks = 0; ks < 4; ks++) {      // 4 k-steps of 16 channels
            int k0 = ks*8;
            uint32_t af[4][4], bf[4][2];
#pragma unroll
            for (int mi = 0; mi < 4; mi++) {
                int m0 = wm*64 + mi*16;
                af[mi][0] = As[(m0 + lq    )*NSTR + k0 + lr    ];
                af[mi][1] = As[(m0 + 8 + lq)*NSTR + k0 + lr    ];
                af[mi][2] = As[(m0 + lq    )*NSTR + k0 + lr + 4];
                af[mi][3] = As[(m0 + 8 + lq)*NSTR + k0 + lr + 4];
            }
#pragma unroll
            for (int nj = 0; nj < 4; nj++) {
                int n0 = wn*32 + nj*8;
                bf[nj][0] = Bs[(n0+lq)*NSTR + k0 + lr    ];
                bf[nj][1] = Bs[(n0+lq)*NSTR + k0 + lr + 4];
            }
#pragma unroll
            for (int mi = 0; mi < 4; mi++)
#pragma unroll
                for (int nj = 0; nj < 4; nj++)
                    MMAH(c[mi][nj], af[mi], bf[nj]);
        }
        __syncthreads();
    }
    if (layer == 1) {
#pragma unroll
        for (int mi = 0; mi < 4; mi++)
#pragma unroll
            for (int nj = 0; nj < 4; nj++) {
                size_t gr = mBase + wm*64 + mi*16 + lq;
                int colw = wn*16 + nj*4 + lr;
                g_Y2h[gr*64 + colw]     = packh2(c[mi][nj][0], c[mi][nj][1]);
                g_Y2h[(gr+8)*64 + colw] = packh2(c[mi][nj][2], c[mi][nj][3]);
            }
    } else {
#pragma unroll
        for (int mi = 0; mi < 4; mi++) {
            int qg = blockIdx.x*8 + wm*4 + mi;
#pragma unroll
            for (int nj = 0; nj < 4; nj++) {
                float m0v = fmaxf(c[mi][nj][0], c[mi][nj][2]);
                float m1v = fmaxf(c[mi][nj][1], c[mi][nj][3]);
#pragma unroll
                for (int o = 4; o <= 16; o <<= 1) {
                    m0v = fmaxf(m0v, __shfl_xor_sync(0xffffffffu, m0v, o));
                    m1v = fmaxf(m1v, __shfl_xor_sync(0xffffffffu, m1v, o));
                }
                if (lq == 0) {
                    int col = wn*32 + nj*8 + 2*lr;
                    *(float2*)(g_MX + (size_t)qg*HIDC + col) = make_float2(m0v, m1v);
                }
            }
        }
    }
#pragma unroll
    for (int nj = 0; nj < 4; nj++) {
        int ch = wn*32 + nj*8 + 2*lr;
        float s0 = 0.f, q0 = 0.f, s1 = 0.f, q1 = 0.f;
#pragma unroll
        for (int mi = 0; mi < 4; mi++) {
            float x;
            x = c[mi][nj][0]; s0 += x; q0 += x*x;
            x = c[mi][nj][2]; s0 += x; q0 += x*x;
            x = c[mi][nj][1]; s1 += x; q1 += x*x;
            x = c[mi][nj][3]; s1 += x; q1 += x*x;
        }
        atomicAdd(&s_sum[ch],   s0); atomicAdd(&s_sq[ch],   q0);
        atomicAdd(&s_sum[ch+1], s1); atomicAdd(&s_sq[ch+1], q1);
    }
    __syncthreads();
    if (tid < HIDC)      atomicAdd(&g_stats[layer*256 + tid], (double)s_sum[tid]);
    else if (tid < 256)  atomicAdd(&g_stats[layer*256 + 128 + (tid-128)], (double)s_sq[tid-128]);
}

// ---------------- BN3+ReLU on g_MX + transpose (unchanged) ----------------
__global__ __launch_bounds__(256) void maxfinal_kernel(float* __restrict__ out)
{
    __shared__ float T[HIDC][33];
    int b = blockIdx.x >> 4, pb = blockIdx.x & 15;
    int tid = threadIdx.x;
    const float* bnp = g_bn + 2*384;
#pragma unroll
    for (int r = 0; r < 16; r++) {
        int idx = tid + 256*r;
        int ql = idx >> 7, c = idx & 127;
        float v = g_MX[((size_t)(b*NPQ + pb*32 + ql))*HIDC + c];
        T[c][ql] = fmaxf(0.f, (v - bnp[c])*bnp[128+c] + bnp[256+c]);
    }
    __syncthreads();
#pragma unroll
    for (int r = 0; r < 16; r++) {
        int flat = tid + 256*r;
        int o = flat >> 5, pl = flat & 31;
        out[OUT_FEAT + (size_t)b*(HIDC*NPQ) + (size_t)o*NPQ + pb*32 + pl] = T[o][pl];
    }
}

// ---------------------------------------------------------------------------
extern "C" void kernel_launch(void* const* d_in, const int* in_sizes, int n_in,
                              void* d_out, int out_size)
{
    const float* xyz  = (const float*)d_in[0];
    const float* feat = (const float*)d_in[1];
    const float* seed = (const float*)d_in[2];
    const float* w1   = (const float*)d_in[3];
    const float* g1   = (const float*)d_in[4];
    const float* be1  = (const float*)d_in[5];
    const float* w2   = (const float*)d_in[6];
    const float* g2   = (const float*)d_in[7];
    const float* be2  = (const float*)d_in[8];
    const float* w3   = (const float*)d_in[9];
    const float* g3   = (const float*)d_in[10];
    const float* be3  = (const float*)d_in[11];
    float* out = (float*)d_out;

    zero_stats_kernel<<<3, 256>>>();
    prep_w_kernel<<<HIDC, CC>>>(w1, w2, w3);
    fps_kernel<<<BB, 1024>>>(seed, xyz, out);
    gemm1_h<<<dim3(NN/128, 1, BB), 256>>>(feat);
    bq2_kernel<<<(BB*NPQ)/32, 256>>>(xyz, out);
    assemble_kernel<<<NPIX/128, 256>>>(w1);
    finalize_bn_kernel<<<1, 128>>>(0, g1, be1);
    gemm_nt_h<<<NPIX/128, 256>>>(1);
    finalize_bn_kernel<<<1, 128>>>(1, g2, be2);
    gemm_nt_h<<<NPIX/128, 256>>>(2);
    finalize_bn_kernel<<<1, 128>>>(2, g3, be3);
    maxfinal_kernel<<<BB*16, 256>>>(out);
}

// round 12
// speedup vs baseline: 1.2936x; 1.0044x over previous
#include <cuda_runtime.h>
#include <cuda_fp16.h>
#include <math.h>
#include <stdint.h>

#define BB    32
#define NN    4096
#define NPQ   512
#define NSAMP 16
#define CC    256
#define HIDC  128
#define NPIX  (BB*NPQ*NSAMP)
#define NPTS  (BB*NN)

#define OUT_FEAT (BB*NPQ*3)
#define OUT_INDS (OUT_FEAT + BB*HIDC*NPQ)

__device__ uint32_t g_PFh[(size_t)NPTS*64];   // fp16x2 packed conv1 feature part
__device__ uint32_t g_Y1h[(size_t)NPIX*64];   // fp16x2 packed [pix][128ch]
__device__ uint32_t g_Y2h[(size_t)NPIX*64];
__device__ float    g_MX[(size_t)BB*NPQ*HIDC];
__device__ int      g_idx[NPIX];
__device__ float    g_gxyz[(size_t)NPIX*3];
__device__ double   g_stats[3*2*HIDC];
__device__ float    g_bn[3*3*HIDC];
__device__ __half   g_W1h[HIDC*CC];
__device__ __half   g_W2h[HIDC*HIDC];
__device__ __half   g_W3h[HIDC*HIDC];

#define MMAH(c, a, b) asm volatile( \
  "mma.sync.aligned.m16n8k16.row.col.f32.f16.f16.f32 " \
  "{%0,%1,%2,%3}, {%4,%5,%6,%7}, {%8,%9}, {%0,%1,%2,%3};" \
  : "+f"((c)[0]), "+f"((c)[1]), "+f"((c)[2]), "+f"((c)[3]) \
  : "r"((a)[0]), "r"((a)[1]), "r"((a)[2]), "r"((a)[3]), "r"((b)[0]), "r"((b)[1]))

#define LDSM4(r0, r1, r2, r3, a) asm volatile( \
  "ldmatrix.sync.aligned.m8n8.x4.shared.b16 {%0,%1,%2,%3}, [%4];" \
  : "=r"(r0), "=r"(r1), "=r"(r2), "=r"(r3) : "r"(a))

#define SSTRIDE 20   /* gemm1: 80B rows, conflict-free ldmatrix */
#define NSTR 36      /* gemm_nt: 64-ch chunk rows, conflict-free scalar frags */

__device__ __forceinline__ uint32_t packh2(float x, float y) {
    __half2 h = __floats2half2_rn(x, y);
    return *(uint32_t*)&h;
}

__global__ void zero_stats_kernel() {
    int i = blockIdx.x*256 + threadIdx.x;
    if (i < 3*2*HIDC) g_stats[i] = 0.0;
}
__global__ void prep_w_kernel(const float* __restrict__ w1,
                              const float* __restrict__ w2,
                              const float* __restrict__ w3) {
    int o = blockIdx.x, k = threadIdx.x;
    g_W1h[o*CC + k] = __float2half_rn(w1[o*(CC+3) + 3 + k]);
    if (k < HIDC) {
        g_W2h[o*HIDC + k] = __float2half_rn(w2[o*HIDC + k]);
        g_W3h[o*HIDC + k] = __float2half_rn(w3[o*HIDC + k]);
    }
}

// ---------------- FPS (unchanged from R11, passing) ----------------
__global__ __launch_bounds__(1024) void fps_kernel(
    const float* __restrict__ seed, const float* __restrict__ xyz,
    float* __restrict__ out)
{
    int b = blockIdx.x, t = threadIdx.x;
    int lane = t & 31, wid = t >> 5;
    __shared__ float s_cv[2][32], s_cx[2][32], s_cy[2][32], s_cz[2][32];
    __shared__ int   s_ci[2][32];
    __shared__ int   s_inds[NPQ];

    const float* sb = seed + (size_t)b*NN*3;
    float px[4], py[4], pz[4], dist[4];
#pragma unroll
    for (int j = 0; j < 4; j++) {
        int i = t + j*1024;
        px[j] = sb[i*3+0]; py[j] = sb[i*3+1]; pz[j] = sb[i*3+2];
        dist[j] = 1e10f;
    }
    if (t == 0) s_inds[0] = 0;
    float lx = sb[0], ly = sb[1], lz = sb[2];

    for (int it = 1; it < NPQ; ++it) {
        float bv = -1.0f; int bi = 0;
        float bx = 0.f, by = 0.f, bz = 0.f;
#pragma unroll
        for (int j = 0; j < 4; j++) {
            float dx = __fadd_rn(px[j], -lx);
            float dy = __fadd_rn(py[j], -ly);
            float dz = __fadd_rn(pz[j], -lz);
            float d  = __fadd_rn(__fadd_rn(__fmul_rn(dx,dx), __fmul_rn(dy,dy)),
                                 __fmul_rn(dz,dz));
            dist[j] = fminf(dist[j], d);
            if (dist[j] > bv) { bv = dist[j]; bi = t + j*1024;
                                bx = px[j]; by = py[j]; bz = pz[j]; }
        }
        unsigned fb = __float_as_uint(bv);
        unsigned m  = __reduce_max_sync(0xffffffffu, fb);
        unsigned cand = (fb == m) ? (unsigned)bi : 0xffffffffu;
        unsigned cmin = __reduce_min_sync(0xffffffffu, cand);
        int buf = it & 1;
        if (fb == m && (unsigned)bi == cmin) {
            s_cv[buf][wid] = bv; s_ci[buf][wid] = bi;
            s_cx[buf][wid] = bx; s_cy[buf][wid] = by; s_cz[buf][wid] = bz;
        }
        __syncthreads();
        float v  = s_cv[buf][lane];
        int   ci = s_ci[buf][lane];
        unsigned fb2 = __float_as_uint(v);
        unsigned m2  = __reduce_max_sync(0xffffffffu, fb2);
        unsigned cand2 = (fb2 == m2) ? (unsigned)ci : 0xffffffffu;
        unsigned cmin2 = __reduce_min_sync(0xffffffffu, cand2);
        unsigned wmask = __ballot_sync(0xffffffffu, fb2 == m2 && (unsigned)ci == cmin2);
        int sl = __ffs(wmask) - 1;
        lx = s_cx[buf][sl]; ly = s_cy[buf][sl]; lz = s_cz[buf][sl];
        if (t == 0) s_inds[it] = (int)cmin2;
    }
    __syncthreads();
    for (int i = t; i < NPQ; i += 1024) {
        int id = s_inds[i];
        out[OUT_INDS + b*NPQ + i] = (float)id;
        const float* xb = xyz + ((size_t)b*NN + id)*3;
        out[((size_t)b*NPQ + i)*3 + 0] = xb[0];
        out[((size_t)b*NPQ + i)*3 + 1] = xb[1];
        out[((size_t)b*NPQ + i)*3 + 2] = xb[2];
    }
}

// ---------------- Ball query (unchanged, passing) ----------------
__global__ __launch_bounds__(256) void bq2_kernel(
    const float* __restrict__ xyz, const float* __restrict__ out)
{
    __shared__ float sx[NN], sy[NN], sz[NN];
    int tid = threadIdx.x, lane = tid & 31, w = tid >> 5;
    int qbase = blockIdx.x * 32;
    int b = qbase >> 9;
    const float* xb = xyz + (size_t)b*NN*3;
    for (int i = tid; i < NN; i += 256) {
        sx[i] = xb[i*3+0]; sy[i] = xb[i*3+1]; sz[i] = xb[i*3+2];
    }
    __syncthreads();

    const float R2c = (float)(0.3*0.3);
    const float RAD = 0.3f;
    int q0 = qbase + w*4;
    float qx[4], qy[4], qz[4];
    int found[4], first[4];
#pragma unroll
    for (int j = 0; j < 4; j++) {
        qx[j] = out[(size_t)(q0+j)*3+0];
        qy[j] = out[(size_t)(q0+j)*3+1];
        qz[j] = out[(size_t)(q0+j)*3+2];
        found[j] = 0; first[j] = -1;
    }
    for (int s = 0; s < NN/32; s++) {
        int i = s*32 + lane;
        float x = sx[i], y = sy[i], z = sz[i];
        bool pr[4];
#pragma unroll
        for (int j = 0; j < 4; j++) {
            float dx = __fadd_rn(qx[j], -x);
            float dy = __fadd_rn(qy[j], -y);
            float dz = __fadd_rn(qz[j], -z);
            float d  = __fadd_rn(__fadd_rn(__fmul_rn(dx,dx), __fmul_rn(dy,dy)),
                                 __fmul_rn(dz,dz));
            pr[j] = (d < R2c) && (found[j] < NSAMP);
        }
        unsigned anym = __ballot_sync(0xffffffffu, pr[0]|pr[1]|pr[2]|pr[3]);
        if (anym) {
#pragma unroll
            for (int j = 0; j < 4; j++) {
                if (found[j] >= NSAMP) continue;
                unsigned mask = __ballot_sync(0xffffffffu, pr[j]);
                if (!mask) continue;
                if (first[j] < 0) first[j] = s*32 + __ffs(mask) - 1;
                if (pr[j]) {
                    int pos = found[j] + __popc(mask & ((1u << lane) - 1u));
                    if (pos < NSAMP) {
                        int qg = q0 + j;
                        g_idx[qg*NSAMP + pos] = i;
                        g_gxyz[((size_t)qg*NSAMP + pos)*3 + 0] = __fdiv_rn(__fadd_rn(x, -qx[j]), RAD);
                        g_gxyz[((size_t)qg*NSAMP + pos)*3 + 1] = __fdiv_rn(__fadd_rn(y, -qy[j]), RAD);
                        g_gxyz[((size_t)qg*NSAMP + pos)*3 + 2] = __fdiv_rn(__fadd_rn(z, -qz[j]), RAD);
                    }
                }
                found[j] += __popc(mask);
            }
            if (found[0] >= NSAMP && found[1] >= NSAMP &&
                found[2] >= NSAMP && found[3] >= NSAMP) break;
        }
    }
#pragma unroll
    for (int j = 0; j < 4; j++) {
        if (found[j] < NSAMP) {
            int fi = first[j];
            float x = sx[fi], y = sy[fi], z = sz[fi];
            float p0 = __fdiv_rn(__fadd_rn(x, -qx[j]), RAD);
            float p1 = __fdiv_rn(__fadd_rn(y, -qy[j]), RAD);
            float p2 = __fdiv_rn(__fadd_rn(z, -qz[j]), RAD);
            if (lane >= found[j] && lane < NSAMP) {
                int qg = q0 + j;
                g_idx[qg*NSAMP + lane] = fi;
                g_gxyz[((size_t)qg*NSAMP + lane)*3 + 0] = p0;
                g_gxyz[((size_t)qg*NSAMP + lane)*3 + 1] = p1;
                g_gxyz[((size_t)qg*NSAMP + lane)*3 + 2] = p2;
            }
        }
    }
}

// ---------------- GEMM1 fp16 + ldmatrix; now writes packed fp16 PF --------
__global__ __launch_bounds__(256) void gemm1_h(const float* __restrict__ feat)
{
    __shared__ uint32_t As[128*SSTRIDE];
    __shared__ uint32_t Bs[128*SSTRIDE];
    int b = blockIdx.z;
    int mBase = blockIdx.x*128;
    const float* A = feat + (size_t)b*CC*NN;
    const uint32_t* W32 = (const uint32_t*)g_W1h;
    uint32_t* C = g_PFh + ((size_t)b*NN + mBase)*64;
    int tid = threadIdx.x;
    int lane = tid & 31, wid = tid >> 5;
    int wm = wid >> 2, wn = wid & 3;
    int lq = lane >> 2, lr = lane & 3;

    uint32_t asb = (uint32_t)__cvta_generic_to_shared(As);
    uint32_t bsb = (uint32_t)__cvta_generic_to_shared(Bs);
    int arow = (lane & 7) + ((lane >> 3) & 1)*8;
    int akp  = (lane >> 4)*4;
    int brow = (lane & 7) + (lane >> 4)*8;
    int bkp  = ((lane >> 3) & 1)*4;

    float c[4][4][4];
#pragma unroll
    for (int i = 0; i < 4; i++)
#pragma unroll
        for (int j = 0; j < 4; j++)
#pragma unroll
            for (int r = 0; r < 4; r++) c[i][j][r] = 0.f;

    for (int kb = 0; kb < CC/32; kb++) {
#pragma unroll
        for (int r = 0; r < 2; r++) {
            int p = tid + 256*r;
            int cp = p >> 5, m4 = p & 31;
            const float* a0 = A + (size_t)(kb*32 + 2*cp)*NN + mBase + m4*4;
            float4 va = *(const float4*)a0;
            float4 vb = *(const float4*)(a0 + NN);
            As[(m4*4+0)*SSTRIDE + cp] = packh2(va.x, vb.x);
            As[(m4*4+1)*SSTRIDE + cp] = packh2(va.y, vb.y);
            As[(m4*4+2)*SSTRIDE + cp] = packh2(va.z, vb.z);
            As[(m4*4+3)*SSTRIDE + cp] = packh2(va.w, vb.w);
        }
#pragma unroll
        for (int r = 0; r < 8; r++) {
            int p = tid + 256*r;
            int n = p >> 4, wd = p & 15;
            Bs[n*SSTRIDE + wd] = W32[n*(CC/2) + kb*16 + wd];
        }
        __syncthreads();
#pragma unroll
        for (int ks = 0; ks < 2; ks++) {
            int k0 = ks*8;
            uint32_t af[4][4], bf[4][2];
#pragma unroll
            for (int mi = 0; mi < 4; mi++) {
                uint32_t a = asb + (uint32_t)(((wm*64 + mi*16 + arow)*SSTRIDE + k0 + akp)*4);
                LDSM4(af[mi][0], af[mi][1], af[mi][2], af[mi][3], a);
            }
#pragma unroll
            for (int np = 0; np < 2; np++) {
                uint32_t a = bsb + (uint32_t)(((wn*32 + np*16 + brow)*SSTRIDE + k0 + bkp)*4);
                LDSM4(bf[np*2][0], bf[np*2][1], bf[np*2+1][0], bf[np*2+1][1], a);
            }
#pragma unroll
            for (int mi = 0; mi < 4; mi++)
#pragma unroll
                for (int nj = 0; nj < 4; nj++)
                    MMAH(c[mi][nj], af[mi], bf[nj]);
        }
        __syncthreads();
    }
#pragma unroll
    for (int mi = 0; mi < 4; mi++) {
#pragma unroll
        for (int nj = 0; nj < 4; nj++) {
            int gr   = wm*64 + mi*16 + lq;
            int colw = wn*16 + nj*4 + lr;
            C[(size_t)gr*64 + colw]     = packh2(c[mi][nj][0], c[mi][nj][1]);
            C[(size_t)(gr+8)*64 + colw] = packh2(c[mi][nj][2], c[mi][nj][3]);
        }
    }
}

// ---------------- assemble: gathers fp16 PF, writes fp16 Y1 ----------------
__global__ __launch_bounds__(256) void assemble_kernel(const float* __restrict__ w1)
{
    __shared__ float s_wx[HIDC], s_wy[HIDC], s_wz[HIDC];
    __shared__ float s_sum[HIDC], s_sq[HIDC];
    int tid = threadIdx.x, lane = tid & 31, w = tid >> 5;
    if (tid < HIDC) {
        s_wx[tid] = w1[tid*(CC+3) + 0];
        s_wy[tid] = w1[tid*(CC+3) + 1];
        s_wz[tid] = w1[tid*(CC+3) + 2];
        s_sum[tid] = 0.f; s_sq[tid] = 0.f;
    }
    __syncthreads();

    float ls[4] = {0,0,0,0}, lqa[4] = {0,0,0,0};
    float wx[4], wy[4], wz[4];
#pragma unroll
    for (int j = 0; j < 4; j++) {
        int o = lane*4 + j;
        wx[j] = s_wx[o]; wy[j] = s_wy[o]; wz[j] = s_wz[o];
    }
    for (int i = 0; i < 16; i++) {
        int p = blockIdx.x*128 + w*16 + i;
        int b = p >> 13;
        int n = g_idx[p];
        float gx = g_gxyz[(size_t)p*3+0];
        float gy = g_gxyz[(size_t)p*3+1];
        float gz = g_gxyz[(size_t)p*3+2];
        uint2 pv = *(const uint2*)(g_PFh + ((size_t)b*NN + n)*64 + lane*2);
        float2 f0 = __half22float2(*(__half2*)&pv.x);
        float2 f1 = __half22float2(*(__half2*)&pv.y);
        float y[4] = {f0.x, f0.y, f1.x, f1.y};
#pragma unroll
        for (int j = 0; j < 4; j++) {
            float r = y[j] + wx[j]*gx + wy[j]*gy + wz[j]*gz;
            y[j] = r;
            ls[j] += r; lqa[j] += r*r;
        }
        uint2 pk = make_uint2(packh2(y[0], y[1]), packh2(y[2], y[3]));
        *(uint2*)(g_Y1h + (size_t)p*64 + lane*2) = pk;
    }
#pragma unroll
    for (int j = 0; j < 4; j++) {
        atomicAdd(&s_sum[lane*4 + j], ls[j]);
        atomicAdd(&s_sq [lane*4 + j], lqa[j]);
    }
    __syncthreads();
    if (tid < HIDC)      atomicAdd(&g_stats[0*256 + tid], (double)s_sum[tid]);
    else if (tid < 256)  atomicAdd(&g_stats[0*256 + 128 + (tid-128)], (double)s_sq[tid-128]);
}

__global__ void finalize_bn_kernel(int L, const float* __restrict__ g,
                                   const float* __restrict__ be)
{
    int cc = threadIdx.x;
    if (cc >= HIDC) return;
    const double cnt = (double)NPIX;
    double s = g_stats[L*256 + cc];
    double q = g_stats[L*256 + 128 + cc];
    double m = s / cnt;
    double v = q / cnt - m*m;
    if (v < 0.0) v = 0.0;
    float scale = g[cc] / sqrtf((float)v + 1e-5f);
    g_bn[L*384 + cc]       = (float)m;
    g_bn[L*384 + 128 + cc] = scale;
    g_bn[L*384 + 256 + cc] = be[cc];
}

// ---------------- NT GEMM fp16 (unchanged from R11, passing) ----------------
__global__ __launch_bounds__(256) void gemm_nt_h(int layer)
{
    __shared__ uint32_t As[128*NSTR];
    __shared__ uint32_t Bs[128*NSTR];
    __shared__ float s_bnp[384];
    __shared__ float s_sum[HIDC], s_sq[HIDC];
    const uint32_t* Ah = (layer == 1) ? g_Y1h : g_Y2h;
    const uint32_t* W32 = (const uint32_t*)((layer == 1) ? g_W2h : g_W3h);
    const float* bnp = g_bn + (layer-1)*384;

    int tid = threadIdx.x;
    int lane = tid & 31, wid = tid >> 5;
    int wm = wid >> 2, wn = wid & 3;
    int lq = lane >> 2, lr = lane & 3;
    if (tid < HIDC) { s_sum[tid] = 0.f; s_sq[tid] = 0.f; }
    for (int i = tid; i < 384; i += 256) s_bnp[i] = bnp[i];
    __syncthreads();

    size_t mBase = (size_t)blockIdx.x * 128;
    float c[4][4][4];
#pragma unroll
    for (int i = 0; i < 4; i++)
#pragma unroll
        for (int j = 0; j < 4; j++)
#pragma unroll
            for (int r = 0; r < 4; r++) c[i][j][r] = 0.f;

    for (int kb = 0; kb < 2; kb++) {
#pragma unroll
        for (int r = 0; r < 4; r++) {
            int p = tid + 256*r;
            int row = p >> 3, q = p & 7;
            int ch = kb*64 + q*8;
            uint4 v = *(const uint4*)(Ah + (mBase + row)*64 + kb*32 + q*4);
            uint32_t wds[4] = {v.x, v.y, v.z, v.w};
#pragma unroll
            for (int k = 0; k < 4; k++) {
                float2 f = __half22float2(*(__half2*)&wds[k]);
                int cch = ch + 2*k;
                float a0 = fmaxf(0.f, (f.x - s_bnp[cch])  *s_bnp[128+cch]   + s_bnp[256+cch]);
                float a1 = fmaxf(0.f, (f.y - s_bnp[cch+1])*s_bnp[128+cch+1] + s_bnp[256+cch+1]);
                As[row*NSTR + q*4 + k] = packh2(a0, a1);
            }
        }
#pragma unroll
        for (int r = 0; r < 4; r++) {
            int p = tid + 256*r;
            int n = p >> 3, q = p & 7;
            *(uint4*)(Bs + n*NSTR + q*4) = *(const uint4*)(W32 + n*64 + kb*32 + q*4);
        }
        __syncthreads();
#pragma unroll
        for (int ks = 0; ks < 4; ks++) {
            int k0 = ks*8;
            uint32_t af[4][4], bf[4][2];
#pragma unroll
            for (int mi = 0; mi < 4; mi++) {
                int m0 = wm*64 + mi*16;
                af[mi][0] = As[(m0 + lq    )*NSTR + k0 + lr    ];
                af[mi][1] = As[(m0 + 8 + lq)*NSTR + k0 + lr    ];
                af[mi][2] = As[(m0 + lq    )*NSTR + k0 + lr + 4];
                af[mi][3] = As[(m0 + 8 + lq)*NSTR + k0 + lr + 4];
            }
#pragma unroll
            for (int nj = 0; nj < 4; nj++) {
                int n0 = wn*32 + nj*8;
                bf[nj][0] = Bs[(n0+lq)*NSTR + k0 + lr    ];
                bf[nj][1] = Bs[(n0+lq)*NSTR + k0 + lr + 4];
            }
#pragma unroll
            for (int mi = 0; mi < 4; mi++)
#pragma unroll
                for (int nj = 0; nj < 4; nj++)
                    MMAH(c[mi][nj], af[mi], bf[nj]);
        }
        __syncthreads();
    }
    if (layer == 1) {
#pragma unroll
        for (int mi = 0; mi < 4; mi++)
#pragma unroll
            for (int nj = 0; nj < 4; nj++) {
                size_t gr = mBase + wm*64 + mi*16 + lq;
                int colw = wn*16 + nj*4 + lr;
                g_Y2h[gr*64 + colw]     = packh2(c[mi][nj][0], c[mi][nj][1]);
                g_Y2h[(gr+8)*64 + colw] = packh2(c[mi][nj][2], c[mi][nj][3]);
            }
    } else {
#pragma unroll
        for (int mi = 0; mi < 4; mi++) {
            int qg = blockIdx.x*8 + wm*4 + mi;
#pragma unroll
            for (int nj = 0; nj < 4; nj++) {
                float m0v = fmaxf(c[mi][nj][0], c[mi][nj][2]);
                float m1v = fmaxf(c[mi][nj][1], c[mi][nj][3]);
#pragma unroll
                for (int o = 4; o <= 16; o <<= 1) {
                    m0v = fmaxf(m0v, __shfl_xor_sync(0xffffffffu, m0v, o));
                    m1v = fmaxf(m1v, __shfl_xor_sync(0xffffffffu, m1v, o));
                }
                if (lq == 0) {
                    int col = wn*32 + nj*8 + 2*lr;
                    *(float2*)(g_MX + (size_t)qg*HIDC + col) = make_float2(m0v, m1v);
                }
            }
        }
    }
#pragma unroll
    for (int nj = 0; nj < 4; nj++) {
        int ch = wn*32 + nj*8 + 2*lr;
        float s0 = 0.f, q0 = 0.f, s1 = 0.f, q1 = 0.f;
#pragma unroll
        for (int mi = 0; mi < 4; mi++) {
            float x;
            x = c[mi][nj][0]; s0 += x; q0 += x*x;
            x = c[mi][nj][2]; s0 += x; q0 += x*x;
            x = c[mi][nj][1]; s1 += x; q1 += x*x;
            x = c[mi][nj][3]; s1 += x; q1 += x*x;
        }
        atomicAdd(&s_sum[ch],   s0); atomicAdd(&s_sq[ch],   q0);
        atomicAdd(&s_sum[ch+1], s1); atomicAdd(&s_sq[ch+1], q1);
    }
    __syncthreads();
    if (tid < HIDC)      atomicAdd(&g_stats[layer*256 + tid], (double)s_sum[tid]);
    else if (tid < 256)  atomicAdd(&g_stats[layer*256 + 128 + (tid-128)], (double)s_sq[tid-128]);
}

// ---------------- BN3+ReLU on g_MX + transpose (unchanged) ----------------
__global__ __launch_bounds__(256) void maxfinal_kernel(float* __restrict__ out)
{
    __shared__ float T[HIDC][33];
    int b = blockIdx.x >> 4, pb = blockIdx.x & 15;
    int tid = threadIdx.x;
    const float* bnp = g_bn + 2*384;
#pragma unroll
    for (int r = 0; r < 16; r++) {
        int idx = tid + 256*r;
        int ql = idx >> 7, c = idx & 127;
        float v = g_MX[((size_t)(b*NPQ + pb*32 + ql))*HIDC + c];
        T[c][ql] = fmaxf(0.f, (v - bnp[c])*bnp[128+c] + bnp[256+c]);
    }
    __syncthreads();
#pragma unroll
    for (int r = 0; r < 16; r++) {
        int flat = tid + 256*r;
        int o = flat >> 5, pl = flat & 31;
        out[OUT_FEAT + (size_t)b*(HIDC*NPQ) + (size_t)o*NPQ + pb*32 + pl] = T[o][pl];
    }
}

// ---------------------------------------------------------------------------
extern "C" void kernel_launch(void* const* d_in, const int* in_sizes, int n_in,
                              void* d_out, int out_size)
{
    const float* xyz  = (const float*)d_in[0];
    const float* feat = (const float*)d_in[1];
    const float* seed = (const float*)d_in[2];
    const float* w1   = (const float*)d_in[3];
    const float* g1   = (const float*)d_in[4];
    const float* be1  = (const float*)d_in[5];
    const float* w2   = (const float*)d_in[6];
    const float* g2   = (const float*)d_in[7];
    const float* be2  = (const float*)d_in[8];
    const float* w3   = (const float*)d_in[9];
    const float* g3   = (const float*)d_in[10];
    const float* be3  = (const float*)d_in[11];
    float* out = (float*)d_out;

    zero_stats_kernel<<<3, 256>>>();
    prep_w_kernel<<<HIDC, CC>>>(w1, w2, w3);
    fps_kernel<<<BB, 1024>>>(seed, xyz, out);
    gemm1_h<<<dim3(NN/128, 1, BB), 256>>>(feat);
    bq2_kernel<<<(BB*NPQ)/32, 256>>>(xyz, out);
    assemble_kernel<<<NPIX/128, 256>>>(w1);
    finalize_bn_kernel<<<1, 128>>>(0, g1, be1);
    gemm_nt_h<<<NPIX/128, 256>>>(1);
    finalize_bn_kernel<<<1, 128>>>(1, g2, be2);
    gemm_nt_h<<<NPIX/128, 256>>>(2);
    finalize_bn_kernel<<<1, 128>>>(2, g3, be3);
    maxfinal_kernel<<<BB*16, 256>>>(out);
}

// round 13
// speedup vs baseline: 1.3467x; 1.0410x over previous
#include <cuda_runtime.h>
#include <cuda_fp16.h>
#include <math.h>
#include <stdint.h>

#define BB    32
#define NN    4096
#define NPQ   512
#define NSAMP 16
#define CC    256
#define HIDC  128
#define NPIX  (BB*NPQ*NSAMP)
#define NPTS  (BB*NN)

#define OUT_FEAT (BB*NPQ*3)
#define OUT_INDS (OUT_FEAT + BB*HIDC*NPQ)

__device__ uint32_t g_PFh[(size_t)NPTS*64];   // fp16x2 packed conv1 feature part
__device__ uint32_t g_Y1h[(size_t)NPIX*64];   // fp16x2 packed [pix][128ch]
__device__ uint32_t g_Y2h[(size_t)NPIX*64];
__device__ float    g_MX[(size_t)BB*NPQ*HIDC];
__device__ int      g_idx[NPIX];
__device__ float    g_gxyz[(size_t)NPIX*3];
__device__ double   g_stats[3*2*HIDC];
__device__ float    g_bn[3*3*HIDC];
__device__ __half   g_W1h[HIDC*CC];
__device__ __half   g_W2h[HIDC*HIDC];
__device__ __half   g_W3h[HIDC*HIDC];

#define MMAH(c, a, b) asm volatile( \
  "mma.sync.aligned.m16n8k16.row.col.f32.f16.f16.f32 " \
  "{%0,%1,%2,%3}, {%4,%5,%6,%7}, {%8,%9}, {%0,%1,%2,%3};" \
  : "+f"((c)[0]), "+f"((c)[1]), "+f"((c)[2]), "+f"((c)[3]) \
  : "r"((a)[0]), "r"((a)[1]), "r"((a)[2]), "r"((a)[3]), "r"((b)[0]), "r"((b)[1]))

#define LDSM4(r0, r1, r2, r3, a) asm volatile( \
  "ldmatrix.sync.aligned.m8n8.x4.shared.b16 {%0,%1,%2,%3}, [%4];" \
  : "=r"(r0), "=r"(r1), "=r"(r2), "=r"(r3) : "r"(a))

#define SSTRIDE 20   /* gemm1: 80B rows, conflict-free ldmatrix */
#define NSTR 36      /* gemm_nt: 64-ch chunk rows, conflict-free scalar frags */

__device__ __forceinline__ uint32_t packh2(float x, float y) {
    __half2 h = __floats2half2_rn(x, y);
    return *(uint32_t*)&h;
}

__global__ void zero_stats_kernel() {
    int i = blockIdx.x*256 + threadIdx.x;
    if (i < 3*2*HIDC) g_stats[i] = 0.0;
}
__global__ void prep_w_kernel(const float* __restrict__ w1,
                              const float* __restrict__ w2,
                              const float* __restrict__ w3) {
    int o = blockIdx.x, k = threadIdx.x;
    g_W1h[o*CC + k] = __float2half_rn(w1[o*(CC+3) + 3 + k]);
    if (k < HIDC) {
        g_W2h[o*HIDC + k] = __float2half_rn(w2[o*HIDC + k]);
        g_W3h[o*HIDC + k] = __float2half_rn(w3[o*HIDC + k]);
    }
}

// ---------------- FPS v3: 512 threads, 8 pts/thread, 16-warp reduce --------
// Same fp math and global-index tie-break semantics as passing R11/R12.
__global__ __launch_bounds__(512) void fps_kernel(
    const float* __restrict__ seed, const float* __restrict__ xyz,
    float* __restrict__ out)
{
    int b = blockIdx.x, t = threadIdx.x;
    int lane = t & 31, wid = t >> 5;          // 16 warps
    __shared__ float s_cv[2][16], s_cx[2][16], s_cy[2][16], s_cz[2][16];
    __shared__ int   s_ci[2][16];
    __shared__ int   s_inds[NPQ];

    const float* sb = seed + (size_t)b*NN*3;
    float px[8], py[8], pz[8], dist[8];
#pragma unroll
    for (int j = 0; j < 8; j++) {
        int i = t + j*512;
        px[j] = sb[i*3+0]; py[j] = sb[i*3+1]; pz[j] = sb[i*3+2];
        dist[j] = 1e10f;
    }
    if (t == 0) s_inds[0] = 0;
    float lx = sb[0], ly = sb[1], lz = sb[2];

    for (int it = 1; it < NPQ; ++it) {
        float bv = -1.0f; int bi = 0;
        float bx = 0.f, by = 0.f, bz = 0.f;
#pragma unroll
        for (int j = 0; j < 8; j++) {
            float dx = __fadd_rn(px[j], -lx);
            float dy = __fadd_rn(py[j], -ly);
            float dz = __fadd_rn(pz[j], -lz);
            float d  = __fadd_rn(__fadd_rn(__fmul_rn(dx,dx), __fmul_rn(dy,dy)),
                                 __fmul_rn(dz,dz));
            dist[j] = fminf(dist[j], d);
            if (dist[j] > bv) { bv = dist[j]; bi = t + j*512;
                                bx = px[j]; by = py[j]; bz = pz[j]; }
        }
        // warp winner: max dist-bits (nonneg float bit-monotone), min index tie
        unsigned fb = __float_as_uint(bv);
        unsigned m  = __reduce_max_sync(0xffffffffu, fb);
        unsigned cand = (fb == m) ? (unsigned)bi : 0xffffffffu;
        unsigned cmin = __reduce_min_sync(0xffffffffu, cand);
        int buf = it & 1;
        if (fb == m && (unsigned)bi == cmin) {   // exactly one lane per warp
            s_cv[buf][wid] = bv; s_ci[buf][wid] = bi;
            s_cx[buf][wid] = bx; s_cy[buf][wid] = by; s_cz[buf][wid] = bz;
        }
        __syncthreads();
        // all warps redundantly reduce the 16 candidates (slots replicated 2x)
        int slot = lane & 15;
        float v  = s_cv[buf][slot];
        int   ci = s_ci[buf][slot];
        unsigned fb2 = __float_as_uint(v);
        unsigned m2  = __reduce_max_sync(0xffffffffu, fb2);
        unsigned cand2 = (fb2 == m2) ? (unsigned)ci : 0xffffffffu;
        unsigned cmin2 = __reduce_min_sync(0xffffffffu, cand2);
        unsigned wmask = __ballot_sync(0xffffffffu, fb2 == m2 && (unsigned)ci == cmin2);
        int sl = (__ffs(wmask) - 1) & 15;
        lx = s_cx[buf][sl]; ly = s_cy[buf][sl]; lz = s_cz[buf][sl];
        if (t == 0) s_inds[it] = (int)cmin2;
    }
    __syncthreads();
    for (int i = t; i < NPQ; i += 512) {
        int id = s_inds[i];
        out[OUT_INDS + b*NPQ + i] = (float)id;
        const float* xb = xyz + ((size_t)b*NN + id)*3;
        out[((size_t)b*NPQ + i)*3 + 0] = xb[0];
        out[((size_t)b*NPQ + i)*3 + 1] = xb[1];
        out[((size_t)b*NPQ + i)*3 + 2] = xb[2];
    }
}

// ---------------- Ball query (unchanged, passing) ----------------
__global__ __launch_bounds__(256) void bq2_kernel(
    const float* __restrict__ xyz, const float* __restrict__ out)
{
    __shared__ float sx[NN], sy[NN], sz[NN];
    int tid = threadIdx.x, lane = tid & 31, w = tid >> 5;
    int qbase = blockIdx.x * 32;
    int b = qbase >> 9;
    const float* xb = xyz + (size_t)b*NN*3;
    for (int i = tid; i < NN; i += 256) {
        sx[i] = xb[i*3+0]; sy[i] = xb[i*3+1]; sz[i] = xb[i*3+2];
    }
    __syncthreads();

    const float R2c = (float)(0.3*0.3);
    const float RAD = 0.3f;
    int q0 = qbase + w*4;
    float qx[4], qy[4], qz[4];
    int found[4], first[4];
#pragma unroll
    for (int j = 0; j < 4; j++) {
        qx[j] = out[(size_t)(q0+j)*3+0];
        qy[j] = out[(size_t)(q0+j)*3+1];
        qz[j] = out[(size_t)(q0+j)*3+2];
        found[j] = 0; first[j] = -1;
    }
    for (int s = 0; s < NN/32; s++) {
        int i = s*32 + lane;
        float x = sx[i], y = sy[i], z = sz[i];
        bool pr[4];
#pragma unroll
        for (int j = 0; j < 4; j++) {
            float dx = __fadd_rn(qx[j], -x);
            float dy = __fadd_rn(qy[j], -y);
            float dz = __fadd_rn(qz[j], -z);
            float d  = __fadd_rn(__fadd_rn(__fmul_rn(dx,dx), __fmul_rn(dy,dy)),
                                 __fmul_rn(dz,dz));
            pr[j] = (d < R2c) && (found[j] < NSAMP);
        }
        unsigned anym = __ballot_sync(0xffffffffu, pr[0]|pr[1]|pr[2]|pr[3]);
        if (anym) {
#pragma unroll
            for (int j = 0; j < 4; j++) {
                if (found[j] >= NSAMP) continue;
                unsigned mask = __ballot_sync(0xffffffffu, pr[j]);
                if (!mask) continue;
                if (first[j] < 0) first[j] = s*32 + __ffs(mask) - 1;
                if (pr[j]) {
                    int pos = found[j] + __popc(mask & ((1u << lane) - 1u));
                    if (pos < NSAMP) {
                        int qg = q0 + j;
                        g_idx[qg*NSAMP + pos] = i;
                        g_gxyz[((size_t)qg*NSAMP + pos)*3 + 0] = __fdiv_rn(__fadd_rn(x, -qx[j]), RAD);
                        g_gxyz[((size_t)qg*NSAMP + pos)*3 + 1] = __fdiv_rn(__fadd_rn(y, -qy[j]), RAD);
                        g_gxyz[((size_t)qg*NSAMP + pos)*3 + 2] = __fdiv_rn(__fadd_rn(z, -qz[j]), RAD);
                    }
                }
                found[j] += __popc(mask);
            }
            if (found[0] >= NSAMP && found[1] >= NSAMP &&
                found[2] >= NSAMP && found[3] >= NSAMP) break;
        }
    }
#pragma unroll
    for (int j = 0; j < 4; j++) {
        if (found[j] < NSAMP) {
            int fi = first[j];
            float x = sx[fi], y = sy[fi], z = sz[fi];
            float p0 = __fdiv_rn(__fadd_rn(x, -qx[j]), RAD);
            float p1 = __fdiv_rn(__fadd_rn(y, -qy[j]), RAD);
            float p2 = __fdiv_rn(__fadd_rn(z, -qz[j]), RAD);
            if (lane >= found[j] && lane < NSAMP) {
                int qg = q0 + j;
                g_idx[qg*NSAMP + lane] = fi;
                g_gxyz[((size_t)qg*NSAMP + lane)*3 + 0] = p0;
                g_gxyz[((size_t)qg*NSAMP + lane)*3 + 1] = p1;
                g_gxyz[((size_t)qg*NSAMP + lane)*3 + 2] = p2;
            }
        }
    }
}

// ---------------- GEMM1 fp16 + ldmatrix (unchanged, passing) ----------------
__global__ __launch_bounds__(256) void gemm1_h(const float* __restrict__ feat)
{
    __shared__ uint32_t As[128*SSTRIDE];
    __shared__ uint32_t Bs[128*SSTRIDE];
    int b = blockIdx.z;
    int mBase = blockIdx.x*128;
    const float* A = feat + (size_t)b*CC*NN;
    const uint32_t* W32 = (const uint32_t*)g_W1h;
    uint32_t* C = g_PFh + ((size_t)b*NN + mBase)*64;
    int tid = threadIdx.x;
    int lane = tid & 31, wid = tid >> 5;
    int wm = wid >> 2, wn = wid & 3;
    int lq = lane >> 2, lr = lane & 3;

    uint32_t asb = (uint32_t)__cvta_generic_to_shared(As);
    uint32_t bsb = (uint32_t)__cvta_generic_to_shared(Bs);
    int arow = (lane & 7) + ((lane >> 3) & 1)*8;
    int akp  = (lane >> 4)*4;
    int brow = (lane & 7) + (lane >> 4)*8;
    int bkp  = ((lane >> 3) & 1)*4;

    float c[4][4][4];
#pragma unroll
    for (int i = 0; i < 4; i++)
#pragma unroll
        for (int j = 0; j < 4; j++)
#pragma unroll
            for (int r = 0; r < 4; r++) c[i][j][r] = 0.f;

    for (int kb = 0; kb < CC/32; kb++) {
#pragma unroll
        for (int r = 0; r < 2; r++) {
            int p = tid + 256*r;
            int cp = p >> 5, m4 = p & 31;
            const float* a0 = A + (size_t)(kb*32 + 2*cp)*NN + mBase + m4*4;
            float4 va = *(const float4*)a0;
            float4 vb = *(const float4*)(a0 + NN);
            As[(m4*4+0)*SSTRIDE + cp] = packh2(va.x, vb.x);
            As[(m4*4+1)*SSTRIDE + cp] = packh2(va.y, vb.y);
            As[(m4*4+2)*SSTRIDE + cp] = packh2(va.z, vb.z);
            As[(m4*4+3)*SSTRIDE + cp] = packh2(va.w, vb.w);
        }
#pragma unroll
        for (int r = 0; r < 8; r++) {
            int p = tid + 256*r;
            int n = p >> 4, wd = p & 15;
            Bs[n*SSTRIDE + wd] = W32[n*(CC/2) + kb*16 + wd];
        }
        __syncthreads();
#pragma unroll
        for (int ks = 0; ks < 2; ks++) {
            int k0 = ks*8;
            uint32_t af[4][4], bf[4][2];
#pragma unroll
            for (int mi = 0; mi < 4; mi++) {
                uint32_t a = asb + (uint32_t)(((wm*64 + mi*16 + arow)*SSTRIDE + k0 + akp)*4);
                LDSM4(af[mi][0], af[mi][1], af[mi][2], af[mi][3], a);
            }
#pragma unroll
            for (int np = 0; np < 2; np++) {
                uint32_t a = bsb + (uint32_t)(((wn*32 + np*16 + brow)*SSTRIDE + k0 + bkp)*4);
                LDSM4(bf[np*2][0], bf[np*2][1], bf[np*2+1][0], bf[np*2+1][1], a);
            }
#pragma unroll
            for (int mi = 0; mi < 4; mi++)
#pragma unroll
                for (int nj = 0; nj < 4; nj++)
                    MMAH(c[mi][nj], af[mi], bf[nj]);
        }
        __syncthreads();
    }
#pragma unroll
    for (int mi = 0; mi < 4; mi++) {
#pragma unroll
        for (int nj = 0; nj < 4; nj++) {
            int gr   = wm*64 + mi*16 + lq;
            int colw = wn*16 + nj*4 + lr;
            C[(size_t)gr*64 + colw]     = packh2(c[mi][nj][0], c[mi][nj][1]);
            C[(size_t)(gr+8)*64 + colw] = packh2(c[mi][nj][2], c[mi][nj][3]);
        }
    }
}

// ---------------- assemble (unchanged from R12, passing) ----------------
__global__ __launch_bounds__(256) void assemble_kernel(const float* __restrict__ w1)
{
    __shared__ float s_wx[HIDC], s_wy[HIDC], s_wz[HIDC];
    __shared__ float s_sum[HIDC], s_sq[HIDC];
    int tid = threadIdx.x, lane = tid & 31, w = tid >> 5;
    if (tid < HIDC) {
        s_wx[tid] = w1[tid*(CC+3) + 0];
        s_wy[tid] = w1[tid*(CC+3) + 1];
        s_wz[tid] = w1[tid*(CC+3) + 2];
        s_sum[tid] = 0.f; s_sq[tid] = 0.f;
    }
    __syncthreads();

    float ls[4] = {0,0,0,0}, lqa[4] = {0,0,0,0};
    float wx[4], wy[4], wz[4];
#pragma unroll
    for (int j = 0; j < 4; j++) {
        int o = lane*4 + j;
        wx[j] = s_wx[o]; wy[j] = s_wy[o]; wz[j] = s_wz[o];
    }
    for (int i = 0; i < 16; i++) {
        int p = blockIdx.x*128 + w*16 + i;
        int b = p >> 13;
        int n = g_idx[p];
        float gx = g_gxyz[(size_t)p*3+0];
        float gy = g_gxyz[(size_t)p*3+1];
        float gz = g_gxyz[(size_t)p*3+2];
        uint2 pv = *(const uint2*)(g_PFh + ((size_t)b*NN + n)*64 + lane*2);
        float2 f0 = __half22float2(*(__half2*)&pv.x);
        float2 f1 = __half22float2(*(__half2*)&pv.y);
        float y[4] = {f0.x, f0.y, f1.x, f1.y};
#pragma unroll
        for (int j = 0; j < 4; j++) {
            float r = y[j] + wx[j]*gx + wy[j]*gy + wz[j]*gz;
            y[j] = r;
            ls[j] += r; lqa[j] += r*r;
        }
        uint2 pk = make_uint2(packh2(y[0], y[1]), packh2(y[2], y[3]));
        *(uint2*)(g_Y1h + (size_t)p*64 + lane*2) = pk;
    }
#pragma unroll
    for (int j = 0; j < 4; j++) {
        atomicAdd(&s_sum[lane*4 + j], ls[j]);
        atomicAdd(&s_sq [lane*4 + j], lqa[j]);
    }
    __syncthreads();
    if (tid < HIDC)      atomicAdd(&g_stats[0*256 + tid], (double)s_sum[tid]);
    else if (tid < 256)  atomicAdd(&g_stats[0*256 + 128 + (tid-128)], (double)s_sq[tid-128]);
}

__global__ void finalize_bn_kernel(int L, const float* __restrict__ g,
                                   const float* __restrict__ be)
{
    int cc = threadIdx.x;
    if (cc >= HIDC) return;
    const double cnt = (double)NPIX;
    double s = g_stats[L*256 + cc];
    double q = g_stats[L*256 + 128 + cc];
    double m = s / cnt;
    double v = q / cnt - m*m;
    if (v < 0.0) v = 0.0;
    float scale = g[cc] / sqrtf((float)v + 1e-5f);
    g_bn[L*384 + cc]       = (float)m;
    g_bn[L*384 + 128 + cc] = scale;
    g_bn[L*384 + 256 + cc] = be[cc];
}

// ---------------- NT GEMM fp16 (unchanged from R12, passing) ----------------
__global__ __launch_bounds__(256) void gemm_nt_h(int layer)
{
    __shared__ uint32_t As[128*NSTR];
    __shared__ uint32_t Bs[128*NSTR];
    __shared__ float s_bnp[384];
    __shared__ float s_sum[HIDC], s_sq[HIDC];
    const uint32_t* Ah = (layer == 1) ? g_Y1h : g_Y2h;
    const uint32_t* W32 = (const uint32_t*)((layer == 1) ? g_W2h : g_W3h);
    const float* bnp = g_bn + (layer-1)*384;

    int tid = threadIdx.x;
    int lane = tid & 31, wid = tid >> 5;
    int wm = wid >> 2, wn = wid & 3;
    int lq = lane >> 2, lr = lane & 3;
    if (tid < HIDC) { s_sum[tid] = 0.f; s_sq[tid] = 0.f; }
    for (int i = tid; i < 384; i += 256) s_bnp[i] = bnp[i];
    __syncthreads();

    size_t mBase = (size_t)blockIdx.x * 128;
    float c[4][4][4];
#pragma unroll
    for (int i = 0; i < 4; i++)
#pragma unroll
        for (int j = 0; j < 4; j++)
#pragma unroll
            for (int r = 0; r < 4; r++) c[i][j][r] = 0.f;

    for (int kb = 0; kb < 2; kb++) {
#pragma unroll
        for (int r = 0; r < 4; r++) {
            int p = tid + 256*r;
            int row = p >> 3, q = p & 7;
            int ch = kb*64 + q*8;
            uint4 v = *(const uint4*)(Ah + (mBase + row)*64 + kb*32 + q*4);
            uint32_t wds[4] = {v.x, v.y, v.z, v.w};
#pragma unroll
            for (int k = 0; k < 4; k++) {
                float2 f = __half22float2(*(__half2*)&wds[k]);
                int cch = ch + 2*k;
                float a0 = fmaxf(0.f, (f.x - s_bnp[cch])  *s_bnp[128+cch]   + s_bnp[256+cch]);
                float a1 = fmaxf(0.f, (f.y - s_bnp[cch+1])*s_bnp[128+cch+1] + s_bnp[256+cch+1]);
                As[row*NSTR + q*4 + k] = packh2(a0, a1);
            }
        }
#pragma unroll
        for (int r = 0; r < 4; r++) {
            int p = tid + 256*r;
            int n = p >> 3, q = p & 7;
            *(uint4*)(Bs + n*NSTR + q*4) = *(const uint4*)(W32 + n*64 + kb*32 + q*4);
        }
        __syncthreads();
#pragma unroll
        for (int ks = 0; ks < 4; ks++) {
            int k0 = ks*8;
            uint32_t af[4][4], bf[4][2];
#pragma unroll
            for (int mi = 0; mi < 4; mi++) {
                int m0 = wm*64 + mi*16;
                af[mi][0] = As[(m0 + lq    )*NSTR + k0 + lr    ];
                af[mi][1] = As[(m0 + 8 + lq)*NSTR + k0 + lr    ];
                af[mi][2] = As[(m0 + lq    )*NSTR + k0 + lr + 4];
                af[mi][3] = As[(m0 + 8 + lq)*NSTR + k0 + lr + 4];
            }
#pragma unroll
            for (int nj = 0; nj < 4; nj++) {
                int n0 = wn*32 + nj*8;
                bf[nj][0] = Bs[(n0+lq)*NSTR + k0 + lr    ];
                bf[nj][1] = Bs[(n0+lq)*NSTR + k0 + lr + 4];
            }
#pragma unroll
            for (int mi = 0; mi < 4; mi++)
#pragma unroll
                for (int nj = 0; nj < 4; nj++)
                    MMAH(c[mi][nj], af[mi], bf[nj]);
        }
        __syncthreads();
    }
    if (layer == 1) {
#pragma unroll
        for (int mi = 0; mi < 4; mi++)
#pragma unroll
            for (int nj = 0; nj < 4; nj++) {
                size_t gr = mBase + wm*64 + mi*16 + lq;
                int colw = wn*16 + nj*4 + lr;
                g_Y2h[gr*64 + colw]     = packh2(c[mi][nj][0], c[mi][nj][1]);
                g_Y2h[(gr+8)*64 + colw] = packh2(c[mi][nj][2], c[mi][nj][3]);
            }
    } else {
#pragma unroll
        for (int mi = 0; mi < 4; mi++) {
            int qg = blockIdx.x*8 + wm*4 + mi;
#pragma unroll
            for (int nj = 0; nj < 4; nj++) {
                float m0v = fmaxf(c[mi][nj][0], c[mi][nj][2]);
                float m1v = fmaxf(c[mi][nj][1], c[mi][nj][3]);
#pragma unroll
                for (int o = 4; o <= 16; o <<= 1) {
                    m0v = fmaxf(m0v, __shfl_xor_sync(0xffffffffu, m0v, o));
                    m1v = fmaxf(m1v, __shfl_xor_sync(0xffffffffu, m1v, o));
                }
                if (lq == 0) {
                    int col = wn*32 + nj*8 + 2*lr;
                    *(float2*)(g_MX + (size_t)qg*HIDC + col) = make_float2(m0v, m1v);
                }
            }
        }
    }
#pragma unroll
    for (int nj = 0; nj < 4; nj++) {
        int ch = wn*32 + nj*8 + 2*lr;
        float s0 = 0.f, q0 = 0.f, s1 = 0.f, q1 = 0.f;
#pragma unroll
        for (int mi = 0; mi < 4; mi++) {
            float x;
            x = c[mi][nj][0]; s0 += x; q0 += x*x;
            x = c[mi][nj][2]; s0 += x; q0 += x*x;
            x = c[mi][nj][1]; s1 += x; q1 += x*x;
            x = c[mi][nj][3]; s1 += x; q1 += x*x;
        }
        atomicAdd(&s_sum[ch],   s0); atomicAdd(&s_sq[ch],   q0);
        atomicAdd(&s_sum[ch+1], s1); atomicAdd(&s_sq[ch+1], q1);
    }
    __syncthreads();
    if (tid < HIDC)      atomicAdd(&g_stats[layer*256 + tid], (double)s_sum[tid]);
    else if (tid < 256)  atomicAdd(&g_stats[layer*256 + 128 + (tid-128)], (double)s_sq[tid-128]);
}

// ---------------- BN3+ReLU on g_MX + transpose (unchanged) ----------------
__global__ __launch_bounds__(256) void maxfinal_kernel(float* __restrict__ out)
{
    __shared__ float T[HIDC][33];
    int b = blockIdx.x >> 4, pb = blockIdx.x & 15;
    int tid = threadIdx.x;
    const float* bnp = g_bn + 2*384;
#pragma unroll
    for (int r = 0; r < 16; r++) {
        int idx = tid + 256*r;
        int ql = idx >> 7, c = idx & 127;
        float v = g_MX[((size_t)(b*NPQ + pb*32 + ql))*HIDC + c];
        T[c][ql] = fmaxf(0.f, (v - bnp[c])*bnp[128+c] + bnp[256+c]);
    }
    __syncthreads();
#pragma unroll
    for (int r = 0; r < 16; r++) {
        int flat = tid + 256*r;
        int o = flat >> 5, pl = flat & 31;
        out[OUT_FEAT + (size_t)b*(HIDC*NPQ) + (size_t)o*NPQ + pb*32 + pl] = T[o][pl];
    }
}

// ---------------------------------------------------------------------------
extern "C" void kernel_launch(void* const* d_in, const int* in_sizes, int n_in,
                              void* d_out, int out_size)
{
    const float* xyz  = (const float*)d_in[0];
    const float* feat = (const float*)d_in[1];
    const float* seed = (const float*)d_in[2];
    const float* w1   = (const float*)d_in[3];
    const float* g1   = (const float*)d_in[4];
    const float* be1  = (const float*)d_in[5];
    const float* w2   = (const float*)d_in[6];
    const float* g2   = (const float*)d_in[7];
    const float* be2  = (const float*)d_in[8];
    const float* w3   = (const float*)d_in[9];
    const float* g3   = (const float*)d_in[10];
    const float* be3  = (const float*)d_in[11];
    float* out = (float*)d_out;

    // fps moved to launch index 3 so the profiler captures it next round.
    zero_stats_kernel<<<3, 256>>>();
    prep_w_kernel<<<HIDC, CC>>>(w1, w2, w3);
    gemm1_h<<<dim3(NN/128, 1, BB), 256>>>(feat);
    fps_kernel<<<BB, 512>>>(seed, xyz, out);
    bq2_kernel<<<(BB*NPQ)/32, 256>>>(xyz, out);
    assemble_kernel<<<NPIX/128, 256>>>(w1);
    finalize_bn_kernel<<<1, 128>>>(0, g1, be1);
    gemm_nt_h<<<NPIX/128, 256>>>(1);
    finalize_bn_kernel<<<1, 128>>>(1, g2, be2);
    gemm_nt_h<<<NPIX/128, 256>>>(2);
    finalize_bn_kernel<<<1, 128>>>(2, g3, be3);
    maxfinal_kernel<<<BB*16, 256>>>(out);
}

// round 14
// speedup vs baseline: 1.3936x; 1.0348x over previous
#include <cuda_runtime.h>
#include <cuda_fp16.h>
#include <math.h>
#include <stdint.h>

#define BB    32
#define NN    4096
#define NPQ   512
#define NSAMP 16
#define CC    256
#define HIDC  128
#define NPIX  (BB*NPQ*NSAMP)
#define NPTS  (BB*NN)

#define OUT_FEAT (BB*NPQ*3)
#define OUT_INDS (OUT_FEAT + BB*HIDC*NPQ)

__device__ uint32_t g_PFh[(size_t)NPTS*64];   // fp16x2 packed conv1 feature part
__device__ uint32_t g_Y1h[(size_t)NPIX*64];   // fp16x2 packed [pix][128ch]
__device__ uint32_t g_Y2h[(size_t)NPIX*64];
__device__ float    g_MX[(size_t)BB*NPQ*HIDC];
__device__ int      g_idx[NPIX];
__device__ float    g_gxyz[(size_t)NPIX*3];
__device__ double   g_stats[3*2*HIDC];
__device__ float    g_bn[3*3*HIDC];
__device__ __half   g_W1h[HIDC*CC];
__device__ __half   g_W2h[HIDC*HIDC];
__device__ __half   g_W3h[HIDC*HIDC];

#define MMAH(c, a, b) asm volatile( \
  "mma.sync.aligned.m16n8k16.row.col.f32.f16.f16.f32 " \
  "{%0,%1,%2,%3}, {%4,%5,%6,%7}, {%8,%9}, {%0,%1,%2,%3};" \
  : "+f"((c)[0]), "+f"((c)[1]), "+f"((c)[2]), "+f"((c)[3]) \
  : "r"((a)[0]), "r"((a)[1]), "r"((a)[2]), "r"((a)[3]), "r"((b)[0]), "r"((b)[1]))

#define LDSM4(r0, r1, r2, r3, a) asm volatile( \
  "ldmatrix.sync.aligned.m8n8.x4.shared.b16 {%0,%1,%2,%3}, [%4];" \
  : "=r"(r0), "=r"(r1), "=r"(r2), "=r"(r3) : "r"(a))

#define SSTRIDE 20   /* gemm1: 80B rows, conflict-free ldmatrix */
#define NSTR 36      /* gemm_nt: 64-ch chunk rows, conflict-free scalar frags */
#define FPS_SMEM (12864*4)   /* 3*4096 coords + 512 inds + 2*16 cv + 2*16 ci */

__device__ __forceinline__ uint32_t packh2(float x, float y) {
    __half2 h = __floats2half2_rn(x, y);
    return *(uint32_t*)&h;
}

__global__ void zero_stats_kernel() {
    int i = blockIdx.x*256 + threadIdx.x;
    if (i < 3*2*HIDC) g_stats[i] = 0.0;
}
__global__ void prep_w_kernel(const float* __restrict__ w1,
                              const float* __restrict__ w2,
                              const float* __restrict__ w3) {
    int o = blockIdx.x, k = threadIdx.x;
    g_W1h[o*CC + k] = __float2half_rn(w1[o*(CC+3) + 3 + k]);
    if (k < HIDC) {
        g_W2h[o*HIDC + k] = __float2half_rn(w2[o*HIDC + k]);
        g_W3h[o*HIDC + k] = __float2half_rn(w3[o*HIDC + k]);
    }
}

// ---------------- FPS v4: no coord carries; winner coords via smem bcast ----
// Same fp math and global-index tie-break semantics as passing R13.
__global__ __launch_bounds__(512) void fps_kernel(
    const float* __restrict__ seed, const float* __restrict__ xyz,
    float* __restrict__ out)
{
    extern __shared__ float fsm[];
    float* s_px  = fsm;                 // 4096
    float* s_py  = fsm + 4096;
    float* s_pz  = fsm + 8192;
    int*   s_inds = (int*)(fsm + 12288);     // 512
    float* s_cv  = fsm + 12800;              // 2*16
    int*   s_ci  = (int*)(fsm + 12832);      // 2*16

    int b = blockIdx.x, t = threadIdx.x;
    int lane = t & 31, wid = t >> 5;

    const float* sb = seed + (size_t)b*NN*3;
    float px[8], py[8], pz[8], dist[8];
#pragma unroll
    for (int j = 0; j < 8; j++) {
        int i = t + j*512;
        float x = sb[i*3+0], y = sb[i*3+1], z = sb[i*3+2];
        px[j] = x; py[j] = y; pz[j] = z;
        s_px[i] = x; s_py[i] = y; s_pz[i] = z;
        dist[j] = 1e10f;
    }
    if (t == 0) s_inds[0] = 0;
    __syncthreads();
    float lx = s_px[0], ly = s_py[0], lz = s_pz[0];

    for (int it = 1; it < NPQ; ++it) {
        float bv = -1.0f; int bi = 0;
#pragma unroll
        for (int j = 0; j < 8; j++) {
            float dx = __fadd_rn(px[j], -lx);
            float dy = __fadd_rn(py[j], -ly);
            float dz = __fadd_rn(pz[j], -lz);
            float d  = __fadd_rn(__fadd_rn(__fmul_rn(dx,dx), __fmul_rn(dy,dy)),
                                 __fmul_rn(dz,dz));
            dist[j] = fminf(dist[j], d);
            if (dist[j] > bv) { bv = dist[j]; bi = t + j*512; }
        }
        // warp winner: max dist-bits (nonneg float bit-monotone), min index tie
        unsigned fb = __float_as_uint(bv);
        unsigned m  = __reduce_max_sync(0xffffffffu, fb);
        unsigned cand = (fb == m) ? (unsigned)bi : 0xffffffffu;
        unsigned cmin = __reduce_min_sync(0xffffffffu, cand);
        int buf = it & 1;
        if (fb == m && (unsigned)bi == cmin) {   // exactly one lane per warp
            s_cv[buf*16 + wid] = bv; s_ci[buf*16 + wid] = bi;
        }
        __syncthreads();
        // all warps redundantly reduce the 16 candidates (slots replicated 2x)
        int slot = lane & 15;
        float v  = s_cv[buf*16 + slot];
        int   ci = s_ci[buf*16 + slot];
        unsigned fb2 = __float_as_uint(v);
        unsigned m2  = __reduce_max_sync(0xffffffffu, fb2);
        unsigned cand2 = (fb2 == m2) ? (unsigned)ci : 0xffffffffu;
        unsigned gi = __reduce_min_sync(0xffffffffu, cand2);
        lx = s_px[gi]; ly = s_py[gi]; lz = s_pz[gi];
        if (t == 0) s_inds[it] = (int)gi;
    }
    __syncthreads();
    for (int i = t; i < NPQ; i += 512) {
        int id = s_inds[i];
        out[OUT_INDS + b*NPQ + i] = (float)id;
        const float* xb = xyz + ((size_t)b*NN + id)*3;
        out[((size_t)b*NPQ + i)*3 + 0] = xb[0];
        out[((size_t)b*NPQ + i)*3 + 1] = xb[1];
        out[((size_t)b*NPQ + i)*3 + 2] = xb[2];
    }
}

// ---------------- Ball query (unchanged, passing) ----------------
__global__ __launch_bounds__(256) void bq2_kernel(
    const float* __restrict__ xyz, const float* __restrict__ out)
{
    __shared__ float sx[NN], sy[NN], sz[NN];
    int tid = threadIdx.x, lane = tid & 31, w = tid >> 5;
    int qbase = blockIdx.x * 32;
    int b = qbase >> 9;
    const float* xb = xyz + (size_t)b*NN*3;
    for (int i = tid; i < NN; i += 256) {
        sx[i] = xb[i*3+0]; sy[i] = xb[i*3+1]; sz[i] = xb[i*3+2];
    }
    __syncthreads();

    const float R2c = (float)(0.3*0.3);
    const float RAD = 0.3f;
    int q0 = qbase + w*4;
    float qx[4], qy[4], qz[4];
    int found[4], first[4];
#pragma unroll
    for (int j = 0; j < 4; j++) {
        qx[j] = out[(size_t)(q0+j)*3+0];
        qy[j] = out[(size_t)(q0+j)*3+1];
        qz[j] = out[(size_t)(q0+j)*3+2];
        found[j] = 0; first[j] = -1;
    }
    for (int s = 0; s < NN/32; s++) {
        int i = s*32 + lane;
        float x = sx[i], y = sy[i], z = sz[i];
        bool pr[4];
#pragma unroll
        for (int j = 0; j < 4; j++) {
            float dx = __fadd_rn(qx[j], -x);
            float dy = __fadd_rn(qy[j], -y);
            float dz = __fadd_rn(qz[j], -z);
            float d  = __fadd_rn(__fadd_rn(__fmul_rn(dx,dx), __fmul_rn(dy,dy)),
                                 __fmul_rn(dz,dz));
            pr[j] = (d < R2c) && (found[j] < NSAMP);
        }
        unsigned anym = __ballot_sync(0xffffffffu, pr[0]|pr[1]|pr[2]|pr[3]);
        if (anym) {
#pragma unroll
            for (int j = 0; j < 4; j++) {
                if (found[j] >= NSAMP) continue;
                unsigned mask = __ballot_sync(0xffffffffu, pr[j]);
                if (!mask) continue;
                if (first[j] < 0) first[j] = s*32 + __ffs(mask) - 1;
                if (pr[j]) {
                    int pos = found[j] + __popc(mask & ((1u << lane) - 1u));
                    if (pos < NSAMP) {
                        int qg = q0 + j;
                        g_idx[qg*NSAMP + pos] = i;
                        g_gxyz[((size_t)qg*NSAMP + pos)*3 + 0] = __fdiv_rn(__fadd_rn(x, -qx[j]), RAD);
                        g_gxyz[((size_t)qg*NSAMP + pos)*3 + 1] = __fdiv_rn(__fadd_rn(y, -qy[j]), RAD);
                        g_gxyz[((size_t)qg*NSAMP + pos)*3 + 2] = __fdiv_rn(__fadd_rn(z, -qz[j]), RAD);
                    }
                }
                found[j] += __popc(mask);
            }
            if (found[0] >= NSAMP && found[1] >= NSAMP &&
                found[2] >= NSAMP && found[3] >= NSAMP) break;
        }
    }
#pragma unroll
    for (int j = 0; j < 4; j++) {
        if (found[j] < NSAMP) {
            int fi = first[j];
            float x = sx[fi], y = sy[fi], z = sz[fi];
            float p0 = __fdiv_rn(__fadd_rn(x, -qx[j]), RAD);
            float p1 = __fdiv_rn(__fadd_rn(y, -qy[j]), RAD);
            float p2 = __fdiv_rn(__fadd_rn(z, -qz[j]), RAD);
            if (lane >= found[j] && lane < NSAMP) {
                int qg = q0 + j;
                g_idx[qg*NSAMP + lane] = fi;
                g_gxyz[((size_t)qg*NSAMP + lane)*3 + 0] = p0;
                g_gxyz[((size_t)qg*NSAMP + lane)*3 + 1] = p1;
                g_gxyz[((size_t)qg*NSAMP + lane)*3 + 2] = p2;
            }
        }
    }
}

// ---------------- GEMM1 fp16 + ldmatrix (unchanged, passing) ----------------
__global__ __launch_bounds__(256) void gemm1_h(const float* __restrict__ feat)
{
    __shared__ uint32_t As[128*SSTRIDE];
    __shared__ uint32_t Bs[128*SSTRIDE];
    int b = blockIdx.z;
    int mBase = blockIdx.x*128;
    const float* A = feat + (size_t)b*CC*NN;
    const uint32_t* W32 = (const uint32_t*)g_W1h;
    uint32_t* C = g_PFh + ((size_t)b*NN + mBase)*64;
    int tid = threadIdx.x;
    int lane = tid & 31, wid = tid >> 5;
    int wm = wid >> 2, wn = wid & 3;
    int lq = lane >> 2, lr = lane & 3;

    uint32_t asb = (uint32_t)__cvta_generic_to_shared(As);
    uint32_t bsb = (uint32_t)__cvta_generic_to_shared(Bs);
    int arow = (lane & 7) + ((lane >> 3) & 1)*8;
    int akp  = (lane >> 4)*4;
    int brow = (lane & 7) + (lane >> 4)*8;
    int bkp  = ((lane >> 3) & 1)*4;

    float c[4][4][4];
#pragma unroll
    for (int i = 0; i < 4; i++)
#pragma unroll
        for (int j = 0; j < 4; j++)
#pragma unroll
            for (int r = 0; r < 4; r++) c[i][j][r] = 0.f;

    for (int kb = 0; kb < CC/32; kb++) {
#pragma unroll
        for (int r = 0; r < 2; r++) {
            int p = tid + 256*r;
            int cp = p >> 5, m4 = p & 31;
            const float* a0 = A + (size_t)(kb*32 + 2*cp)*NN + mBase + m4*4;
            float4 va = *(const float4*)a0;
            float4 vb = *(const float4*)(a0 + NN);
            As[(m4*4+0)*SSTRIDE + cp] = packh2(va.x, vb.x);
            As[(m4*4+1)*SSTRIDE + cp] = packh2(va.y, vb.y);
            As[(m4*4+2)*SSTRIDE + cp] = packh2(va.z, vb.z);
            As[(m4*4+3)*SSTRIDE + cp] = packh2(va.w, vb.w);
        }
#pragma unroll
        for (int r = 0; r < 8; r++) {
            int p = tid + 256*r;
            int n = p >> 4, wd = p & 15;
            Bs[n*SSTRIDE + wd] = W32[n*(CC/2) + kb*16 + wd];
        }
        __syncthreads();
#pragma unroll
        for (int ks = 0; ks < 2; ks++) {
            int k0 = ks*8;
            uint32_t af[4][4], bf[4][2];
#pragma unroll
            for (int mi = 0; mi < 4; mi++) {
                uint32_t a = asb + (uint32_t)(((wm*64 + mi*16 + arow)*SSTRIDE + k0 + akp)*4);
                LDSM4(af[mi][0], af[mi][1], af[mi][2], af[mi][3], a);
            }
#pragma unroll
            for (int np = 0; np < 2; np++) {
                uint32_t a = bsb + (uint32_t)(((wn*32 + np*16 + brow)*SSTRIDE + k0 + bkp)*4);
                LDSM4(bf[np*2][0], bf[np*2][1], bf[np*2+1][0], bf[np*2+1][1], a);
            }
#pragma unroll
            for (int mi = 0; mi < 4; mi++)
#pragma unroll
                for (int nj = 0; nj < 4; nj++)
                    MMAH(c[mi][nj], af[mi], bf[nj]);
        }
        __syncthreads();
    }
#pragma unroll
    for (int mi = 0; mi < 4; mi++) {
#pragma unroll
        for (int nj = 0; nj < 4; nj++) {
            int gr   = wm*64 + mi*16 + lq;
            int colw = wn*16 + nj*4 + lr;
            C[(size_t)gr*64 + colw]     = packh2(c[mi][nj][0], c[mi][nj][1]);
            C[(size_t)(gr+8)*64 + colw] = packh2(c[mi][nj][2], c[mi][nj][3]);
        }
    }
}

// ---------------- assemble: unroll-4 gather loop for MLP ----------------
__global__ __launch_bounds__(256) void assemble_kernel(const float* __restrict__ w1)
{
    __shared__ float s_wx[HIDC], s_wy[HIDC], s_wz[HIDC];
    __shared__ float s_sum[HIDC], s_sq[HIDC];
    int tid = threadIdx.x, lane = tid & 31, w = tid >> 5;
    if (tid < HIDC) {
        s_wx[tid] = w1[tid*(CC+3) + 0];
        s_wy[tid] = w1[tid*(CC+3) + 1];
        s_wz[tid] = w1[tid*(CC+3) + 2];
        s_sum[tid] = 0.f; s_sq[tid] = 0.f;
    }
    __syncthreads();

    float ls[4] = {0,0,0,0}, lqa[4] = {0,0,0,0};
    float wx[4], wy[4], wz[4];
#pragma unroll
    for (int j = 0; j < 4; j++) {
        int o = lane*4 + j;
        wx[j] = s_wx[o]; wy[j] = s_wy[o]; wz[j] = s_wz[o];
    }
#pragma unroll 4
    for (int i = 0; i < 16; i++) {
        int p = blockIdx.x*128 + w*16 + i;
        int b = p >> 13;
        int n = g_idx[p];
        float gx = g_gxyz[(size_t)p*3+0];
        float gy = g_gxyz[(size_t)p*3+1];
        float gz = g_gxyz[(size_t)p*3+2];
        uint2 pv = *(const uint2*)(g_PFh + ((size_t)b*NN + n)*64 + lane*2);
        float2 f0 = __half22float2(*(__half2*)&pv.x);
        float2 f1 = __half22float2(*(__half2*)&pv.y);
        float y[4] = {f0.x, f0.y, f1.x, f1.y};
#pragma unroll
        for (int j = 0; j < 4; j++) {
            float r = y[j] + wx[j]*gx + wy[j]*gy + wz[j]*gz;
            y[j] = r;
            ls[j] += r; lqa[j] += r*r;
        }
        uint2 pk = make_uint2(packh2(y[0], y[1]), packh2(y[2], y[3]));
        *(uint2*)(g_Y1h + (size_t)p*64 + lane*2) = pk;
    }
#pragma unroll
    for (int j = 0; j < 4; j++) {
        atomicAdd(&s_sum[lane*4 + j], ls[j]);
        atomicAdd(&s_sq [lane*4 + j], lqa[j]);
    }
    __syncthreads();
    if (tid < HIDC)      atomicAdd(&g_stats[0*256 + tid], (double)s_sum[tid]);
    else if (tid < 256)  atomicAdd(&g_stats[0*256 + 128 + (tid-128)], (double)s_sq[tid-128]);
}

__global__ void finalize_bn_kernel(int L, const float* __restrict__ g,
                                   const float* __restrict__ be)
{
    int cc = threadIdx.x;
    if (cc >= HIDC) return;
    const double cnt = (double)NPIX;
    double s = g_stats[L*256 + cc];
    double q = g_stats[L*256 + 128 + cc];
    double m = s / cnt;
    double v = q / cnt - m*m;
    if (v < 0.0) v = 0.0;
    float scale = g[cc] / sqrtf((float)v + 1e-5f);
    g_bn[L*384 + cc]       = (float)m;
    g_bn[L*384 + 128 + cc] = scale;
    g_bn[L*384 + 256 + cc] = be[cc];
}

// ---------------- NT GEMM fp16 (unchanged from R13, passing) ----------------
__global__ __launch_bounds__(256) void gemm_nt_h(int layer)
{
    __shared__ uint32_t As[128*NSTR];
    __shared__ uint32_t Bs[128*NSTR];
    __shared__ float s_bnp[384];
    __shared__ float s_sum[HIDC], s_sq[HIDC];
    const uint32_t* Ah = (layer == 1) ? g_Y1h : g_Y2h;
    const uint32_t* W32 = (const uint32_t*)((layer == 1) ? g_W2h : g_W3h);
    const float* bnp = g_bn + (layer-1)*384;

    int tid = threadIdx.x;
    int lane = tid & 31, wid = tid >> 5;
    int wm = wid >> 2, wn = wid & 3;
    int lq = lane >> 2, lr = lane & 3;
    if (tid < HIDC) { s_sum[tid] = 0.f; s_sq[tid] = 0.f; }
    for (int i = tid; i < 384; i += 256) s_bnp[i] = bnp[i];
    __syncthreads();

    size_t mBase = (size_t)blockIdx.x * 128;
    float c[4][4][4];
#pragma unroll
    for (int i = 0; i < 4; i++)
#pragma unroll
        for (int j = 0; j < 4; j++)
#pragma unroll
            for (int r = 0; r < 4; r++) c[i][j][r] = 0.f;

    for (int kb = 0; kb < 2; kb++) {
#pragma unroll
        for (int r = 0; r < 4; r++) {
            int p = tid + 256*r;
            int row = p >> 3, q = p & 7;
            int ch = kb*64 + q*8;
            uint4 v = *(const uint4*)(Ah + (mBase + row)*64 + kb*32 + q*4);
            uint32_t wds[4] = {v.x, v.y, v.z, v.w};
#pragma unroll
            for (int k = 0; k < 4; k++) {
                float2 f = __half22float2(*(__half2*)&wds[k]);
                int cch = ch + 2*k;
                float a0 = fmaxf(0.f, (f.x - s_bnp[cch])  *s_bnp[128+cch]   + s_bnp[256+cch]);
                float a1 = fmaxf(0.f, (f.y - s_bnp[cch+1])*s_bnp[128+cch+1] + s_bnp[256+cch+1]);
                As[row*NSTR + q*4 + k] = packh2(a0, a1);
            }
        }
#pragma unroll
        for (int r = 0; r < 4; r++) {
            int p = tid + 256*r;
            int n = p >> 3, q = p & 7;
            *(uint4*)(Bs + n*NSTR + q*4) = *(const uint4*)(W32 + n*64 + kb*32 + q*4);
        }
        __syncthreads();
#pragma unroll
        for (int ks = 0; ks < 4; ks++) {
            int k0 = ks*8;
            uint32_t af[4][4], bf[4][2];
#pragma unroll
            for (int mi = 0; mi < 4; mi++) {
                int m0 = wm*64 + mi*16;
                af[mi][0] = As[(m0 + lq    )*NSTR + k0 + lr    ];
                af[mi][1] = As[(m0 + 8 + lq)*NSTR + k0 + lr    ];
                af[mi][2] = As[(m0 + lq    )*NSTR + k0 + lr + 4];
                af[mi][3] = As[(m0 + 8 + lq)*NSTR + k0 + lr + 4];
            }
#pragma unroll
            for (int nj = 0; nj < 4; nj++) {
                int n0 = wn*32 + nj*8;
                bf[nj][0] = Bs[(n0+lq)*NSTR + k0 + lr    ];
                bf[nj][1] = Bs[(n0+lq)*NSTR + k0 + lr + 4];
            }
#pragma unroll
            for (int mi = 0; mi < 4; mi++)
#pragma unroll
                for (int nj = 0; nj < 4; nj++)
                    MMAH(c[mi][nj], af[mi], bf[nj]);
        }
        __syncthreads();
    }
    if (layer == 1) {
#pragma unroll
        for (int mi = 0; mi < 4; mi++)
#pragma unroll
            for (int nj = 0; nj < 4; nj++) {
                size_t gr = mBase + wm*64 + mi*16 + lq;
                int colw = wn*16 + nj*4 + lr;
                g_Y2h[gr*64 + colw]     = packh2(c[mi][nj][0], c[mi][nj][1]);
                g_Y2h[(gr+8)*64 + colw] = packh2(c[mi][nj][2], c[mi][nj][3]);
            }
    } else {
#pragma unroll
        for (int mi = 0; mi < 4; mi++) {
            int qg = blockIdx.x*8 + wm*4 + mi;
#pragma unroll
            for (int nj = 0; nj < 4; nj++) {
                float m0v = fmaxf(c[mi][nj][0], c[mi][nj][2]);
                float m1v = fmaxf(c[mi][nj][1], c[mi][nj][3]);
#pragma unroll
                for (int o = 4; o <= 16; o <<= 1) {
                    m0v = fmaxf(m0v, __shfl_xor_sync(0xffffffffu, m0v, o));
                    m1v = fmaxf(m1v, __shfl_xor_sync(0xffffffffu, m1v, o));
                }
                if (lq == 0) {
                    int col = wn*32 + nj*8 + 2*lr;
                    *(float2*)(g_MX + (size_t)qg*HIDC + col) = make_float2(m0v, m1v);
                }
            }
        }
    }
#pragma unroll
    for (int nj = 0; nj < 4; nj++) {
        int ch = wn*32 + nj*8 + 2*lr;
        float s0 = 0.f, q0 = 0.f, s1 = 0.f, q1 = 0.f;
#pragma unroll
        for (int mi = 0; mi < 4; mi++) {
            float x;
            x = c[mi][nj][0]; s0 += x; q0 += x*x;
            x = c[mi][nj][2]; s0 += x; q0 += x*x;
            x = c[mi][nj][1]; s1 += x; q1 += x*x;
            x = c[mi][nj][3]; s1 += x; q1 += x*x;
        }
        atomicAdd(&s_sum[ch],   s0); atomicAdd(&s_sq[ch],   q0);
        atomicAdd(&s_sum[ch+1], s1); atomicAdd(&s_sq[ch+1], q1);
    }
    __syncthreads();
    if (tid < HIDC)      atomicAdd(&g_stats[layer*256 + tid], (double)s_sum[tid]);
    else if (tid < 256)  atomicAdd(&g_stats[layer*256 + 128 + (tid-128)], (double)s_sq[tid-128]);
}

// ---------------- BN3+ReLU on g_MX + transpose (unchanged) ----------------
__global__ __launch_bounds__(256) void maxfinal_kernel(float* __restrict__ out)
{
    __shared__ float T[HIDC][33];
    int b = blockIdx.x >> 4, pb = blockIdx.x & 15;
    int tid = threadIdx.x;
    const float* bnp = g_bn + 2*384;
#pragma unroll
    for (int r = 0; r < 16; r++) {
        int idx = tid + 256*r;
        int ql = idx >> 7, c = idx & 127;
        float v = g_MX[((size_t)(b*NPQ + pb*32 + ql))*HIDC + c];
        T[c][ql] = fmaxf(0.f, (v - bnp[c])*bnp[128+c] + bnp[256+c]);
    }
    __syncthreads();
#pragma unroll
    for (int r = 0; r < 16; r++) {
        int flat = tid + 256*r;
        int o = flat >> 5, pl = flat & 31;
        out[OUT_FEAT + (size_t)b*(HIDC*NPQ) + (size_t)o*NPQ + pb*32 + pl] = T[o][pl];
    }
}

// ---------------------------------------------------------------------------
extern "C" void kernel_launch(void* const* d_in, const int* in_sizes, int n_in,
                              void* d_out, int out_size)
{
    const float* xyz  = (const float*)d_in[0];
    const float* feat = (const float*)d_in[1];
    const float* seed = (const float*)d_in[2];
    const float* w1   = (const float*)d_in[3];
    const float* g1   = (const float*)d_in[4];
    const float* be1  = (const float*)d_in[5];
    const float* w2   = (const float*)d_in[6];
    const float* g2   = (const float*)d_in[7];
    const float* be2  = (const float*)d_in[8];
    const float* w3   = (const float*)d_in[9];
    const float* g3   = (const float*)d_in[10];
    const float* be3  = (const float*)d_in[11];
    float* out = (float*)d_out;

    cudaFuncSetAttribute(fps_kernel, cudaFuncAttributeMaxDynamicSharedMemorySize, FPS_SMEM);

    // fps stays at launch index 3 so the profiler re-measures it.
    zero_stats_kernel<<<3, 256>>>();
    prep_w_kernel<<<HIDC, CC>>>(w1, w2, w3);
    gemm1_h<<<dim3(NN/128, 1, BB), 256>>>(feat);
    fps_kernel<<<BB, 512, FPS_SMEM>>>(seed, xyz, out);
    bq2_kernel<<<(BB*NPQ)/32, 256>>>(xyz, out);
    assemble_kernel<<<NPIX/128, 256>>>(w1);
    finalize_bn_kernel<<<1, 128>>>(0, g1, be1);
    gemm_nt_h<<<NPIX/128, 256>>>(1);
    finalize_bn_kernel<<<1, 128>>>(1, g2, be2);
    gemm_nt_h<<<NPIX/128, 256>>>(2);
    finalize_bn_kernel<<<1, 128>>>(2, g3, be3);
    maxfinal_kernel<<<BB*16, 256>>>(out);
}

// round 15
// speedup vs baseline: 1.4373x; 1.0314x over previous
#include <cuda_runtime.h>
#include <cuda_fp16.h>
#include <math.h>
#include <stdint.h>

#define BB    32
#define NN    4096
#define NPQ   512
#define NSAMP 16
#define CC    256
#define HIDC  128
#define NPIX  (BB*NPQ*NSAMP)
#define NPTS  (BB*NN)

#define OUT_FEAT (BB*NPQ*3)
#define OUT_INDS (OUT_FEAT + BB*HIDC*NPQ)

__device__ uint32_t g_PFh[(size_t)NPTS*64];
__device__ uint32_t g_Y1h[(size_t)NPIX*64];
__device__ uint32_t g_Y2h[(size_t)NPIX*64];
__device__ float    g_MX[(size_t)BB*NPQ*HIDC];
__device__ int      g_idx[NPIX];
__device__ float    g_gxyz[(size_t)NPIX*3];
__device__ double   g_stats[3*2*HIDC];
__device__ float    g_bn[3*3*HIDC];
__device__ __half   g_W1h[HIDC*CC];
__device__ __half   g_W2h[HIDC*HIDC];
__device__ __half   g_W3h[HIDC*HIDC];

#define MMAH(c, a, b) asm volatile( \
  "mma.sync.aligned.m16n8k16.row.col.f32.f16.f16.f32 " \
  "{%0,%1,%2,%3}, {%4,%5,%6,%7}, {%8,%9}, {%0,%1,%2,%3};" \
  : "+f"((c)[0]), "+f"((c)[1]), "+f"((c)[2]), "+f"((c)[3]) \
  : "r"((a)[0]), "r"((a)[1]), "r"((a)[2]), "r"((a)[3]), "r"((b)[0]), "r"((b)[1]))

#define LDSM4(r0, r1, r2, r3, a) asm volatile( \
  "ldmatrix.sync.aligned.m8n8.x4.shared.b16 {%0,%1,%2,%3}, [%4];" \
  : "=r"(r0), "=r"(r1), "=r"(r2), "=r"(r3) : "r"(a))

#define SSTRIDE 20
#define NSTR 36
#define FPS_SMEM (12928*4)     /* 3*4096 coords + 512 inds + 2*32 cv + 2*32 ci */
#define FUSE_SMEM 49152        /* bq2: 3*4096 f32; gemm1 uses first 20480 B */

__device__ __forceinline__ uint32_t packh2(float x, float y) {
    __half2 h = __floats2half2_rn(x, y);
    return *(uint32_t*)&h;
}

__global__ void zero_stats_kernel() {
    int i = blockIdx.x*256 + threadIdx.x;
    if (i < 3*2*HIDC) g_stats[i] = 0.0;
}
__global__ void prep_w_kernel(const float* __restrict__ w1,
                              const float* __restrict__ w2,
                              const float* __restrict__ w3) {
    int o = blockIdx.x, k = threadIdx.x;
    g_W1h[o*CC + k] = __float2half_rn(w1[o*(CC+3) + 3 + k]);
    if (k < HIDC) {
        g_W2h[o*HIDC + k] = __float2half_rn(w2[o*HIDC + k]);
        g_W3h[o*HIDC + k] = __float2half_rn(w3[o*HIDC + k]);
    }
}

// ---------------- FPS v5: 1024 threads, lean loop, redux reductions --------
__global__ __launch_bounds__(1024) void fps_kernel(
    const float* __restrict__ seed, const float* __restrict__ xyz,
    float* __restrict__ out)
{
    extern __shared__ float fsm[];
    float* s_px = fsm;
    float* s_py = fsm + 4096;
    float* s_pz = fsm + 8192;
    int*   s_inds = (int*)(fsm + 12288);
    float* s_cv = fsm + 12800;
    int*   s_ci = (int*)(fsm + 12864);

    int b = blockIdx.x, t = threadIdx.x;
    int lane = t & 31, wid = t >> 5;   // 32 warps

    const float* sb = seed + (size_t)b*NN*3;
    float px[4], py[4], pz[4], dist[4];
#pragma unroll
    for (int j = 0; j < 4; j++) {
        int i = t + j*1024;
        float x = sb[i*3+0], y = sb[i*3+1], z = sb[i*3+2];
        px[j] = x; py[j] = y; pz[j] = z;
        s_px[i] = x; s_py[i] = y; s_pz[i] = z;
        dist[j] = 1e10f;
    }
    if (t == 0) s_inds[0] = 0;
    __syncthreads();
    float lx = s_px[0], ly = s_py[0], lz = s_pz[0];

    for (int it = 1; it < NPQ; ++it) {
        float bv = -1.0f; int bi = 0;
#pragma unroll
        for (int j = 0; j < 4; j++) {
            float dx = __fadd_rn(px[j], -lx);
            float dy = __fadd_rn(py[j], -ly);
            float dz = __fadd_rn(pz[j], -lz);
            float d  = __fadd_rn(__fadd_rn(__fmul_rn(dx,dx), __fmul_rn(dy,dy)),
                                 __fmul_rn(dz,dz));
            dist[j] = fminf(dist[j], d);
            if (dist[j] > bv) { bv = dist[j]; bi = t + j*1024; }
        }
        unsigned fb = __float_as_uint(bv);
        unsigned m  = __reduce_max_sync(0xffffffffu, fb);
        unsigned cand = (fb == m) ? (unsigned)bi : 0xffffffffu;
        unsigned cmin = __reduce_min_sync(0xffffffffu, cand);
        int buf = it & 1;
        if (fb == m && (unsigned)bi == cmin) {
            s_cv[buf*32 + wid] = bv; s_ci[buf*32 + wid] = bi;
        }
        __syncthreads();
        float v  = s_cv[buf*32 + lane];
        int   ci = s_ci[buf*32 + lane];
        unsigned fb2 = __float_as_uint(v);
        unsigned m2  = __reduce_max_sync(0xffffffffu, fb2);
        unsigned cand2 = (fb2 == m2) ? (unsigned)ci : 0xffffffffu;
        unsigned gi = __reduce_min_sync(0xffffffffu, cand2);
        lx = s_px[gi]; ly = s_py[gi]; lz = s_pz[gi];
        if (t == 0) s_inds[it] = (int)gi;
    }
    __syncthreads();
    for (int i = t; i < NPQ; i += 1024) {
        int id = s_inds[i];
        out[OUT_INDS + b*NPQ + i] = (float)id;
        const float* xb = xyz + ((size_t)b*NN + id)*3;
        out[((size_t)b*NPQ + i)*3 + 0] = xb[0];
        out[((size_t)b*NPQ + i)*3 + 1] = xb[1];
        out[((size_t)b*NPQ + i)*3 + 2] = xb[2];
    }
}

// ---------------- fused gemm1 + ball-query (independent work) --------------
// blocks [0,1024): gemm1 path (mt = bx&31, b = bx>>5), 20KB of dyn smem.
// blocks [1024,1536): bq2 path (qbase = (bx-1024)*32), 48KB of dyn smem.
__global__ __launch_bounds__(256) void fused_g1bq_kernel(
    const float* __restrict__ feat, const float* __restrict__ xyz,
    const float* __restrict__ outv)
{
    extern __shared__ char dsm[];
    int tid = threadIdx.x, lane = tid & 31;

    if (blockIdx.x < 1024) {
        // ======== gemm1 (identical math/layout to passing R14) ========
        uint32_t* As = (uint32_t*)dsm;
        uint32_t* Bs = As + 128*SSTRIDE;
        int b = blockIdx.x >> 5;
        int mBase = (blockIdx.x & 31)*128;
        const float* A = feat + (size_t)b*CC*NN;
        const uint32_t* W32 = (const uint32_t*)g_W1h;
        uint32_t* C = g_PFh + ((size_t)b*NN + mBase)*64;
        int wid = tid >> 5;
        int wm = wid >> 2, wn = wid & 3;
        int lq = lane >> 2, lr = lane & 3;

        uint32_t asb = (uint32_t)__cvta_generic_to_shared(As);
        uint32_t bsb = (uint32_t)__cvta_generic_to_shared(Bs);
        int arow = (lane & 7) + ((lane >> 3) & 1)*8;
        int akp  = (lane >> 4)*4;
        int brow = (lane & 7) + (lane >> 4)*8;
        int bkp  = ((lane >> 3) & 1)*4;

        float c[4][4][4];
#pragma unroll
        for (int i = 0; i < 4; i++)
#pragma unroll
            for (int j = 0; j < 4; j++)
#pragma unroll
                for (int r = 0; r < 4; r++) c[i][j][r] = 0.f;

        for (int kb = 0; kb < CC/32; kb++) {
#pragma unroll
            for (int r = 0; r < 2; r++) {
                int p = tid + 256*r;
                int cp = p >> 5, m4 = p & 31;
                const float* a0 = A + (size_t)(kb*32 + 2*cp)*NN + mBase + m4*4;
                float4 va = *(const float4*)a0;
                float4 vb = *(const float4*)(a0 + NN);
                As[(m4*4+0)*SSTRIDE + cp] = packh2(va.x, vb.x);
                As[(m4*4+1)*SSTRIDE + cp] = packh2(va.y, vb.y);
                As[(m4*4+2)*SSTRIDE + cp] = packh2(va.z, vb.z);
                As[(m4*4+3)*SSTRIDE + cp] = packh2(va.w, vb.w);
            }
#pragma unroll
            for (int r = 0; r < 8; r++) {
                int p = tid + 256*r;
                int n = p >> 4, wd = p & 15;
                Bs[n*SSTRIDE + wd] = W32[n*(CC/2) + kb*16 + wd];
            }
            __syncthreads();
#pragma unroll
            for (int ks = 0; ks < 2; ks++) {
                int k0 = ks*8;
                uint32_t af[4][4], bf[4][2];
#pragma unroll
                for (int mi = 0; mi < 4; mi++) {
                    uint32_t a = asb + (uint32_t)(((wm*64 + mi*16 + arow)*SSTRIDE + k0 + akp)*4);
                    LDSM4(af[mi][0], af[mi][1], af[mi][2], af[mi][3], a);
                }
#pragma unroll
                for (int np = 0; np < 2; np++) {
                    uint32_t a = bsb + (uint32_t)(((wn*32 + np*16 + brow)*SSTRIDE + k0 + bkp)*4);
                    LDSM4(bf[np*2][0], bf[np*2][1], bf[np*2+1][0], bf[np*2+1][1], a);
                }
#pragma unroll
                for (int mi = 0; mi < 4; mi++)
#pragma unroll
                    for (int nj = 0; nj < 4; nj++)
                        MMAH(c[mi][nj], af[mi], bf[nj]);
            }
            __syncthreads();
        }
#pragma unroll
        for (int mi = 0; mi < 4; mi++) {
#pragma unroll
            for (int nj = 0; nj < 4; nj++) {
                int gr   = wm*64 + mi*16 + lq;
                int colw = wn*16 + nj*4 + lr;
                C[(size_t)gr*64 + colw]     = packh2(c[mi][nj][0], c[mi][nj][1]);
                C[(size_t)(gr+8)*64 + colw] = packh2(c[mi][nj][2], c[mi][nj][3]);
            }
        }
    } else {
        // ======== ball query (identical semantics to passing R14) ========
        float* sx = (float*)dsm;
        float* sy = sx + NN;
        float* sz = sy + NN;
        int w = tid >> 5;
        int qbase = (blockIdx.x - 1024) * 32;
        int b = qbase >> 9;
        const float* xb = xyz + (size_t)b*NN*3;
        for (int i = tid; i < NN; i += 256) {
            sx[i] = xb[i*3+0]; sy[i] = xb[i*3+1]; sz[i] = xb[i*3+2];
        }
        __syncthreads();

        const float R2c = (float)(0.3*0.3);
        const float RAD = 0.3f;
        int q0 = qbase + w*4;
        float qx[4], qy[4], qz[4];
        int found[4], first[4];
#pragma unroll
        for (int j = 0; j < 4; j++) {
            qx[j] = outv[(size_t)(q0+j)*3+0];
            qy[j] = outv[(size_t)(q0+j)*3+1];
            qz[j] = outv[(size_t)(q0+j)*3+2];
            found[j] = 0; first[j] = -1;
        }
        for (int s = 0; s < NN/32; s++) {
            int i = s*32 + lane;
            float x = sx[i], y = sy[i], z = sz[i];
            bool pr[4];
#pragma unroll
            for (int j = 0; j < 4; j++) {
                float dx = __fadd_rn(qx[j], -x);
                float dy = __fadd_rn(qy[j], -y);
                float dz = __fadd_rn(qz[j], -z);
                float d  = __fadd_rn(__fadd_rn(__fmul_rn(dx,dx), __fmul_rn(dy,dy)),
                                     __fmul_rn(dz,dz));
                pr[j] = (d < R2c) && (found[j] < NSAMP);
            }
            unsigned anym = __ballot_sync(0xffffffffu, pr[0]|pr[1]|pr[2]|pr[3]);
            if (anym) {
#pragma unroll
                for (int j = 0; j < 4; j++) {
                    if (found[j] >= NSAMP) continue;
                    unsigned mask = __ballot_sync(0xffffffffu, pr[j]);
                    if (!mask) continue;
                    if (first[j] < 0) first[j] = s*32 + __ffs(mask) - 1;
                    if (pr[j]) {
                        int pos = found[j] + __popc(mask & ((1u << lane) - 1u));
                        if (pos < NSAMP) {
                            int qg = q0 + j;
                            g_idx[qg*NSAMP + pos] = i;
                            g_gxyz[((size_t)qg*NSAMP + pos)*3 + 0] = __fdiv_rn(__fadd_rn(x, -qx[j]), RAD);
                            g_gxyz[((size_t)qg*NSAMP + pos)*3 + 1] = __fdiv_rn(__fadd_rn(y, -qy[j]), RAD);
                            g_gxyz[((size_t)qg*NSAMP + pos)*3 + 2] = __fdiv_rn(__fadd_rn(z, -qz[j]), RAD);
                        }
                    }
                    found[j] += __popc(mask);
                }
                if (found[0] >= NSAMP && found[1] >= NSAMP &&
                    found[2] >= NSAMP && found[3] >= NSAMP) break;
            }
        }
#pragma unroll
        for (int j = 0; j < 4; j++) {
            if (found[j] < NSAMP) {
                int fi = first[j];
                float x = sx[fi], y = sy[fi], z = sz[fi];
                float p0 = __fdiv_rn(__fadd_rn(x, -qx[j]), RAD);
                float p1 = __fdiv_rn(__fadd_rn(y, -qy[j]), RAD);
                float p2 = __fdiv_rn(__fadd_rn(z, -qz[j]), RAD);
                if (lane >= found[j] && lane < NSAMP) {
                    int qg = q0 + j;
                    g_idx[qg*NSAMP + lane] = fi;
                    g_gxyz[((size_t)qg*NSAMP + lane)*3 + 0] = p0;
                    g_gxyz[((size_t)qg*NSAMP + lane)*3 + 1] = p1;
                    g_gxyz[((size_t)qg*NSAMP + lane)*3 + 2] = p2;
                }
            }
        }
    }
}

// ---------------- assemble (unchanged from R14, passing) ----------------
__global__ __launch_bounds__(256) void assemble_kernel(const float* __restrict__ w1)
{
    __shared__ float s_wx[HIDC], s_wy[HIDC], s_wz[HIDC];
    __shared__ float s_sum[HIDC], s_sq[HIDC];
    int tid = threadIdx.x, lane = tid & 31, w = tid >> 5;
    if (tid < HIDC) {
        s_wx[tid] = w1[tid*(CC+3) + 0];
        s_wy[tid] = w1[tid*(CC+3) + 1];
        s_wz[tid] = w1[tid*(CC+3) + 2];
        s_sum[tid] = 0.f; s_sq[tid] = 0.f;
    }
    __syncthreads();

    float ls[4] = {0,0,0,0}, lqa[4] = {0,0,0,0};
    float wx[4], wy[4], wz[4];
#pragma unroll
    for (int j = 0; j < 4; j++) {
        int o = lane*4 + j;
        wx[j] = s_wx[o]; wy[j] = s_wy[o]; wz[j] = s_wz[o];
    }
#pragma unroll 4
    for (int i = 0; i < 16; i++) {
        int p = blockIdx.x*128 + w*16 + i;
        int b = p >> 13;
        int n = g_idx[p];
        float gx = g_gxyz[(size_t)p*3+0];
        float gy = g_gxyz[(size_t)p*3+1];
        float gz = g_gxyz[(size_t)p*3+2];
        uint2 pv = *(const uint2*)(g_PFh + ((size_t)b*NN + n)*64 + lane*2);
        float2 f0 = __half22float2(*(__half2*)&pv.x);
        float2 f1 = __half22float2(*(__half2*)&pv.y);
        float y[4] = {f0.x, f0.y, f1.x, f1.y};
#pragma unroll
        for (int j = 0; j < 4; j++) {
            float r = y[j] + wx[j]*gx + wy[j]*gy + wz[j]*gz;
            y[j] = r;
            ls[j] += r; lqa[j] += r*r;
        }
        uint2 pk = make_uint2(packh2(y[0], y[1]), packh2(y[2], y[3]));
        *(uint2*)(g_Y1h + (size_t)p*64 + lane*2) = pk;
    }
#pragma unroll
    for (int j = 0; j < 4; j++) {
        atomicAdd(&s_sum[lane*4 + j], ls[j]);
        atomicAdd(&s_sq [lane*4 + j], lqa[j]);
    }
    __syncthreads();
    if (tid < HIDC)      atomicAdd(&g_stats[0*256 + tid], (double)s_sum[tid]);
    else if (tid < 256)  atomicAdd(&g_stats[0*256 + 128 + (tid-128)], (double)s_sq[tid-128]);
}

__global__ void finalize_bn_kernel(int L, const float* __restrict__ g,
                                   const float* __restrict__ be)
{
    int cc = threadIdx.x;
    if (cc >= HIDC) return;
    const double cnt = (double)NPIX;
    double s = g_stats[L*256 + cc];
    double q = g_stats[L*256 + 128 + cc];
    double m = s / cnt;
    double v = q / cnt - m*m;
    if (v < 0.0) v = 0.0;
    float scale = g[cc] / sqrtf((float)v + 1e-5f);
    g_bn[L*384 + cc]       = (float)m;
    g_bn[L*384 + 128 + cc] = scale;
    g_bn[L*384 + 256 + cc] = be[cc];
}

// ---------------- NT GEMM fp16 (unchanged from R14, passing) ----------------
__global__ __launch_bounds__(256) void gemm_nt_h(int layer)
{
    __shared__ uint32_t As[128*NSTR];
    __shared__ uint32_t Bs[128*NSTR];
    __shared__ float s_bnp[384];
    __shared__ float s_sum[HIDC], s_sq[HIDC];
    const uint32_t* Ah = (layer == 1) ? g_Y1h : g_Y2h;
    const uint32_t* W32 = (const uint32_t*)((layer == 1) ? g_W2h : g_W3h);
    const float* bnp = g_bn + (layer-1)*384;

    int tid = threadIdx.x;
    int lane = tid & 31, wid = tid >> 5;
    int wm = wid >> 2, wn = wid & 3;
    int lq = lane >> 2, lr = lane & 3;
    if (tid < HIDC) { s_sum[tid] = 0.f; s_sq[tid] = 0.f; }
    for (int i = tid; i < 384; i += 256) s_bnp[i] = bnp[i];
    __syncthreads();

    size_t mBase = (size_t)blockIdx.x * 128;
    float c[4][4][4];
#pragma unroll
    for (int i = 0; i < 4; i++)
#pragma unroll
        for (int j = 0; j < 4; j++)
#pragma unroll
            for (int r = 0; r < 4; r++) c[i][j][r] = 0.f;

    for (int kb = 0; kb < 2; kb++) {
#pragma unroll
        for (int r = 0; r < 4; r++) {
            int p = tid + 256*r;
            int row = p >> 3, q = p & 7;
            int ch = kb*64 + q*8;
            uint4 v = *(const uint4*)(Ah + (mBase + row)*64 + kb*32 + q*4);
            uint32_t wds[4] = {v.x, v.y, v.z, v.w};
#pragma unroll
            for (int k = 0; k < 4; k++) {
                float2 f = __half22float2(*(__half2*)&wds[k]);
                int cch = ch + 2*k;
                float a0 = fmaxf(0.f, (f.x - s_bnp[cch])  *s_bnp[128+cch]   + s_bnp[256+cch]);
                float a1 = fmaxf(0.f, (f.y - s_bnp[cch+1])*s_bnp[128+cch+1] + s_bnp[256+cch+1]);
                As[row*NSTR + q*4 + k] = packh2(a0, a1);
            }
        }
#pragma unroll
        for (int r = 0; r < 4; r++) {
            int p = tid + 256*r;
            int n = p >> 3, q = p & 7;
            *(uint4*)(Bs + n*NSTR + q*4) = *(const uint4*)(W32 + n*64 + kb*32 + q*4);
        }
        __syncthreads();
#pragma unroll
        for (int ks = 0; ks < 4; ks++) {
            int k0 = ks*8;
            uint32_t af[4][4], bf[4][2];
#pragma unroll
            for (int mi = 0; mi < 4; mi++) {
                int m0 = wm*64 + mi*16;
                af[mi][0] = As[(m0 + lq    )*NSTR + k0 + lr    ];
                af[mi][1] = As[(m0 + 8 + lq)*NSTR + k0 + lr    ];
                af[mi][2] = As[(m0 + lq    )*NSTR + k0 + lr + 4];
                af[mi][3] = As[(m0 + 8 + lq)*NSTR + k0 + lr + 4];
            }
#pragma unroll
            for (int nj = 0; nj < 4; nj++) {
                int n0 = wn*32 + nj*8;
                bf[nj][0] = Bs[(n0+lq)*NSTR + k0 + lr    ];
                bf[nj][1] = Bs[(n0+lq)*NSTR + k0 + lr + 4];
            }
#pragma unroll
            for (int mi = 0; mi < 4; mi++)
#pragma unroll
                for (int nj = 0; nj < 4; nj++)
                    MMAH(c[mi][nj], af[mi], bf[nj]);
        }
        __syncthreads();
    }
    if (layer == 1) {
#pragma unroll
        for (int mi = 0; mi < 4; mi++)
#pragma unroll
            for (int nj = 0; nj < 4; nj++) {
                size_t gr = mBase + wm*64 + mi*16 + lq;
                int colw = wn*16 + nj*4 + lr;
                g_Y2h[gr*64 + colw]     = packh2(c[mi][nj][0], c[mi][nj][1]);
                g_Y2h[(gr+8)*64 + colw] = packh2(c[mi][nj][2], c[mi][nj][3]);
            }
    } else {
#pragma unroll
        for (int mi = 0; mi < 4; mi++) {
            int qg = blockIdx.x*8 + wm*4 + mi;
#pragma unroll
            for (int nj = 0; nj < 4; nj++) {
                float m0v = fmaxf(c[mi][nj][0], c[mi][nj][2]);
                float m1v = fmaxf(c[mi][nj][1], c[mi][nj][3]);
#pragma unroll
                for (int o = 4; o <= 16; o <<= 1) {
                    m0v = fmaxf(m0v, __shfl_xor_sync(0xffffffffu, m0v, o));
                    m1v = fmaxf(m1v, __shfl_xor_sync(0xffffffffu, m1v, o));
                }
                if (lq == 0) {
                    int col = wn*32 + nj*8 + 2*lr;
                    *(float2*)(g_MX + (size_t)qg*HIDC + col) = make_float2(m0v, m1v);
                }
            }
        }
    }
#pragma unroll
    for (int nj = 0; nj < 4; nj++) {
        int ch = wn*32 + nj*8 + 2*lr;
        float s0 = 0.f, q0 = 0.f, s1 = 0.f, q1 = 0.f;
#pragma unroll
        for (int mi = 0; mi < 4; mi++) {
            float x;
            x = c[mi][nj][0]; s0 += x; q0 += x*x;
            x = c[mi][nj][2]; s0 += x; q0 += x*x;
            x = c[mi][nj][1]; s1 += x; q1 += x*x;
            x = c[mi][nj][3]; s1 += x; q1 += x*x;
        }
        atomicAdd(&s_sum[ch],   s0); atomicAdd(&s_sq[ch],   q0);
        atomicAdd(&s_sum[ch+1], s1); atomicAdd(&s_sq[ch+1], q1);
    }
    __syncthreads();
    if (tid < HIDC)      atomicAdd(&g_stats[layer*256 + tid], (double)s_sum[tid]);
    else if (tid < 256)  atomicAdd(&g_stats[layer*256 + 128 + (tid-128)], (double)s_sq[tid-128]);
}

// ---------------- BN3+ReLU on g_MX + transpose (unchanged) ----------------
__global__ __launch_bounds__(256) void maxfinal_kernel(float* __restrict__ out)
{
    __shared__ float T[HIDC][33];
    int b = blockIdx.x >> 4, pb = blockIdx.x & 15;
    int tid = threadIdx.x;
    const float* bnp = g_bn + 2*384;
#pragma unroll
    for (int r = 0; r < 16; r++) {
        int idx = tid + 256*r;
        int ql = idx >> 7, c = idx & 127;
        float v = g_MX[((size_t)(b*NPQ + pb*32 + ql))*HIDC + c];
        T[c][ql] = fmaxf(0.f, (v - bnp[c])*bnp[128+c] + bnp[256+c]);
    }
    __syncthreads();
#pragma unroll
    for (int r = 0; r < 16; r++) {
        int flat = tid + 256*r;
        int o = flat >> 5, pl = flat & 31;
        out[OUT_FEAT + (size_t)b*(HIDC*NPQ) + (size_t)o*NPQ + pb*32 + pl] = T[o][pl];
    }
}

// ---------------------------------------------------------------------------
extern "C" void kernel_launch(void* const* d_in, const int* in_sizes, int n_in,
                              void* d_out, int out_size)
{
    const float* xyz  = (const float*)d_in[0];
    const float* feat = (const float*)d_in[1];
    const float* seed = (const float*)d_in[2];
    const float* w1   = (const float*)d_in[3];
    const float* g1   = (const float*)d_in[4];
    const float* be1  = (const float*)d_in[5];
    const float* w2   = (const float*)d_in[6];
    const float* g2   = (const float*)d_in[7];
    const float* be2  = (const float*)d_in[8];
    const float* w3   = (const float*)d_in[9];
    const float* g3   = (const float*)d_in[10];
    const float* be3  = (const float*)d_in[11];
    float* out = (float*)d_out;

    cudaFuncSetAttribute(fps_kernel, cudaFuncAttributeMaxDynamicSharedMemorySize, FPS_SMEM);
    cudaFuncSetAttribute(fused_g1bq_kernel, cudaFuncAttributeMaxDynamicSharedMemorySize, FUSE_SMEM);

    zero_stats_kernel<<<3, 256>>>();
    prep_w_kernel<<<HIDC, CC>>>(w1, w2, w3);
    fps_kernel<<<BB, 1024, FPS_SMEM>>>(seed, xyz, out);
    fused_g1bq_kernel<<<1536, 256, FUSE_SMEM>>>(feat, xyz, out);
    assemble_kernel<<<NPIX/128, 256>>>(w1);
    finalize_bn_kernel<<<1, 128>>>(0, g1, be1);
    gemm_nt_h<<<NPIX/128, 256>>>(1);
    finalize_bn_kernel<<<1, 128>>>(1, g2, be2);
    gemm_nt_h<<<NPIX/128, 256>>>(2);
    finalize_bn_kernel<<<1, 128>>>(2, g3, be3);
    maxfinal_kernel<<<BB*16, 256>>>(out);
}

// round 16
// speedup vs baseline: 1.7251x; 1.2002x over previous
#include <cuda_runtime.h>
#include <cuda_fp16.h>
#include <math.h>
#include <stdint.h>

#define BB    32
#define NN    4096
#define NPQ   512
#define NSAMP 16
#define CC    256
#define HIDC  128
#define NPIX  (BB*NPQ*NSAMP)
#define NPTS  (BB*NN)

#define OUT_FEAT (BB*NPQ*3)
#define OUT_INDS (OUT_FEAT + BB*HIDC*NPQ)

__device__ uint32_t g_PFh[(size_t)NPTS*64];
__device__ uint32_t g_Y1h[(size_t)NPIX*64];
__device__ uint32_t g_Y2h[(size_t)NPIX*64];
__device__ float    g_MX[(size_t)BB*NPQ*HIDC];
__device__ int      g_idx[NPIX];
__device__ float    g_gxyz[(size_t)NPIX*3];
__device__ double   g_stats[3*2*HIDC];
__device__ __half   g_W1h[HIDC*CC];
__device__ __half   g_W2h[HIDC*HIDC];
__device__ __half   g_W3h[HIDC*HIDC];

#define MMAH(c, a, b) asm volatile( \
  "mma.sync.aligned.m16n8k16.row.col.f32.f16.f16.f32 " \
  "{%0,%1,%2,%3}, {%4,%5,%6,%7}, {%8,%9}, {%0,%1,%2,%3};" \
  : "+f"((c)[0]), "+f"((c)[1]), "+f"((c)[2]), "+f"((c)[3]) \
  : "r"((a)[0]), "r"((a)[1]), "r"((a)[2]), "r"((a)[3]), "r"((b)[0]), "r"((b)[1]))

#define LDSM4(r0, r1, r2, r3, a) asm volatile( \
  "ldmatrix.sync.aligned.m8n8.x4.shared.b16 {%0,%1,%2,%3}, [%4];" \
  : "=r"(r0), "=r"(r1), "=r"(r2), "=r"(r3) : "r"(a))

#define SSTRIDE 20
#define NSTR 36
#define FPS_SMEM (12928*4)
#define FUSE_SMEM 49152
#define NT_SMEM  (3*4608*4)    /* As + Bs0 + Bs1, 55296 B dynamic */

__device__ __forceinline__ uint32_t packh2(float x, float y) {
    __half2 h = __floats2half2_rn(x, y);
    return *(uint32_t*)&h;
}

__global__ void zero_stats_kernel() {
    int i = blockIdx.x*256 + threadIdx.x;
    if (i < 3*2*HIDC) g_stats[i] = 0.0;
}
__global__ void prep_w_kernel(const float* __restrict__ w1,
                              const float* __restrict__ w2,
                              const float* __restrict__ w3) {
    int o = blockIdx.x, k = threadIdx.x;
    g_W1h[o*CC + k] = __float2half_rn(w1[o*(CC+3) + 3 + k]);
    if (k < HIDC) {
        g_W2h[o*HIDC + k] = __float2half_rn(w2[o*HIDC + k]);
        g_W3h[o*HIDC + k] = __float2half_rn(w3[o*HIDC + k]);
    }
}

// ---------------- FPS (unchanged from R15, passing) ----------------
__global__ __launch_bounds__(1024) void fps_kernel(
    const float* __restrict__ seed, const float* __restrict__ xyz,
    float* __restrict__ out)
{
    extern __shared__ float fsm[];
    float* s_px = fsm;
    float* s_py = fsm + 4096;
    float* s_pz = fsm + 8192;
    int*   s_inds = (int*)(fsm + 12288);
    float* s_cv = fsm + 12800;
    int*   s_ci = (int*)(fsm + 12864);

    int b = blockIdx.x, t = threadIdx.x;
    int lane = t & 31, wid = t >> 5;

    const float* sb = seed + (size_t)b*NN*3;
    float px[4], py[4], pz[4], dist[4];
#pragma unroll
    for (int j = 0; j < 4; j++) {
        int i = t + j*1024;
        float x = sb[i*3+0], y = sb[i*3+1], z = sb[i*3+2];
        px[j] = x; py[j] = y; pz[j] = z;
        s_px[i] = x; s_py[i] = y; s_pz[i] = z;
        dist[j] = 1e10f;
    }
    if (t == 0) s_inds[0] = 0;
    __syncthreads();
    float lx = s_px[0], ly = s_py[0], lz = s_pz[0];

    for (int it = 1; it < NPQ; ++it) {
        float bv = -1.0f; int bi = 0;
#pragma unroll
        for (int j = 0; j < 4; j++) {
            float dx = __fadd_rn(px[j], -lx);
            float dy = __fadd_rn(py[j], -ly);
            float dz = __fadd_rn(pz[j], -lz);
            float d  = __fadd_rn(__fadd_rn(__fmul_rn(dx,dx), __fmul_rn(dy,dy)),
                                 __fmul_rn(dz,dz));
            dist[j] = fminf(dist[j], d);
            if (dist[j] > bv) { bv = dist[j]; bi = t + j*1024; }
        }
        unsigned fb = __float_as_uint(bv);
        unsigned m  = __reduce_max_sync(0xffffffffu, fb);
        unsigned cand = (fb == m) ? (unsigned)bi : 0xffffffffu;
        unsigned cmin = __reduce_min_sync(0xffffffffu, cand);
        int buf = it & 1;
        if (fb == m && (unsigned)bi == cmin) {
            s_cv[buf*32 + wid] = bv; s_ci[buf*32 + wid] = bi;
        }
        __syncthreads();
        float v  = s_cv[buf*32 + lane];
        int   ci = s_ci[buf*32 + lane];
        unsigned fb2 = __float_as_uint(v);
        unsigned m2  = __reduce_max_sync(0xffffffffu, fb2);
        unsigned cand2 = (fb2 == m2) ? (unsigned)ci : 0xffffffffu;
        unsigned gi = __reduce_min_sync(0xffffffffu, cand2);
        lx = s_px[gi]; ly = s_py[gi]; lz = s_pz[gi];
        if (t == 0) s_inds[it] = (int)gi;
    }
    __syncthreads();
    for (int i = t; i < NPQ; i += 1024) {
        int id = s_inds[i];
        out[OUT_INDS + b*NPQ + i] = (float)id;
        const float* xb = xyz + ((size_t)b*NN + id)*3;
        out[((size_t)b*NPQ + i)*3 + 0] = xb[0];
        out[((size_t)b*NPQ + i)*3 + 1] = xb[1];
        out[((size_t)b*NPQ + i)*3 + 2] = xb[2];
    }
}

// ---------------- fused gemm1 + ball-query (unchanged from R15) ------------
__global__ __launch_bounds__(256) void fused_g1bq_kernel(
    const float* __restrict__ feat, const float* __restrict__ xyz,
    const float* __restrict__ outv)
{
    extern __shared__ char dsm[];
    int tid = threadIdx.x, lane = tid & 31;

    if (blockIdx.x < 1024) {
        uint32_t* As = (uint32_t*)dsm;
        uint32_t* Bs = As + 128*SSTRIDE;
        int b = blockIdx.x >> 5;
        int mBase = (blockIdx.x & 31)*128;
        const float* A = feat + (size_t)b*CC*NN;
        const uint32_t* W32 = (const uint32_t*)g_W1h;
        uint32_t* C = g_PFh + ((size_t)b*NN + mBase)*64;
        int wid = tid >> 5;
        int wm = wid >> 2, wn = wid & 3;
        int lq = lane >> 2, lr = lane & 3;

        uint32_t asb = (uint32_t)__cvta_generic_to_shared(As);
        uint32_t bsb = (uint32_t)__cvta_generic_to_shared(Bs);
        int arow = (lane & 7) + ((lane >> 3) & 1)*8;
        int akp  = (lane >> 4)*4;
        int brow = (lane & 7) + (lane >> 4)*8;
        int bkp  = ((lane >> 3) & 1)*4;

        float c[4][4][4];
#pragma unroll
        for (int i = 0; i < 4; i++)
#pragma unroll
            for (int j = 0; j < 4; j++)
#pragma unroll
                for (int r = 0; r < 4; r++) c[i][j][r] = 0.f;

        for (int kb = 0; kb < CC/32; kb++) {
#pragma unroll
            for (int r = 0; r < 2; r++) {
                int p = tid + 256*r;
                int cp = p >> 5, m4 = p & 31;
                const float* a0 = A + (size_t)(kb*32 + 2*cp)*NN + mBase + m4*4;
                float4 va = *(const float4*)a0;
                float4 vb = *(const float4*)(a0 + NN);
                As[(m4*4+0)*SSTRIDE + cp] = packh2(va.x, vb.x);
                As[(m4*4+1)*SSTRIDE + cp] = packh2(va.y, vb.y);
                As[(m4*4+2)*SSTRIDE + cp] = packh2(va.z, vb.z);
                As[(m4*4+3)*SSTRIDE + cp] = packh2(va.w, vb.w);
            }
#pragma unroll
            for (int r = 0; r < 8; r++) {
                int p = tid + 256*r;
                int n = p >> 4, wd = p & 15;
                Bs[n*SSTRIDE + wd] = W32[n*(CC/2) + kb*16 + wd];
            }
            __syncthreads();
#pragma unroll
            for (int ks = 0; ks < 2; ks++) {
                int k0 = ks*8;
                uint32_t af[4][4], bf[4][2];
#pragma unroll
                for (int mi = 0; mi < 4; mi++) {
                    uint32_t a = asb + (uint32_t)(((wm*64 + mi*16 + arow)*SSTRIDE + k0 + akp)*4);
                    LDSM4(af[mi][0], af[mi][1], af[mi][2], af[mi][3], a);
                }
#pragma unroll
                for (int np = 0; np < 2; np++) {
                    uint32_t a = bsb + (uint32_t)(((wn*32 + np*16 + brow)*SSTRIDE + k0 + bkp)*4);
                    LDSM4(bf[np*2][0], bf[np*2][1], bf[np*2+1][0], bf[np*2+1][1], a);
                }
#pragma unroll
                for (int mi = 0; mi < 4; mi++)
#pragma unroll
                    for (int nj = 0; nj < 4; nj++)
                        MMAH(c[mi][nj], af[mi], bf[nj]);
            }
            __syncthreads();
        }
#pragma unroll
        for (int mi = 0; mi < 4; mi++) {
#pragma unroll
            for (int nj = 0; nj < 4; nj++) {
                int gr   = wm*64 + mi*16 + lq;
                int colw = wn*16 + nj*4 + lr;
                C[(size_t)gr*64 + colw]     = packh2(c[mi][nj][0], c[mi][nj][1]);
                C[(size_t)(gr+8)*64 + colw] = packh2(c[mi][nj][2], c[mi][nj][3]);
            }
        }
    } else {
        float* sx = (float*)dsm;
        float* sy = sx + NN;
        float* sz = sy + NN;
        int w = tid >> 5;
        int qbase = (blockIdx.x - 1024) * 32;
        int b = qbase >> 9;
        const float* xb = xyz + (size_t)b*NN*3;
        for (int i = tid; i < NN; i += 256) {
            sx[i] = xb[i*3+0]; sy[i] = xb[i*3+1]; sz[i] = xb[i*3+2];
        }
        __syncthreads();

        const float R2c = (float)(0.3*0.3);
        const float RAD = 0.3f;
        int q0 = qbase + w*4;
        float qx[4], qy[4], qz[4];
        int found[4], first[4];
#pragma unroll
        for (int j = 0; j < 4; j++) {
            qx[j] = outv[(size_t)(q0+j)*3+0];
            qy[j] = outv[(size_t)(q0+j)*3+1];
            qz[j] = outv[(size_t)(q0+j)*3+2];
            found[j] = 0; first[j] = -1;
        }
        for (int s = 0; s < NN/32; s++) {
            int i = s*32 + lane;
            float x = sx[i], y = sy[i], z = sz[i];
            bool pr[4];
#pragma unroll
            for (int j = 0; j < 4; j++) {
                float dx = __fadd_rn(qx[j], -x);
                float dy = __fadd_rn(qy[j], -y);
                float dz = __fadd_rn(qz[j], -z);
                float d  = __fadd_rn(__fadd_rn(__fmul_rn(dx,dx), __fmul_rn(dy,dy)),
                                     __fmul_rn(dz,dz));
                pr[j] = (d < R2c) && (found[j] < NSAMP);
            }
            unsigned anym = __ballot_sync(0xffffffffu, pr[0]|pr[1]|pr[2]|pr[3]);
            if (anym) {
#pragma unroll
                for (int j = 0; j < 4; j++) {
                    if (found[j] >= NSAMP) continue;
                    unsigned mask = __ballot_sync(0xffffffffu, pr[j]);
                    if (!mask) continue;
                    if (first[j] < 0) first[j] = s*32 + __ffs(mask) - 1;
                    if (pr[j]) {
                        int pos = found[j] + __popc(mask & ((1u << lane) - 1u));
                        if (pos < NSAMP) {
                            int qg = q0 + j;
                            g_idx[qg*NSAMP + pos] = i;
                            g_gxyz[((size_t)qg*NSAMP + pos)*3 + 0] = __fdiv_rn(__fadd_rn(x, -qx[j]), RAD);
                            g_gxyz[((size_t)qg*NSAMP + pos)*3 + 1] = __fdiv_rn(__fadd_rn(y, -qy[j]), RAD);
                            g_gxyz[((size_t)qg*NSAMP + pos)*3 + 2] = __fdiv_rn(__fadd_rn(z, -qz[j]), RAD);
                        }
                    }
                    found[j] += __popc(mask);
                }
                if (found[0] >= NSAMP && found[1] >= NSAMP &&
                    found[2] >= NSAMP && found[3] >= NSAMP) break;
            }
        }
#pragma unroll
        for (int j = 0; j < 4; j++) {
            if (found[j] < NSAMP) {
                int fi = first[j];
                float x = sx[fi], y = sy[fi], z = sz[fi];
                float p0 = __fdiv_rn(__fadd_rn(x, -qx[j]), RAD);
                float p1 = __fdiv_rn(__fadd_rn(y, -qy[j]), RAD);
                float p2 = __fdiv_rn(__fadd_rn(z, -qz[j]), RAD);
                if (lane >= found[j] && lane < NSAMP) {
                    int qg = q0 + j;
                    g_idx[qg*NSAMP + lane] = fi;
                    g_gxyz[((size_t)qg*NSAMP + lane)*3 + 0] = p0;
                    g_gxyz[((size_t)qg*NSAMP + lane)*3 + 1] = p1;
                    g_gxyz[((size_t)qg*NSAMP + lane)*3 + 2] = p2;
                }
            }
        }
    }
}

// ---------------- assemble (unchanged from R15, passing) ----------------
__global__ __launch_bounds__(256) void assemble_kernel(const float* __restrict__ w1)
{
    __shared__ float s_wx[HIDC], s_wy[HIDC], s_wz[HIDC];
    __shared__ float s_sum[HIDC], s_sq[HIDC];
    int tid = threadIdx.x, lane = tid & 31, w = tid >> 5;
    if (tid < HIDC) {
        s_wx[tid] = w1[tid*(CC+3) + 0];
        s_wy[tid] = w1[tid*(CC+3) + 1];
        s_wz[tid] = w1[tid*(CC+3) + 2];
        s_sum[tid] = 0.f; s_sq[tid] = 0.f;
    }
    __syncthreads();

    float ls[4] = {0,0,0,0}, lqa[4] = {0,0,0,0};
    float wx[4], wy[4], wz[4];
#pragma unroll
    for (int j = 0; j < 4; j++) {
        int o = lane*4 + j;
        wx[j] = s_wx[o]; wy[j] = s_wy[o]; wz[j] = s_wz[o];
    }
#pragma unroll 4
    for (int i = 0; i < 16; i++) {
        int p = blockIdx.x*128 + w*16 + i;
        int b = p >> 13;
        int n = g_idx[p];
        float gx = g_gxyz[(size_t)p*3+0];
        float gy = g_gxyz[(size_t)p*3+1];
        float gz = g_gxyz[(size_t)p*3+2];
        uint2 pv = *(const uint2*)(g_PFh + ((size_t)b*NN + n)*64 + lane*2);
        float2 f0 = __half22float2(*(__half2*)&pv.x);
        float2 f1 = __half22float2(*(__half2*)&pv.y);
        float y[4] = {f0.x, f0.y, f1.x, f1.y};
#pragma unroll
        for (int j = 0; j < 4; j++) {
            float r = y[j] + wx[j]*gx + wy[j]*gy + wz[j]*gz;
            y[j] = r;
            ls[j] += r; lqa[j] += r*r;
        }
        uint2 pk = make_uint2(packh2(y[0], y[1]), packh2(y[2], y[3]));
        *(uint2*)(g_Y1h + (size_t)p*64 + lane*2) = pk;
    }
#pragma unroll
    for (int j = 0; j < 4; j++) {
        atomicAdd(&s_sum[lane*4 + j], ls[j]);
        atomicAdd(&s_sq [lane*4 + j], lqa[j]);
    }
    __syncthreads();
    if (tid < HIDC)      atomicAdd(&g_stats[0*256 + tid], (double)s_sum[tid]);
    else if (tid < 256)  atomicAdd(&g_stats[0*256 + 128 + (tid-128)], (double)s_sq[tid-128]);
}

// ---------------- NT GEMM fp16: 2 M-tiles/block, inline BN, shared B -------
__global__ __launch_bounds__(256) void gemm_nt2_kernel(
    int layer, const float* __restrict__ g, const float* __restrict__ be)
{
    extern __shared__ uint32_t dsm2[];
    uint32_t* As  = dsm2;          // [128][36]
    uint32_t* Bs0 = dsm2 + 4608;   // chunk 0 weights
    uint32_t* Bs1 = dsm2 + 9216;   // chunk 1 weights
    __shared__ float s_bnp[384];
    __shared__ float s_sum[HIDC], s_sq[HIDC];
    const uint32_t* Ah = (layer == 1) ? g_Y1h : g_Y2h;
    const uint32_t* W32 = (const uint32_t*)((layer == 1) ? g_W2h : g_W3h);

    int tid = threadIdx.x;
    int lane = tid & 31, wid = tid >> 5;
    int wm = wid >> 2, wn = wid & 3;
    int lq = lane >> 2, lr = lane & 3;

    // inline BN finalize (same double-precision math as old finalize_bn)
    if (tid < HIDC) {
        const double cnt = (double)NPIX;
        double s = g_stats[(layer-1)*256 + tid];
        double q = g_stats[(layer-1)*256 + 128 + tid];
        double m = s / cnt;
        double v = q / cnt - m*m;
        if (v < 0.0) v = 0.0;
        s_bnp[tid]       = (float)m;
        s_bnp[128 + tid] = g[tid] / sqrtf((float)v + 1e-5f);
        s_bnp[256 + tid] = be[tid];
        s_sum[tid] = 0.f; s_sq[tid] = 0.f;
    }
    // B tiles for both chunks, loaded once
#pragma unroll
    for (int r = 0; r < 4; r++) {
        int p = tid + 256*r;
        int n = p >> 3, q = p & 7;
        *(uint4*)(Bs0 + n*NSTR + q*4) = *(const uint4*)(W32 + n*64 + q*4);
        *(uint4*)(Bs1 + n*NSTR + q*4) = *(const uint4*)(W32 + n*64 + 32 + q*4);
    }
    __syncthreads();

#pragma unroll 1
    for (int t = 0; t < 2; t++) {
        size_t mBase = (size_t)blockIdx.x*256 + (size_t)t*128;
        float c[4][4][4];
#pragma unroll
        for (int i = 0; i < 4; i++)
#pragma unroll
            for (int j = 0; j < 4; j++)
#pragma unroll
                for (int r = 0; r < 4; r++) c[i][j][r] = 0.f;

#pragma unroll 1
        for (int kb = 0; kb < 2; kb++) {
#pragma unroll
            for (int r = 0; r < 4; r++) {
                int p = tid + 256*r;
                int row = p >> 3, q = p & 7;
                int ch = kb*64 + q*8;
                uint4 v = *(const uint4*)(Ah + (mBase + row)*64 + kb*32 + q*4);
                uint32_t wds[4] = {v.x, v.y, v.z, v.w};
#pragma unroll
                for (int k = 0; k < 4; k++) {
                    float2 f = __half22float2(*(__half2*)&wds[k]);
                    int cch = ch + 2*k;
                    float a0 = fmaxf(0.f, (f.x - s_bnp[cch])  *s_bnp[128+cch]   + s_bnp[256+cch]);
                    float a1 = fmaxf(0.f, (f.y - s_bnp[cch+1])*s_bnp[128+cch+1] + s_bnp[256+cch+1]);
                    As[row*NSTR + q*4 + k] = packh2(a0, a1);
                }
            }
            __syncthreads();
            const uint32_t* Bc = kb ? Bs1 : Bs0;
#pragma unroll
            for (int ks = 0; ks < 4; ks++) {
                int k0 = ks*8;
                uint32_t af[4][4], bf[4][2];
#pragma unroll
                for (int mi = 0; mi < 4; mi++) {
                    int m0 = wm*64 + mi*16;
                    af[mi][0] = As[(m0 + lq    )*NSTR + k0 + lr    ];
                    af[mi][1] = As[(m0 + 8 + lq)*NSTR + k0 + lr    ];
                    af[mi][2] = As[(m0 + lq    )*NSTR + k0 + lr + 4];
                    af[mi][3] = As[(m0 + 8 + lq)*NSTR + k0 + lr + 4];
                }
#pragma unroll
                for (int nj = 0; nj < 4; nj++) {
                    int n0 = wn*32 + nj*8;
                    bf[nj][0] = Bc[(n0+lq)*NSTR + k0 + lr    ];
                    bf[nj][1] = Bc[(n0+lq)*NSTR + k0 + lr + 4];
                }
#pragma unroll
                for (int mi = 0; mi < 4; mi++)
#pragma unroll
                    for (int nj = 0; nj < 4; nj++)
                        MMAH(c[mi][nj], af[mi], bf[nj]);
            }
            __syncthreads();
        }
        if (layer == 1) {
#pragma unroll
            for (int mi = 0; mi < 4; mi++)
#pragma unroll
                for (int nj = 0; nj < 4; nj++) {
                    size_t gr = mBase + wm*64 + mi*16 + lq;
                    int colw = wn*16 + nj*4 + lr;
                    g_Y2h[gr*64 + colw]     = packh2(c[mi][nj][0], c[mi][nj][1]);
                    g_Y2h[(gr+8)*64 + colw] = packh2(c[mi][nj][2], c[mi][nj][3]);
                }
        } else {
#pragma unroll
            for (int mi = 0; mi < 4; mi++) {
                int qg = blockIdx.x*16 + t*8 + wm*4 + mi;
#pragma unroll
                for (int nj = 0; nj < 4; nj++) {
                    float m0v = fmaxf(c[mi][nj][0], c[mi][nj][2]);
                    float m1v = fmaxf(c[mi][nj][1], c[mi][nj][3]);
#pragma unroll
                    for (int o = 4; o <= 16; o <<= 1) {
                        m0v = fmaxf(m0v, __shfl_xor_sync(0xffffffffu, m0v, o));
                        m1v = fmaxf(m1v, __shfl_xor_sync(0xffffffffu, m1v, o));
                    }
                    if (lq == 0) {
                        int col = wn*32 + nj*8 + 2*lr;
                        *(float2*)(g_MX + (size_t)qg*HIDC + col) = make_float2(m0v, m1v);
                    }
                }
            }
        }
#pragma unroll
        for (int nj = 0; nj < 4; nj++) {
            int ch = wn*32 + nj*8 + 2*lr;
            float s0 = 0.f, q0 = 0.f, s1 = 0.f, q1 = 0.f;
#pragma unroll
            for (int mi = 0; mi < 4; mi++) {
                float x;
                x = c[mi][nj][0]; s0 += x; q0 += x*x;
                x = c[mi][nj][2]; s0 += x; q0 += x*x;
                x = c[mi][nj][1]; s1 += x; q1 += x*x;
                x = c[mi][nj][3]; s1 += x; q1 += x*x;
            }
            atomicAdd(&s_sum[ch],   s0); atomicAdd(&s_sq[ch],   q0);
            atomicAdd(&s_sum[ch+1], s1); atomicAdd(&s_sq[ch+1], q1);
        }
    }
    __syncthreads();
    if (tid < HIDC)      atomicAdd(&g_stats[layer*256 + tid], (double)s_sum[tid]);
    else if (tid < 256)  atomicAdd(&g_stats[layer*256 + 128 + (tid-128)], (double)s_sq[tid-128]);
}

// ---------------- maxfinal: inline BN3 + transpose ----------------
__global__ __launch_bounds__(256) void maxfinal_kernel(
    float* __restrict__ out, const float* __restrict__ g, const float* __restrict__ be)
{
    __shared__ float T[HIDC][33];
    __shared__ float s_bn[384];
    int b = blockIdx.x >> 4, pb = blockIdx.x & 15;
    int tid = threadIdx.x;
    if (tid < HIDC) {
        const double cnt = (double)NPIX;
        double s = g_stats[2*256 + tid];
        double q = g_stats[2*256 + 128 + tid];
        double m = s / cnt;
        double v = q / cnt - m*m;
        if (v < 0.0) v = 0.0;
        s_bn[tid]       = (float)m;
        s_bn[128 + tid] = g[tid] / sqrtf((float)v + 1e-5f);
        s_bn[256 + tid] = be[tid];
    }
    __syncthreads();
#pragma unroll
    for (int r = 0; r < 16; r++) {
        int idx = tid + 256*r;
        int ql = idx >> 7, c = idx & 127;
        float v = g_MX[((size_t)(b*NPQ + pb*32 + ql))*HIDC + c];
        T[c][ql] = fmaxf(0.f, (v - s_bn[c])*s_bn[128+c] + s_bn[256+c]);
    }
    __syncthreads();
#pragma unroll
    for (int r = 0; r < 16; r++) {
        int flat = tid + 256*r;
        int o = flat >> 5, pl = flat & 31;
        out[OUT_FEAT + (size_t)b*(HIDC*NPQ) + (size_t)o*NPQ + pb*32 + pl] = T[o][pl];
    }
}

// ---------------------------------------------------------------------------
extern "C" void kernel_launch(void* const* d_in, const int* in_sizes, int n_in,
                              void* d_out, int out_size)
{
    const float* xyz  = (const float*)d_in[0];
    const float* feat = (const float*)d_in[1];
    const float* seed = (const float*)d_in[2];
    const float* w1   = (const float*)d_in[3];
    const float* g1   = (const float*)d_in[4];
    const float* be1  = (const float*)d_in[5];
    const float* w2   = (const float*)d_in[6];
    const float* g2   = (const float*)d_in[7];
    const float* be2  = (const float*)d_in[8];
    const float* w3   = (const float*)d_in[9];
    const float* g3   = (const float*)d_in[10];
    const float* be3  = (const float*)d_in[11];
    float* out = (float*)d_out;

    cudaFuncSetAttribute(fps_kernel, cudaFuncAttributeMaxDynamicSharedMemorySize, FPS_SMEM);
    cudaFuncSetAttribute(fused_g1bq_kernel, cudaFuncAttributeMaxDynamicSharedMemorySize, FUSE_SMEM);
    cudaFuncSetAttribute(gemm_nt2_kernel, cudaFuncAttributeMaxDynamicSharedMemorySize, NT_SMEM);

    zero_stats_kernel<<<3, 256>>>();
    prep_w_kernel<<<HIDC, CC>>>(w1, w2, w3);
    fps_kernel<<<BB, 1024, FPS_SMEM>>>(seed, xyz, out);
    fused_g1bq_kernel<<<1536, 256, FUSE_SMEM>>>(feat, xyz, out);
    assemble_kernel<<<NPIX/128, 256>>>(w1);
    gemm_nt2_kernel<<<NPIX/256, 256, NT_SMEM>>>(1, g1, be1);
    gemm_nt2_kernel<<<NPIX/256, 256, NT_SMEM>>>(2, g2, be2);
    maxfinal_kernel<<<BB*16, 256>>>(out, g3, be3);
}

// round 17
// speedup vs baseline: 1.8406x; 1.0670x over previous
#include <cuda_runtime.h>
#include <cuda_fp16.h>
#include <math.h>
#include <stdint.h>

#define BB    32
#define NN    4096
#define NPQ   512
#define NSAMP 16
#define CC    256
#define HIDC  128
#define NPIX  (BB*NPQ*NSAMP)
#define NPTS  (BB*NN)

#define OUT_FEAT (BB*NPQ*3)
#define OUT_INDS (OUT_FEAT + BB*HIDC*NPQ)

__device__ uint32_t g_PFh[(size_t)NPTS*64];
__device__ uint32_t g_Y1h[(size_t)NPIX*64];
__device__ uint32_t g_Y2h[(size_t)NPIX*64];
__device__ float    g_MX[(size_t)BB*NPQ*HIDC];
__device__ int      g_idx[NPIX];
__device__ float    g_gxyz[(size_t)NPIX*3];
__device__ double   g_stats[3*2*HIDC];
__device__ __half   g_W1h[HIDC*CC];
__device__ __half   g_W2h[HIDC*HIDC];
__device__ __half   g_W3h[HIDC*HIDC];

#define MMAH(c, a, b) asm volatile( \
  "mma.sync.aligned.m16n8k16.row.col.f32.f16.f16.f32 " \
  "{%0,%1,%2,%3}, {%4,%5,%6,%7}, {%8,%9}, {%0,%1,%2,%3};" \
  : "+f"((c)[0]), "+f"((c)[1]), "+f"((c)[2]), "+f"((c)[3]) \
  : "r"((a)[0]), "r"((a)[1]), "r"((a)[2]), "r"((a)[3]), "r"((b)[0]), "r"((b)[1]))

#define LDSM4(r0, r1, r2, r3, a) asm volatile( \
  "ldmatrix.sync.aligned.m8n8.x4.shared.b16 {%0,%1,%2,%3}, [%4];" \
  : "=r"(r0), "=r"(r1), "=r"(r2), "=r"(r3) : "r"(a))

// packed f32x2 (per-lane bit-identical to scalar rn ops)
#define ADD2(o,a,b) asm("add.rn.f32x2 %0, %1, %2;" : "=l"(o) : "l"(a), "l"(b))
#define MUL2(o,a,b) asm("mul.rn.f32x2 %0, %1, %2;" : "=l"(o) : "l"(a), "l"(b))
#define PACK2(o,lo,hi) asm("mov.b64 %0, {%1, %2};" : "=l"(o) : "r"(lo), "r"(hi))
#define UNPK2(lo,hi,i) asm("mov.b64 {%0, %1}, %2;" : "=r"(lo), "=r"(hi) : "l"(i))

#define SSTRIDE 20
#define NSTR 36
#define FPS_SMEM (12928*4)
#define FUSE_SMEM 49152
#define NT_SMEM  (3*4608*4)

__device__ __forceinline__ uint32_t packh2(float x, float y) {
    __half2 h = __floats2half2_rn(x, y);
    return *(uint32_t*)&h;
}

// prep_w also zeroes the stats accumulators (absorbs zero_stats launch)
__global__ void prep_w_kernel(const float* __restrict__ w1,
                              const float* __restrict__ w2,
                              const float* __restrict__ w3) {
    int o = blockIdx.x, k = threadIdx.x;
    int flat = o*256 + k;
    if (flat < 3*2*HIDC) g_stats[flat] = 0.0;
    g_W1h[o*CC + k] = __float2half_rn(w1[o*(CC+3) + 3 + k]);
    if (k < HIDC) {
        g_W2h[o*HIDC + k] = __float2half_rn(w2[o*HIDC + k]);
        g_W3h[o*HIDC + k] = __float2half_rn(w3[o*HIDC + k]);
    }
}

// ---------------- FPS v6: f32x2 packed distance chain ----------------
__global__ __launch_bounds__(1024) void fps_kernel(
    const float* __restrict__ seed, const float* __restrict__ xyz,
    float* __restrict__ out)
{
    extern __shared__ float fsm[];
    float* s_px = fsm;
    float* s_py = fsm + 4096;
    float* s_pz = fsm + 8192;
    int*   s_inds = (int*)(fsm + 12288);
    float* s_cv = fsm + 12800;
    int*   s_ci = (int*)(fsm + 12864);

    int b = blockIdx.x, t = threadIdx.x;
    int lane = t & 31, wid = t >> 5;

    const float* sb = seed + (size_t)b*NN*3;
    float pxs[4], pys[4], pzs[4];
#pragma unroll
    for (int j = 0; j < 4; j++) {
        int i = t + j*1024;
        float x = sb[i*3+0], y = sb[i*3+1], z = sb[i*3+2];
        pxs[j] = x; pys[j] = y; pzs[j] = z;
        s_px[i] = x; s_py[i] = y; s_pz[i] = z;
    }
    uint64_t X01, X23, Y01, Y23, Z01, Z23;
    PACK2(X01, __float_as_uint(pxs[0]), __float_as_uint(pxs[1]));
    PACK2(X23, __float_as_uint(pxs[2]), __float_as_uint(pxs[3]));
    PACK2(Y01, __float_as_uint(pys[0]), __float_as_uint(pys[1]));
    PACK2(Y23, __float_as_uint(pys[2]), __float_as_uint(pys[3]));
    PACK2(Z01, __float_as_uint(pzs[0]), __float_as_uint(pzs[1]));
    PACK2(Z23, __float_as_uint(pzs[2]), __float_as_uint(pzs[3]));
    float dist0 = 1e10f, dist1 = 1e10f, dist2 = 1e10f, dist3 = 1e10f;

    if (t == 0) s_inds[0] = 0;
    __syncthreads();
    float lx = s_px[0], ly = s_py[0], lz = s_pz[0];

    for (int it = 1; it < NPQ; ++it) {
        // dx = px + (-lx)  (bit-identical to __fadd_rn(px,-lx))
        uint32_t nx = __float_as_uint(-lx);
        uint32_t ny = __float_as_uint(-ly);
        uint32_t nz = __float_as_uint(-lz);
        uint64_t NX, NY, NZ;
        PACK2(NX, nx, nx); PACK2(NY, ny, ny); PACK2(NZ, nz, nz);
        uint64_t dx01, dx23, dy01, dy23, dz01, dz23;
        ADD2(dx01, X01, NX); ADD2(dx23, X23, NX);
        ADD2(dy01, Y01, NY); ADD2(dy23, Y23, NY);
        ADD2(dz01, Z01, NZ); ADD2(dz23, Z23, NZ);
        uint64_t sx01, sx23, sy01, sy23, sz01, sz23;
        MUL2(sx01, dx01, dx01); MUL2(sx23, dx23, dx23);
        MUL2(sy01, dy01, dy01); MUL2(sy23, dy23, dy23);
        MUL2(sz01, dz01, dz01); MUL2(sz23, dz23, dz23);
        uint64_t t01, t23, d01, d23;
        ADD2(t01, sx01, sy01); ADD2(d01, t01, sz01);
        ADD2(t23, sx23, sy23); ADD2(d23, t23, sz23);
        uint32_t u0, u1, u2, u3;
        UNPK2(u0, u1, d01); UNPK2(u2, u3, d23);
        dist0 = fminf(dist0, __uint_as_float(u0));
        dist1 = fminf(dist1, __uint_as_float(u1));
        dist2 = fminf(dist2, __uint_as_float(u2));
        dist3 = fminf(dist3, __uint_as_float(u3));
        // argmax with first-index tie-break (j ascending)
        float bv = fmaxf(fmaxf(dist0, dist1), fmaxf(dist2, dist3));
        int bi = (dist0 == bv) ? t
               : (dist1 == bv) ? t + 1024
               : (dist2 == bv) ? t + 2048 : t + 3072;

        unsigned fb = __float_as_uint(bv);
        unsigned m  = __reduce_max_sync(0xffffffffu, fb);
        unsigned cand = (fb == m) ? (unsigned)bi : 0xffffffffu;
        unsigned cmin = __reduce_min_sync(0xffffffffu, cand);
        int buf = it & 1;
        if (fb == m && (unsigned)bi == cmin) {
            s_cv[buf*32 + wid] = bv; s_ci[buf*32 + wid] = bi;
        }
        __syncthreads();
        float v  = s_cv[buf*32 + lane];
        int   ci = s_ci[buf*32 + lane];
        unsigned fb2 = __float_as_uint(v);
        unsigned m2  = __reduce_max_sync(0xffffffffu, fb2);
        unsigned cand2 = (fb2 == m2) ? (unsigned)ci : 0xffffffffu;
        unsigned gi = __reduce_min_sync(0xffffffffu, cand2);
        lx = s_px[gi]; ly = s_py[gi]; lz = s_pz[gi];
        if (t == 0) s_inds[it] = (int)gi;
    }
    __syncthreads();
    for (int i = t; i < NPQ; i += 1024) {
        int id = s_inds[i];
        out[OUT_INDS + b*NPQ + i] = (float)id;
        const float* xb = xyz + ((size_t)b*NN + id)*3;
        out[((size_t)b*NPQ + i)*3 + 0] = xb[0];
        out[((size_t)b*NPQ + i)*3 + 1] = xb[1];
        out[((size_t)b*NPQ + i)*3 + 2] = xb[2];
    }
}

// ---------------- fused gemm1 + ball-query (unchanged, passing) ------------
__global__ __launch_bounds__(256) void fused_g1bq_kernel(
    const float* __restrict__ feat, const float* __restrict__ xyz,
    const float* __restrict__ outv)
{
    extern __shared__ char dsm[];
    int tid = threadIdx.x, lane = tid & 31;

    if (blockIdx.x < 1024) {
        uint32_t* As = (uint32_t*)dsm;
        uint32_t* Bs = As + 128*SSTRIDE;
        int b = blockIdx.x >> 5;
        int mBase = (blockIdx.x & 31)*128;
        const float* A = feat + (size_t)b*CC*NN;
        const uint32_t* W32 = (const uint32_t*)g_W1h;
        uint32_t* C = g_PFh + ((size_t)b*NN + mBase)*64;
        int wid = tid >> 5;
        int wm = wid >> 2, wn = wid & 3;
        int lq = lane >> 2, lr = lane & 3;

        uint32_t asb = (uint32_t)__cvta_generic_to_shared(As);
        uint32_t bsb = (uint32_t)__cvta_generic_to_shared(Bs);
        int arow = (lane & 7) + ((lane >> 3) & 1)*8;
        int akp  = (lane >> 4)*4;
        int brow = (lane & 7) + (lane >> 4)*8;
        int bkp  = ((lane >> 3) & 1)*4;

        float c[4][4][4];
#pragma unroll
        for (int i = 0; i < 4; i++)
#pragma unroll
            for (int j = 0; j < 4; j++)
#pragma unroll
                for (int r = 0; r < 4; r++) c[i][j][r] = 0.f;

        for (int kb = 0; kb < CC/32; kb++) {
#pragma unroll
            for (int r = 0; r < 2; r++) {
                int p = tid + 256*r;
                int cp = p >> 5, m4 = p & 31;
                const float* a0 = A + (size_t)(kb*32 + 2*cp)*NN + mBase + m4*4;
                float4 va = *(const float4*)a0;
                float4 vb = *(const float4*)(a0 + NN);
                As[(m4*4+0)*SSTRIDE + cp] = packh2(va.x, vb.x);
                As[(m4*4+1)*SSTRIDE + cp] = packh2(va.y, vb.y);
                As[(m4*4+2)*SSTRIDE + cp] = packh2(va.z, vb.z);
                As[(m4*4+3)*SSTRIDE + cp] = packh2(va.w, vb.w);
            }
#pragma unroll
            for (int r = 0; r < 8; r++) {
                int p = tid + 256*r;
                int n = p >> 4, wd = p & 15;
                Bs[n*SSTRIDE + wd] = W32[n*(CC/2) + kb*16 + wd];
            }
            __syncthreads();
#pragma unroll
            for (int ks = 0; ks < 2; ks++) {
                int k0 = ks*8;
                uint32_t af[4][4], bf[4][2];
#pragma unroll
                for (int mi = 0; mi < 4; mi++) {
                    uint32_t a = asb + (uint32_t)(((wm*64 + mi*16 + arow)*SSTRIDE + k0 + akp)*4);
                    LDSM4(af[mi][0], af[mi][1], af[mi][2], af[mi][3], a);
                }
#pragma unroll
                for (int np = 0; np < 2; np++) {
                    uint32_t a = bsb + (uint32_t)(((wn*32 + np*16 + brow)*SSTRIDE + k0 + bkp)*4);
                    LDSM4(bf[np*2][0], bf[np*2][1], bf[np*2+1][0], bf[np*2+1][1], a);
                }
#pragma unroll
                for (int mi = 0; mi < 4; mi++)
#pragma unroll
                    for (int nj = 0; nj < 4; nj++)
                        MMAH(c[mi][nj], af[mi], bf[nj]);
            }
            __syncthreads();
        }
#pragma unroll
        for (int mi = 0; mi < 4; mi++) {
#pragma unroll
            for (int nj = 0; nj < 4; nj++) {
                int gr   = wm*64 + mi*16 + lq;
                int colw = wn*16 + nj*4 + lr;
                C[(size_t)gr*64 + colw]     = packh2(c[mi][nj][0], c[mi][nj][1]);
                C[(size_t)(gr+8)*64 + colw] = packh2(c[mi][nj][2], c[mi][nj][3]);
            }
        }
    } else {
        float* sx = (float*)dsm;
        float* sy = sx + NN;
        float* sz = sy + NN;
        int w = tid >> 5;
        int qbase = (blockIdx.x - 1024) * 32;
        int b = qbase >> 9;
        const float* xb = xyz + (size_t)b*NN*3;
        for (int i = tid; i < NN; i += 256) {
            sx[i] = xb[i*3+0]; sy[i] = xb[i*3+1]; sz[i] = xb[i*3+2];
        }
        __syncthreads();

        const float R2c = (float)(0.3*0.3);
        const float RAD = 0.3f;
        int q0 = qbase + w*4;
        float qx[4], qy[4], qz[4];
        int found[4], first[4];
#pragma unroll
        for (int j = 0; j < 4; j++) {
            qx[j] = outv[(size_t)(q0+j)*3+0];
            qy[j] = outv[(size_t)(q0+j)*3+1];
            qz[j] = outv[(size_t)(q0+j)*3+2];
            found[j] = 0; first[j] = -1;
        }
        for (int s = 0; s < NN/32; s++) {
            int i = s*32 + lane;
            float x = sx[i], y = sy[i], z = sz[i];
            bool pr[4];
#pragma unroll
            for (int j = 0; j < 4; j++) {
                float dx = __fadd_rn(qx[j], -x);
                float dy = __fadd_rn(qy[j], -y);
                float dz = __fadd_rn(qz[j], -z);
                float d  = __fadd_rn(__fadd_rn(__fmul_rn(dx,dx), __fmul_rn(dy,dy)),
                                     __fmul_rn(dz,dz));
                pr[j] = (d < R2c) && (found[j] < NSAMP);
            }
            unsigned anym = __ballot_sync(0xffffffffu, pr[0]|pr[1]|pr[2]|pr[3]);
            if (anym) {
#pragma unroll
                for (int j = 0; j < 4; j++) {
                    if (found[j] >= NSAMP) continue;
                    unsigned mask = __ballot_sync(0xffffffffu, pr[j]);
                    if (!mask) continue;
                    if (first[j] < 0) first[j] = s*32 + __ffs(mask) - 1;
                    if (pr[j]) {
                        int pos = found[j] + __popc(mask & ((1u << lane) - 1u));
                        if (pos < NSAMP) {
                            int qg = q0 + j;
                            g_idx[qg*NSAMP + pos] = i;
                            g_gxyz[((size_t)qg*NSAMP + pos)*3 + 0] = __fdiv_rn(__fadd_rn(x, -qx[j]), RAD);
                            g_gxyz[((size_t)qg*NSAMP + pos)*3 + 1] = __fdiv_rn(__fadd_rn(y, -qy[j]), RAD);
                            g_gxyz[((size_t)qg*NSAMP + pos)*3 + 2] = __fdiv_rn(__fadd_rn(z, -qz[j]), RAD);
                        }
                    }
                    found[j] += __popc(mask);
                }
                if (found[0] >= NSAMP && found[1] >= NSAMP &&
                    found[2] >= NSAMP && found[3] >= NSAMP) break;
            }
        }
#pragma unroll
        for (int j = 0; j < 4; j++) {
            if (found[j] < NSAMP) {
                int fi = first[j];
                float x = sx[fi], y = sy[fi], z = sz[fi];
                float p0 = __fdiv_rn(__fadd_rn(x, -qx[j]), RAD);
                float p1 = __fdiv_rn(__fadd_rn(y, -qy[j]), RAD);
                float p2 = __fdiv_rn(__fadd_rn(z, -qz[j]), RAD);
                if (lane >= found[j] && lane < NSAMP) {
                    int qg = q0 + j;
                    g_idx[qg*NSAMP + lane] = fi;
                    g_gxyz[((size_t)qg*NSAMP + lane)*3 + 0] = p0;
                    g_gxyz[((size_t)qg*NSAMP + lane)*3 + 1] = p1;
                    g_gxyz[((size_t)qg*NSAMP + lane)*3 + 2] = p2;
                }
            }
        }
    }
}

// ---------------- assemble (unchanged, passing; now at profile slot 3) -----
__global__ __launch_bounds__(256) void assemble_kernel(const float* __restrict__ w1)
{
    __shared__ float s_wx[HIDC], s_wy[HIDC], s_wz[HIDC];
    __shared__ float s_sum[HIDC], s_sq[HIDC];
    int tid = threadIdx.x, lane = tid & 31, w = tid >> 5;
    if (tid < HIDC) {
        s_wx[tid] = w1[tid*(CC+3) + 0];
        s_wy[tid] = w1[tid*(CC+3) + 1];
        s_wz[tid] = w1[tid*(CC+3) + 2];
        s_sum[tid] = 0.f; s_sq[tid] = 0.f;
    }
    __syncthreads();

    float ls[4] = {0,0,0,0}, lqa[4] = {0,0,0,0};
    float wx[4], wy[4], wz[4];
#pragma unroll
    for (int j = 0; j < 4; j++) {
        int o = lane*4 + j;
        wx[j] = s_wx[o]; wy[j] = s_wy[o]; wz[j] = s_wz[o];
    }
#pragma unroll 4
    for (int i = 0; i < 16; i++) {
        int p = blockIdx.x*128 + w*16 + i;
        int b = p >> 13;
        int n = g_idx[p];
        float gx = g_gxyz[(size_t)p*3+0];
        float gy = g_gxyz[(size_t)p*3+1];
        float gz = g_gxyz[(size_t)p*3+2];
        uint2 pv = *(const uint2*)(g_PFh + ((size_t)b*NN + n)*64 + lane*2);
        float2 f0 = __half22float2(*(__half2*)&pv.x);
        float2 f1 = __half22float2(*(__half2*)&pv.y);
        float y[4] = {f0.x, f0.y, f1.x, f1.y};
#pragma unroll
        for (int j = 0; j < 4; j++) {
            float r = y[j] + wx[j]*gx + wy[j]*gy + wz[j]*gz;
            y[j] = r;
            ls[j] += r; lqa[j] += r*r;
        }
        uint2 pk = make_uint2(packh2(y[0], y[1]), packh2(y[2], y[3]));
        *(uint2*)(g_Y1h + (size_t)p*64 + lane*2) = pk;
    }
#pragma unroll
    for (int j = 0; j < 4; j++) {
        atomicAdd(&s_sum[lane*4 + j], ls[j]);
        atomicAdd(&s_sq [lane*4 + j], lqa[j]);
    }
    __syncthreads();
    if (tid < HIDC)      atomicAdd(&g_stats[0*256 + tid], (double)s_sum[tid]);
    else if (tid < 256)  atomicAdd(&g_stats[0*256 + 128 + (tid-128)], (double)s_sq[tid-128]);
}

// ---------------- NT GEMM fp16: 4 M-tiles/block, inline BN, shared B -------
__global__ __launch_bounds__(256) void gemm_nt2_kernel(
    int layer, const float* __restrict__ g, const float* __restrict__ be)
{
    extern __shared__ uint32_t dsm2[];
    uint32_t* As  = dsm2;
    uint32_t* Bs0 = dsm2 + 4608;
    uint32_t* Bs1 = dsm2 + 9216;
    __shared__ float s_bnp[384];
    __shared__ float s_sum[HIDC], s_sq[HIDC];
    const uint32_t* Ah = (layer == 1) ? g_Y1h : g_Y2h;
    const uint32_t* W32 = (const uint32_t*)((layer == 1) ? g_W2h : g_W3h);

    int tid = threadIdx.x;
    int lane = tid & 31, wid = tid >> 5;
    int wm = wid >> 2, wn = wid & 3;
    int lq = lane >> 2, lr = lane & 3;

    if (tid < HIDC) {
        const double cnt = (double)NPIX;
        double s = g_stats[(layer-1)*256 + tid];
        double q = g_stats[(layer-1)*256 + 128 + tid];
        double m = s / cnt;
        double v = q / cnt - m*m;
        if (v < 0.0) v = 0.0;
        s_bnp[tid]       = (float)m;
        s_bnp[128 + tid] = g[tid] / sqrtf((float)v + 1e-5f);
        s_bnp[256 + tid] = be[tid];
        s_sum[tid] = 0.f; s_sq[tid] = 0.f;
    }
#pragma unroll
    for (int r = 0; r < 4; r++) {
        int p = tid + 256*r;
        int n = p >> 3, q = p & 7;
        *(uint4*)(Bs0 + n*NSTR + q*4) = *(const uint4*)(W32 + n*64 + q*4);
        *(uint4*)(Bs1 + n*NSTR + q*4) = *(const uint4*)(W32 + n*64 + 32 + q*4);
    }
    __syncthreads();

#pragma unroll 1
    for (int t = 0; t < 4; t++) {
        size_t mBase = (size_t)blockIdx.x*512 + (size_t)t*128;
        float c[4][4][4];
#pragma unroll
        for (int i = 0; i < 4; i++)
#pragma unroll
            for (int j = 0; j < 4; j++)
#pragma unroll
                for (int r = 0; r < 4; r++) c[i][j][r] = 0.f;

#pragma unroll 1
        for (int kb = 0; kb < 2; kb++) {
#pragma unroll
            for (int r = 0; r < 4; r++) {
                int p = tid + 256*r;
                int row = p >> 3, q = p & 7;
                int ch = kb*64 + q*8;
                uint4 v = *(const uint4*)(Ah + (mBase + row)*64 + kb*32 + q*4);
                uint32_t wds[4] = {v.x, v.y, v.z, v.w};
#pragma unroll
                for (int k = 0; k < 4; k++) {
                    float2 f = __half22float2(*(__half2*)&wds[k]);
                    int cch = ch + 2*k;
                    float a0 = fmaxf(0.f, (f.x - s_bnp[cch])  *s_bnp[128+cch]   + s_bnp[256+cch]);
                    float a1 = fmaxf(0.f, (f.y - s_bnp[cch+1])*s_bnp[128+cch+1] + s_bnp[256+cch+1]);
                    As[row*NSTR + q*4 + k] = packh2(a0, a1);
                }
            }
            __syncthreads();
            const uint32_t* Bc = kb ? Bs1 : Bs0;
#pragma unroll
            for (int ks = 0; ks < 4; ks++) {
                int k0 = ks*8;
                uint32_t af[4][4], bf[4][2];
#pragma unroll
                for (int mi = 0; mi < 4; mi++) {
                    int m0 = wm*64 + mi*16;
                    af[mi][0] = As[(m0 + lq    )*NSTR + k0 + lr    ];
                    af[mi][1] = As[(m0 + 8 + lq)*NSTR + k0 + lr    ];
                    af[mi][2] = As[(m0 + lq    )*NSTR + k0 + lr + 4];
                    af[mi][3] = As[(m0 + 8 + lq)*NSTR + k0 + lr + 4];
                }
#pragma unroll
                for (int nj = 0; nj < 4; nj++) {
                    int n0 = wn*32 + nj*8;
                    bf[nj][0] = Bc[(n0+lq)*NSTR + k0 + lr    ];
                    bf[nj][1] = Bc[(n0+lq)*NSTR + k0 + lr + 4];
                }
#pragma unroll
                for (int mi = 0; mi < 4; mi++)
#pragma unroll
                    for (int nj = 0; nj < 4; nj++)
                        MMAH(c[mi][nj], af[mi], bf[nj]);
            }
            __syncthreads();
        }
        if (layer == 1) {
#pragma unroll
            for (int mi = 0; mi < 4; mi++)
#pragma unroll
                for (int nj = 0; nj < 4; nj++) {
                    size_t gr = mBase + wm*64 + mi*16 + lq;
                    int colw = wn*16 + nj*4 + lr;
                    g_Y2h[gr*64 + colw]     = packh2(c[mi][nj][0], c[mi][nj][1]);
                    g_Y2h[(gr+8)*64 + colw] = packh2(c[mi][nj][2], c[mi][nj][3]);
                }
        } else {
#pragma unroll
            for (int mi = 0; mi < 4; mi++) {
                int qg = blockIdx.x*32 + t*8 + wm*4 + mi;
#pragma unroll
                for (int nj = 0; nj < 4; nj++) {
                    float m0v = fmaxf(c[mi][nj][0], c[mi][nj][2]);
                    float m1v = fmaxf(c[mi][nj][1], c[mi][nj][3]);
#pragma unroll
                    for (int o = 4; o <= 16; o <<= 1) {
                        m0v = fmaxf(m0v, __shfl_xor_sync(0xffffffffu, m0v, o));
                        m1v = fmaxf(m1v, __shfl_xor_sync(0xffffffffu, m1v, o));
                    }
                    if (lq == 0) {
                        int col = wn*32 + nj*8 + 2*lr;
                        *(float2*)(g_MX + (size_t)qg*HIDC + col) = make_float2(m0v, m1v);
                    }
                }
            }
        }
#pragma unroll
        for (int nj = 0; nj < 4; nj++) {
            int ch = wn*32 + nj*8 + 2*lr;
            float s0 = 0.f, q0 = 0.f, s1 = 0.f, q1 = 0.f;
#pragma unroll
            for (int mi = 0; mi < 4; mi++) {
                float x;
                x = c[mi][nj][0]; s0 += x; q0 += x*x;
                x = c[mi][nj][2]; s0 += x; q0 += x*x;
                x = c[mi][nj][1]; s1 += x; q1 += x*x;
                x = c[mi][nj][3]; s1 += x; q1 += x*x;
            }
            atomicAdd(&s_sum[ch],   s0); atomicAdd(&s_sq[ch],   q0);
            atomicAdd(&s_sum[ch+1], s1); atomicAdd(&s_sq[ch+1], q1);
        }
    }
    __syncthreads();
    if (tid < HIDC)      atomicAdd(&g_stats[layer*256 + tid], (double)s_sum[tid]);
    else if (tid < 256)  atomicAdd(&g_stats[layer*256 + 128 + (tid-128)], (double)s_sq[tid-128]);
}

// ---------------- maxfinal: inline BN3 + transpose (unchanged) -------------
__global__ __launch_bounds__(256) void maxfinal_kernel(
    float* __restrict__ out, const float* __restrict__ g, const float* __restrict__ be)
{
    __shared__ float T[HIDC][33];
    __shared__ float s_bn[384];
    int b = blockIdx.x >> 4, pb = blockIdx.x & 15;
    int tid = threadIdx.x;
    if (tid < HIDC) {
        const double cnt = (double)NPIX;
        double s = g_stats[2*256 + tid];
        double q = g_stats[2*256 + 128 + tid];
        double m = s / cnt;
        double v = q / cnt - m*m;
        if (v < 0.0) v = 0.0;
        s_bn[tid]       = (float)m;
        s_bn[128 + tid] = g[tid] / sqrtf((float)v + 1e-5f);
        s_bn[256 + tid] = be[tid];
    }
    __syncthreads();
#pragma unroll
    for (int r = 0; r < 16; r++) {
        int idx = tid + 256*r;
        int ql = idx >> 7, c = idx & 127;
        float v = g_MX[((size_t)(b*NPQ + pb*32 + ql))*HIDC + c];
        T[c][ql] = fmaxf(0.f, (v - s_bn[c])*s_bn[128+c] + s_bn[256+c]);
    }
    __syncthreads();
#pragma unroll
    for (int r = 0; r < 16; r++) {
        int flat = tid + 256*r;
        int o = flat >> 5, pl = flat & 31;
        out[OUT_FEAT + (size_t)b*(HIDC*NPQ) + (size_t)o*NPQ + pb*32 + pl] = T[o][pl];
    }
}

// ---------------------------------------------------------------------------
extern "C" void kernel_launch(void* const* d_in, const int* in_sizes, int n_in,
                              void* d_out, int out_size)
{
    const float* xyz  = (const float*)d_in[0];
    const float* feat = (const float*)d_in[1];
    const float* seed = (const float*)d_in[2];
    const float* w1   = (const float*)d_in[3];
    const float* g1   = (const float*)d_in[4];
    const float* be1  = (const float*)d_in[5];
    const float* w2   = (const float*)d_in[6];
    const float* g2   = (const float*)d_in[7];
    const float* be2  = (const float*)d_in[8];
    const float* w3   = (const float*)d_in[9];
    const float* g3   = (const float*)d_in[10];
    const float* be3  = (const float*)d_in[11];
    float* out = (float*)d_out;

    cudaFuncSetAttribute(fps_kernel, cudaFuncAttributeMaxDynamicSharedMemorySize, FPS_SMEM);
    cudaFuncSetAttribute(fused_g1bq_kernel, cudaFuncAttributeMaxDynamicSharedMemorySize, FUSE_SMEM);
    cudaFuncSetAttribute(gemm_nt2_kernel, cudaFuncAttributeMaxDynamicSharedMemorySize, NT_SMEM);

    prep_w_kernel<<<HIDC, CC>>>(w1, w2, w3);
    fps_kernel<<<BB, 1024, FPS_SMEM>>>(seed, xyz, out);
    fused_g1bq_kernel<<<1536, 256, FUSE_SMEM>>>(feat, xyz, out);
    assemble_kernel<<<NPIX/128, 256>>>(w1);
    gemm_nt2_kernel<<<NPIX/512, 256, NT_SMEM>>>(1, g1, be1);
    gemm_nt2_kernel<<<NPIX/512, 256, NT_SMEM>>>(2, g2, be2);
    maxfinal_kernel<<<BB*16, 256>>>(out, g3, be3);
}